// round 4
// baseline (speedup 1.0000x reference)
#include <cuda_runtime.h>
#include <cstdint>
#include <math.h>

#define NN   100000
#define NCAT 20
#define EMBD 32
#define CARD 100

// ---------------- scratch (device globals) ----------------
__device__ float g_xhi[(size_t)NN * 192], g_xlo[(size_t)NN * 192];
__device__ float g_p1hi[(size_t)NN * 128], g_p1lo[(size_t)NN * 128];
__device__ float g_p2hi[(size_t)NN * 128], g_p2lo[(size_t)NN * 128];
__device__ float g_y[(size_t)NN * 128];
__device__ float g_agg[(size_t)NN * 128];
__device__ float g_h[(size_t)NN * 128];
__device__ float g_deg[NN], g_s1[NN], g_s2[NN], g_aggs[NN];
__device__ float g_wthi[1536 * 128], g_wtlo[1536 * 128];   // pre-split weights [k][n]
__device__ float g_ehi[NCAT * CARD * EMBD], g_elo[NCAT * CARD * EMBD];

__device__ __forceinline__ float gelu_f(float v) {
    return 0.5f * v * (1.0f + erff(v * 0.70710678118654752f));
}

__device__ __forceinline__ void split_tf32(float v, uint32_t& hi, uint32_t& lo) {
    asm("cvt.rna.tf32.f32 %0, %1;" : "=r"(hi) : "f"(v));
    float r = v - __uint_as_float(hi);
    asm("cvt.rna.tf32.f32 %0, %1;" : "=r"(lo) : "f"(r));
}

__device__ __forceinline__ void mma_tf32(float4& c, const uint32_t* a, const uint32_t* b) {
    asm volatile("mma.sync.aligned.m16n8k8.row.col.f32.tf32.tf32.f32 "
                 "{%0,%1,%2,%3}, {%4,%5,%6,%7}, {%8,%9}, {%0,%1,%2,%3};"
                 : "+f"(c.x), "+f"(c.y), "+f"(c.z), "+f"(c.w)
                 : "r"(a[0]), "r"(a[1]), "r"(a[2]), "r"(a[3]), "r"(b[0]), "r"(b[1]));
}

__device__ __forceinline__ void cpasync16(uint32_t dst, const void* src) {
    asm volatile("cp.async.cg.shared.global [%0], [%1], 16;" :: "r"(dst), "l"(src));
}
__device__ __forceinline__ void cp_commit() { asm volatile("cp.async.commit_group;"); }
template<int N> __device__ __forceinline__ void cp_wait() {
    asm volatile("cp.async.wait_group %0;" :: "n"(N));
}

// ---------------- zero kernel ----------------
__global__ void zero_kernel(float* __restrict__ p, int n4) {
    int i = blockIdx.x * blockDim.x + threadIdx.x;
    int stride = gridDim.x * blockDim.x;
    float4* p4 = (float4*)p;
    float4 z = make_float4(0.f, 0.f, 0.f, 0.f);
    for (; i < n4; i += stride) p4[i] = z;
}

// ---------------- split kernels ----------------
__global__ void split_arr(const float* __restrict__ src, int n,
                          float* __restrict__ oh, float* __restrict__ ol) {
    int i = blockIdx.x * blockDim.x + threadIdx.x;
    if (i < n) {
        uint32_t h, l;
        split_tf32(src[i], h, l);
        oh[i] = __uint_as_float(h);
        ol[i] = __uint_as_float(l);
    }
}

__global__ void copy_cont_split(const float* __restrict__ xc) {
    int i = blockIdx.x * blockDim.x + threadIdx.x;
    if (i < NN * 64) {
        int n = i >> 6, j = i & 63;
        uint32_t h, l;
        split_tf32(xc[i], h, l);
        g_xhi[(size_t)n * 192 + 128 + j] = __uint_as_float(h);
        g_xlo[(size_t)n * 192 + 128 + j] = __uint_as_float(l);
    }
}

// =====================================================================
// tf32 mma.sync GEMM with pre-split hi/lo operands (3xTF32)
// C[M x 128] = A[M x K] @ W[K x 128]
// Block tile 128x128, kstep 16, 8 warps 2(M) x 4(N), warp tile 64x32.
// INMODE: 0 = pre-split A arrays; 1 = embedding gather from pre-split table
// EPI: 0 = gelu(v+bias); 1 = v+bias (bias may be null); 2 = gelu(v+bias+agg/deg)
// OUTMODE: 0 = fp32 -> C0; 1 = hi -> C0, lo -> C1
// =====================================================================
#define LDK 20
#define LDN 136
#define A_SZ (128 * LDK)      // 2560 floats per half
#define B_SZ (16 * LDN)       // 2176 floats per half
#define STG_F (2 * A_SZ + 2 * B_SZ)            // 9472 floats per stage
#define SMEM_DYN (2 * STG_F * 4)               // 75776 bytes
// offsets within a stage (floats)
#define OFF_AH 0
#define OFF_AL A_SZ
#define OFF_BH (2 * A_SZ)
#define OFF_BL (2 * A_SZ + B_SZ)

template<int K, int INMODE, int EPI, int OUTMODE>
__global__ void __launch_bounds__(256, 2)
tgemm2(const float* __restrict__ Ahi, const float* __restrict__ Alo, int lda,
       const float* __restrict__ Bhi, const float* __restrict__ Blo,
       const float* __restrict__ bias,
       float* __restrict__ C0, float* __restrict__ C1, int ldc,
       const int* __restrict__ xcat,
       const float* __restrict__ Ehi, const float* __restrict__ Elo)
{
    extern __shared__ __align__(16) float sm[];

    const int tid  = threadIdx.x;
    const int m0   = blockIdx.x * 128;
    const int wid  = tid >> 5;
    const int lane = tid & 31;
    const int g    = lane >> 2;   // 0..7
    const int tig  = lane & 3;    // 0..3
    const int warpM = (wid >> 2) * 64;
    const int warpN = (wid & 3) * 32;

    constexpr int NK = K / 16;

    float4 acc[4][4];
#pragma unroll
    for (int i = 0; i < 4; i++)
#pragma unroll
        for (int j = 0; j < 4; j++) acc[i][j] = make_float4(0.f, 0.f, 0.f, 0.f);

    auto copy_tile = [&](int buf, int k0) {
        float* st = sm + buf * STG_F;
        uint32_t stB = (uint32_t)__cvta_generic_to_shared(st);
        // A tiles: hi + lo, each 128 rows x 16 k = 512 float4  -> 1024 ops, 4/thread
#pragma unroll
        for (int i = 0; i < 4; i++) {
            int flat = tid + i * 256;          // 0..1023
            int half = flat >> 9;              // 0 = hi, 1 = lo
            int rem  = flat & 511;
            int r = rem >> 2, seg = rem & 3;
            int row = m0 + r; if (row >= NN) row = NN - 1;
            const float* src;
            if (INMODE == 1) {
                int c = k0 >> 5;
                int cat = xcat[(size_t)row * NCAT + c];
                src = (half ? Elo : Ehi) + ((size_t)(c * CARD + cat)) * EMBD + (k0 & 31) + seg * 4;
            } else {
                src = (half ? Alo : Ahi) + (size_t)row * lda + k0 + seg * 4;
            }
            uint32_t dst = stB + (uint32_t)((half ? OFF_AL : OFF_AH) + r * LDK + seg * 4) * 4;
            cpasync16(dst, src);
        }
        // B tiles: hi + lo, each 16 k x 128 n = 512 float4 -> 1024 ops, 4/thread
#pragma unroll
        for (int i = 0; i < 4; i++) {
            int flat = tid + i * 256;
            int half = flat >> 9;
            int rem  = flat & 511;
            int k = rem >> 5, n0 = (rem & 31) * 4;
            const float* src = (half ? Blo : Bhi) + (size_t)(k0 + k) * 128 + n0;
            uint32_t dst = stB + (uint32_t)((half ? OFF_BL : OFF_BH) + k * LDN + n0) * 4;
            cpasync16(dst, src);
        }
        cp_commit();
    };

    copy_tile(0, 0);

    for (int ks = 0; ks < NK; ks++) {
        if (ks + 1 < NK) {
            copy_tile((ks + 1) & 1, (ks + 1) * 16);
            cp_wait<1>();
        } else {
            cp_wait<0>();
        }
        __syncthreads();

        const float* st = sm + (ks & 1) * STG_F;
        const uint32_t* Ah = (const uint32_t*)(st + OFF_AH);
        const uint32_t* Al = (const uint32_t*)(st + OFF_AL);
        const uint32_t* Bh = (const uint32_t*)(st + OFF_BH);
        const uint32_t* Bl = (const uint32_t*)(st + OFF_BL);

#pragma unroll
        for (int kc = 0; kc < 16; kc += 8) {
            uint32_t bh[4][2], bl[4][2];
#pragma unroll
            for (int nt = 0; nt < 4; nt++) {
                int cb = warpN + nt * 8 + g;
                bh[nt][0] = Bh[(kc + tig) * LDN + cb];
                bh[nt][1] = Bh[(kc + tig + 4) * LDN + cb];
                bl[nt][0] = Bl[(kc + tig) * LDN + cb];
                bl[nt][1] = Bl[(kc + tig + 4) * LDN + cb];
            }
#pragma unroll
            for (int mt = 0; mt < 4; mt++) {
                int rm = warpM + mt * 16 + g;
                uint32_t ah[4], al[4];
                ah[0] = Ah[rm * LDK + kc + tig];
                ah[1] = Ah[(rm + 8) * LDK + kc + tig];
                ah[2] = Ah[rm * LDK + kc + tig + 4];
                ah[3] = Ah[(rm + 8) * LDK + kc + tig + 4];
                al[0] = Al[rm * LDK + kc + tig];
                al[1] = Al[(rm + 8) * LDK + kc + tig];
                al[2] = Al[rm * LDK + kc + tig + 4];
                al[3] = Al[(rm + 8) * LDK + kc + tig + 4];
#pragma unroll
                for (int nt = 0; nt < 4; nt++) {
                    mma_tf32(acc[mt][nt], ah, bh[nt]);
                    mma_tf32(acc[mt][nt], ah, bl[nt]);
                    mma_tf32(acc[mt][nt], al, bh[nt]);
                }
            }
        }
        __syncthreads();
    }

    // epilogue
#pragma unroll
    for (int mt = 0; mt < 4; mt++) {
        int r0 = m0 + warpM + mt * 16 + g;
#pragma unroll
        for (int rr = 0; rr < 2; rr++) {
            int r = r0 + rr * 8;
            if (r >= NN) continue;
            float inv = 1.f;
            if (EPI == 2) inv = 1.f / fmaxf(g_deg[r], 1.f);
#pragma unroll
            for (int nt = 0; nt < 4; nt++) {
                int col = warpN + nt * 8 + tig * 2;
                float v0 = (rr == 0) ? acc[mt][nt].x : acc[mt][nt].z;
                float v1 = (rr == 0) ? acc[mt][nt].y : acc[mt][nt].w;
                if (bias) { v0 += bias[col]; v1 += bias[col + 1]; }
                if (EPI == 2) {
                    float2 ag = *(const float2*)&g_agg[(size_t)r * 128 + col];
                    v0 += ag.x * inv; v1 += ag.y * inv;
                }
                if (EPI != 1) { v0 = gelu_f(v0); v1 = gelu_f(v1); }
                if (OUTMODE == 0) {
                    *(float2*)&C0[(size_t)r * ldc + col] = make_float2(v0, v1);
                } else {
                    uint32_t h0, l0, h1, l1;
                    split_tf32(v0, h0, l0);
                    split_tf32(v1, h1, l1);
                    *(float2*)&C0[(size_t)r * ldc + col] =
                        make_float2(__uint_as_float(h0), __uint_as_float(h1));
                    *(float2*)&C1[(size_t)r * ldc + col] =
                        make_float2(__uint_as_float(l0), __uint_as_float(l1));
                }
            }
        }
    }
}

// ---------------- graph kernels ----------------
__global__ void deg_kernel(const int* __restrict__ ei, int E) {
    int e = blockIdx.x * blockDim.x + threadIdx.x;
    if (e < E) atomicAdd(&g_deg[ei[E + e]], 1.0f);
}

__global__ void scatter_vec(const float* __restrict__ y, const int* __restrict__ ei, int E) {
    int gidx = blockIdx.x * blockDim.x + threadIdx.x;
    int e = gidx >> 5;
    if (e >= E) return;
    int lane = gidx & 31;
    int src = __ldg(&ei[e]);
    int dst = __ldg(&ei[E + e]);
    float4 v = *(const float4*)&y[(size_t)src * 128 + lane * 4];
    float* p = &g_agg[(size_t)dst * 128 + lane * 4];
    asm volatile("red.global.add.v4.f32 [%0], {%1,%2,%3,%4};"
                 :: "l"(p), "f"(v.x), "f"(v.y), "f"(v.z), "f"(v.w) : "memory");
}

__global__ void conv3_dot(const float* __restrict__ Wl, const float* __restrict__ Wr) {
    int gidx = blockIdx.x * blockDim.x + threadIdx.x;
    int n = gidx >> 5;
    if (n >= NN) return;
    int lane = gidx & 31;
    float4 xv = *(const float4*)&g_h[(size_t)n * 128 + lane * 4];
    float4 wl = *(const float4*)&Wl[lane * 4];
    float4 wr = *(const float4*)&Wr[lane * 4];
    float s1 = xv.x * wl.x + xv.y * wl.y + xv.z * wl.z + xv.w * wl.w;
    float s2 = xv.x * wr.x + xv.y * wr.y + xv.z * wr.z + xv.w * wr.w;
#pragma unroll
    for (int o = 16; o > 0; o >>= 1) {
        s1 += __shfl_down_sync(0xffffffffu, s1, o);
        s2 += __shfl_down_sync(0xffffffffu, s2, o);
    }
    if (lane == 0) { g_s1[n] = s1; g_s2[n] = s2; }
}

__global__ void scatter_scalar(const int* __restrict__ ei, int E) {
    int e = blockIdx.x * blockDim.x + threadIdx.x;
    if (e < E) atomicAdd(&g_aggs[ei[E + e]], g_s1[ei[e]]);
}

__global__ void final_kernel(const float* __restrict__ bl, float* __restrict__ out) {
    int n = blockIdx.x * blockDim.x + threadIdx.x;
    if (n < NN) out[n] = g_aggs[n] / fmaxf(g_deg[n], 1.f) + bl[0] + g_s2[n];
}

// ---------------- host ----------------
extern "C" void kernel_launch(void* const* d_in, const int* in_sizes, int n_in,
                              void* d_out, int out_size) {
    (void)n_in; (void)out_size;
    const int*   x_cat  = (const int*)  d_in[0];
    const float* x_cont = (const float*)d_in[1];
    const int*   ei     = (const int*)  d_in[2];
    const float* emb    = (const float*)d_in[3];
    const float* W1     = (const float*)d_in[4];
    const float* b1     = (const float*)d_in[5];
    const float* W2     = (const float*)d_in[6];
    const float* b2     = (const float*)d_in[7];
    const float* W3     = (const float*)d_in[8];
    const float* b3     = (const float*)d_in[9];
    const float* c1_Wl  = (const float*)d_in[10];
    const float* c1_bl  = (const float*)d_in[11];
    const float* c1_Wr  = (const float*)d_in[12];
    const float* c2_Wl  = (const float*)d_in[13];
    const float* c2_bl  = (const float*)d_in[14];
    const float* c2_Wr  = (const float*)d_in[15];
    const float* c3_Wl  = (const float*)d_in[16];
    const float* c3_bl  = (const float*)d_in[17];
    const float* c3_Wr  = (const float*)d_in[18];
    float* out = (float*)d_out;

    const int E = in_sizes[2] / 2;

    float *p_xhi, *p_xlo, *p1h, *p1l, *p2h, *p2l, *p_y, *p_agg, *p_h;
    float *p_deg, *p_aggs, *wth, *wtl, *peh, *pel;
    cudaGetSymbolAddress((void**)&p_xhi, g_xhi);
    cudaGetSymbolAddress((void**)&p_xlo, g_xlo);
    cudaGetSymbolAddress((void**)&p1h, g_p1hi);
    cudaGetSymbolAddress((void**)&p1l, g_p1lo);
    cudaGetSymbolAddress((void**)&p2h, g_p2hi);
    cudaGetSymbolAddress((void**)&p2l, g_p2lo);
    cudaGetSymbolAddress((void**)&p_y, g_y);
    cudaGetSymbolAddress((void**)&p_agg, g_agg);
    cudaGetSymbolAddress((void**)&p_h, g_h);
    cudaGetSymbolAddress((void**)&p_deg, g_deg);
    cudaGetSymbolAddress((void**)&p_aggs, g_aggs);
    cudaGetSymbolAddress((void**)&wth, g_wthi);
    cudaGetSymbolAddress((void**)&wtl, g_wtlo);
    cudaGetSymbolAddress((void**)&peh, g_ehi);
    cudaGetSymbolAddress((void**)&pel, g_elo);

    // weight scratch offsets (floats), [k][n] layout preserved
    const int O_W1  = 0;        // 640*128
    const int O_W2  = 81920;    // 128*128
    const int O_W3  = 98304;
    const int O_C1L = 114688;   // 192*128
    const int O_C1R = 139264;
    const int O_C2L = 163840;
    const int O_C2R = 180224;

    cudaFuncSetAttribute(tgemm2<640, 1, 0, 1>, cudaFuncAttributeMaxDynamicSharedMemorySize, SMEM_DYN);
    cudaFuncSetAttribute(tgemm2<128, 0, 0, 1>, cudaFuncAttributeMaxDynamicSharedMemorySize, SMEM_DYN);
    cudaFuncSetAttribute(tgemm2<128, 0, 1, 1>, cudaFuncAttributeMaxDynamicSharedMemorySize, SMEM_DYN);
    cudaFuncSetAttribute(tgemm2<192, 0, 1, 0>, cudaFuncAttributeMaxDynamicSharedMemorySize, SMEM_DYN);
    cudaFuncSetAttribute(tgemm2<192, 0, 2, 1>, cudaFuncAttributeMaxDynamicSharedMemorySize, SMEM_DYN);
    cudaFuncSetAttribute(tgemm2<128, 0, 1, 0>, cudaFuncAttributeMaxDynamicSharedMemorySize, SMEM_DYN);
    cudaFuncSetAttribute(tgemm2<128, 0, 2, 0>, cudaFuncAttributeMaxDynamicSharedMemorySize, SMEM_DYN);

    const int GB = (NN + 127) / 128;

    // prep (independent of MLP chain)
    zero_kernel<<<128, 256>>>(p_deg, NN / 4);
    deg_kernel<<<(E + 255) / 256, 256>>>(ei, E);
    split_arr<<<(640 * 128 + 255) / 256, 256>>>(W1, 640 * 128, wth + O_W1, wtl + O_W1);
    split_arr<<<(128 * 128 + 255) / 256, 256>>>(W2, 128 * 128, wth + O_W2, wtl + O_W2);
    split_arr<<<(128 * 128 + 255) / 256, 256>>>(W3, 128 * 128, wth + O_W3, wtl + O_W3);
    split_arr<<<(192 * 128 + 255) / 256, 256>>>(c1_Wl, 192 * 128, wth + O_C1L, wtl + O_C1L);
    split_arr<<<(192 * 128 + 255) / 256, 256>>>(c1_Wr, 192 * 128, wth + O_C1R, wtl + O_C1R);
    split_arr<<<(128 * 128 + 255) / 256, 256>>>(c2_Wl, 128 * 128, wth + O_C2L, wtl + O_C2L);
    split_arr<<<(128 * 128 + 255) / 256, 256>>>(c2_Wr, 128 * 128, wth + O_C2R, wtl + O_C2R);
    split_arr<<<(NCAT * CARD * EMBD + 255) / 256, 256>>>(emb, NCAT * CARD * EMBD, peh, pel);
    copy_cont_split<<<(NN * 64 + 255) / 256, 256>>>(x_cont);

    // MLP
    tgemm2<640, 1, 0, 1><<<GB, 256, SMEM_DYN>>>(nullptr, nullptr, 0, wth + O_W1, wtl + O_W1,
                                                b1, p1h, p1l, 128, x_cat, peh, pel);
    tgemm2<128, 0, 0, 1><<<GB, 256, SMEM_DYN>>>(p1h, p1l, 128, wth + O_W2, wtl + O_W2,
                                                b2, p2h, p2l, 128, nullptr, nullptr, nullptr);
    tgemm2<128, 0, 1, 1><<<GB, 256, SMEM_DYN>>>(p2h, p2l, 128, wth + O_W3, wtl + O_W3,
                                                b3, p_xhi, p_xlo, 192, nullptr, nullptr, nullptr);

    // conv1
    zero_kernel<<<2048, 256>>>(p_agg, NN * 128 / 4);
    tgemm2<192, 0, 1, 0><<<GB, 256, SMEM_DYN>>>(p_xhi, p_xlo, 192, wth + O_C1L, wtl + O_C1L,
                                                nullptr, p_y, nullptr, 128, nullptr, nullptr, nullptr);
    scatter_vec<<<(E * 32 + 255) / 256, 256>>>(p_y, ei, E);
    tgemm2<192, 0, 2, 1><<<GB, 256, SMEM_DYN>>>(p_xhi, p_xlo, 192, wth + O_C1R, wtl + O_C1R,
                                                c1_bl, p1h, p1l, 128, nullptr, nullptr, nullptr);

    // conv2
    zero_kernel<<<2048, 256>>>(p_agg, NN * 128 / 4);
    tgemm2<128, 0, 1, 0><<<GB, 256, SMEM_DYN>>>(p1h, p1l, 128, wth + O_C2L, wtl + O_C2L,
                                                nullptr, p_y, nullptr, 128, nullptr, nullptr, nullptr);
    scatter_vec<<<(E * 32 + 255) / 256, 256>>>(p_y, ei, E);
    tgemm2<128, 0, 2, 0><<<GB, 256, SMEM_DYN>>>(p1h, p1l, 128, wth + O_C2R, wtl + O_C2R,
                                                c2_bl, p_h, nullptr, 128, nullptr, nullptr, nullptr);

    // conv3 (scalar)
    conv3_dot<<<(NN * 32 + 255) / 256, 256>>>(c3_Wl, c3_Wr);
    zero_kernel<<<128, 256>>>(p_aggs, NN / 4);
    scatter_scalar<<<(E + 255) / 256, 256>>>(ei, E);
    final_kernel<<<(NN + 255) / 256, 256>>>(c3_bl, out);
}

// round 5
// speedup vs baseline: 1.3568x; 1.3568x over previous
#include <cuda_runtime.h>
#include <cuda_bf16.h>
#include <cstdint>
#include <math.h>

#define NN   100000
#define NCAT 20
#define EMBD 32
#define CARD 100

typedef __nv_bfloat16 bf16;
typedef __nv_bfloat162 bf162;

// ---------------- scratch (device globals) ----------------
__device__ bf16 g_xhi[(size_t)NN * 192], g_xlo[(size_t)NN * 192];
__device__ bf16 g_p1hi[(size_t)NN * 128], g_p1lo[(size_t)NN * 128];
__device__ bf16 g_p2hi[(size_t)NN * 128], g_p2lo[(size_t)NN * 128];
__device__ float g_y[(size_t)NN * 128];
__device__ float g_agg[(size_t)NN * 128];
__device__ float g_h[(size_t)NN * 128];
__device__ float g_deg[NN], g_s1[NN], g_s2[NN], g_aggs[NN];
__device__ bf16 g_wthi[1536 * 128], g_wtlo[1536 * 128];   // [n][k] transposed
__device__ bf16 g_ehi[NCAT * CARD * EMBD], g_elo[NCAT * CARD * EMBD];

__device__ __forceinline__ float gelu_f(float v) {
    return 0.5f * v * (1.0f + erff(v * 0.70710678118654752f));
}

__device__ __forceinline__ void split_bf(float v, bf16& h, bf16& l) {
    h = __float2bfloat16(v);
    l = __float2bfloat16(v - __bfloat162float(h));
}

__device__ __forceinline__ void mma_bf16(float4& c, const uint32_t* a, const uint32_t* b) {
    asm volatile("mma.sync.aligned.m16n8k16.row.col.f32.bf16.bf16.f32 "
                 "{%0,%1,%2,%3}, {%4,%5,%6,%7}, {%8,%9}, {%0,%1,%2,%3};"
                 : "+f"(c.x), "+f"(c.y), "+f"(c.z), "+f"(c.w)
                 : "r"(a[0]), "r"(a[1]), "r"(a[2]), "r"(a[3]), "r"(b[0]), "r"(b[1]));
}

__device__ __forceinline__ void cpasync16(uint32_t dst, const void* src) {
    asm volatile("cp.async.cg.shared.global [%0], [%1], 16;" :: "r"(dst), "l"(src));
}
__device__ __forceinline__ void cp_commit() { asm volatile("cp.async.commit_group;"); }
template<int N> __device__ __forceinline__ void cp_wait() {
    asm volatile("cp.async.wait_group %0;" :: "n"(N));
}

// ---------------- utility kernels ----------------
__global__ void zero_kernel(float* __restrict__ p, int n4) {
    int i = blockIdx.x * blockDim.x + threadIdx.x;
    int stride = gridDim.x * blockDim.x;
    float4* p4 = (float4*)p;
    float4 z = make_float4(0.f, 0.f, 0.f, 0.f);
    for (; i < n4; i += stride) p4[i] = z;
}

// W [K][128] fp32 -> out [128][K] bf16 hi/lo
__global__ void prep_weight(const float* __restrict__ W, int K,
                            bf16* __restrict__ oh, bf16* __restrict__ ol) {
    int i = blockIdx.x * blockDim.x + threadIdx.x;
    if (i < 128 * K) {
        int k = i >> 7, n = i & 127;            // coalesced read
        float v = W[i];
        bf16 h, l; split_bf(v, h, l);
        oh[(size_t)n * K + k] = h;
        ol[(size_t)n * K + k] = l;
    }
}

__global__ void prep_emb(const float* __restrict__ src, int n) {
    int i = blockIdx.x * blockDim.x + threadIdx.x;
    if (i < n) {
        bf16 h, l; split_bf(src[i], h, l);
        g_ehi[i] = h; g_elo[i] = l;
    }
}

__global__ void copy_cont_split(const float* __restrict__ xc) {
    int i = blockIdx.x * blockDim.x + threadIdx.x;
    if (i < NN * 64) {
        int n = i >> 6, j = i & 63;
        bf16 h, l; split_bf(xc[i], h, l);
        g_xhi[(size_t)n * 192 + 128 + j] = h;
        g_xlo[(size_t)n * 192 + 128 + j] = l;
    }
}

// =====================================================================
// bf16-pair (3-term) tensor GEMM: C[M x 128] = A[M x K] @ W[K x 128]
// Block tile 128x128, kstep 32, 8 warps 2(M) x 4(N), warp tile 64x32.
// smem per stage: AH 8K | AL 8K | BH 8K | BL 8K = 32KB; 2 stages = 64KB.
// Rows stored as 32 bf16 (16 words), word-group swizzle g' = g ^ ((row>>1)&3).
// INMODE: 0 = pre-split A; 1 = embedding gather from pre-split table
// EPI: 0 = gelu(v+bias); 1 = v+bias; 2 = gelu(v+bias+agg/deg)
// OUTMODE: 0 = fp32 -> C0; 1 = bf16 hi->C0, lo->C1
// =====================================================================
#define SMEM_DYN 65536

template<int K, int INMODE, int EPI, int OUTMODE>
__global__ void __launch_bounds__(256, 2)
tgemm3(const bf16* __restrict__ Ahi, const bf16* __restrict__ Alo, int lda,
       const bf16* __restrict__ Bhi, const bf16* __restrict__ Blo,
       const float* __restrict__ bias,
       void* __restrict__ C0, void* __restrict__ C1, int ldc,
       const int* __restrict__ xcat,
       const bf16* __restrict__ Ehi, const bf16* __restrict__ Elo)
{
    extern __shared__ __align__(16) char sm[];

    const int tid  = threadIdx.x;
    const int m0   = blockIdx.x * 128;
    const int wid  = tid >> 5;
    const int lane = tid & 31;
    const int g    = lane >> 2;   // 0..7
    const int tig  = lane & 3;    // 0..3
    const int warpM = (wid >> 2) * 64;
    const int warpN = (wid & 3) * 32;

    constexpr int NC = K / 32;
    const uint32_t smB = (uint32_t)__cvta_generic_to_shared(sm);

    float4 acc[4][4];
#pragma unroll
    for (int i = 0; i < 4; i++)
#pragma unroll
        for (int j = 0; j < 4; j++) acc[i][j] = make_float4(0.f, 0.f, 0.f, 0.f);

    auto copy_tile = [&](int buf, int k0) {
        uint32_t st = smB + (uint32_t)buf * 32768;
        // A tiles (hi+lo): 128 rows x 32 bf16 = 4 segs of 16B per row per half
#pragma unroll
        for (int i = 0; i < 4; i++) {
            int flat = tid + i * 256;          // 0..1023
            int half = flat >> 9;
            int rem  = flat & 511;
            int r = rem >> 2, seg = rem & 3;
            int row = m0 + r; if (row >= NN) row = NN - 1;
            const bf16* src;
            if (INMODE == 1) {
                int c = k0 >> 5;
                int cat = xcat[(size_t)row * NCAT + c];
                src = (half ? Elo : Ehi) + (size_t)(c * CARD + cat) * EMBD + seg * 8;
            } else {
                src = (half ? Alo : Ahi) + (size_t)row * lda + k0 + seg * 8;
            }
            uint32_t dst = st + (uint32_t)half * 8192 + (uint32_t)r * 64
                         + (uint32_t)((seg ^ ((r >> 1) & 3)) << 4);
            cpasync16(dst, src);
        }
        // B tiles (hi+lo): 128 n-rows x 32 bf16
#pragma unroll
        for (int i = 0; i < 4; i++) {
            int flat = tid + i * 256;
            int half = flat >> 9;
            int rem  = flat & 511;
            int n = rem >> 2, seg = rem & 3;
            const bf16* src = (half ? Blo : Bhi) + (size_t)n * K + k0 + seg * 8;
            uint32_t dst = st + 16384u + (uint32_t)half * 8192 + (uint32_t)n * 64
                         + (uint32_t)((seg ^ ((n >> 1) & 3)) << 4);
            cpasync16(dst, src);
        }
        cp_commit();
    };

    copy_tile(0, 0);

    for (int ks = 0; ks < NC; ks++) {
        if (ks + 1 < NC) {
            copy_tile((ks + 1) & 1, (ks + 1) * 32);
            cp_wait<1>();
        } else {
            cp_wait<0>();
        }
        __syncthreads();

        const uint32_t* S = (const uint32_t*)(sm + (ks & 1) * 32768);
        const uint32_t* Ah32 = S;
        const uint32_t* Al32 = S + 2048;
        const uint32_t* Bh32 = S + 4096;
        const uint32_t* Bl32 = S + 6144;

#pragma unroll
        for (int kc = 0; kc < 2; kc++) {
            const int q0 = kc * 2;
            uint32_t bh[4][2], bl[4][2];
#pragma unroll
            for (int nt = 0; nt < 4; nt++) {
                int n = warpN + nt * 8 + g;
                int qa = (q0 ^ ((n >> 1) & 3)) << 2;
                int i0 = n * 16 + tig;
                bh[nt][0] = Bh32[i0 + qa];
                bh[nt][1] = Bh32[i0 + (qa ^ 4)];
                bl[nt][0] = Bl32[i0 + qa];
                bl[nt][1] = Bl32[i0 + (qa ^ 4)];
            }
#pragma unroll
            for (int mt = 0; mt < 4; mt++) {
                int r1 = warpM + mt * 16 + g;
                int r2 = r1 + 8;
                int qa = (q0 ^ ((r1 >> 1) & 3)) << 2;
                int qb = (q0 ^ ((r2 >> 1) & 3)) << 2;
                int i1 = r1 * 16 + tig, i2 = r2 * 16 + tig;
                uint32_t ah[4], al[4];
                ah[0] = Ah32[i1 + qa]; ah[1] = Ah32[i2 + qb];
                ah[2] = Ah32[i1 + (qa ^ 4)]; ah[3] = Ah32[i2 + (qb ^ 4)];
                al[0] = Al32[i1 + qa]; al[1] = Al32[i2 + qb];
                al[2] = Al32[i1 + (qa ^ 4)]; al[3] = Al32[i2 + (qb ^ 4)];
#pragma unroll
                for (int nt = 0; nt < 4; nt++) {
                    mma_bf16(acc[mt][nt], ah, bh[nt]);
                    mma_bf16(acc[mt][nt], ah, bl[nt]);
                    mma_bf16(acc[mt][nt], al, bh[nt]);
                }
            }
        }
        __syncthreads();
    }

    // epilogue
#pragma unroll
    for (int mt = 0; mt < 4; mt++) {
        int r0 = m0 + warpM + mt * 16 + g;
#pragma unroll
        for (int rr = 0; rr < 2; rr++) {
            int r = r0 + rr * 8;
            if (r >= NN) continue;
            float inv = 1.f;
            if (EPI == 2) inv = 1.f / fmaxf(g_deg[r], 1.f);
#pragma unroll
            for (int nt = 0; nt < 4; nt++) {
                int col = warpN + nt * 8 + tig * 2;
                float v0 = (rr == 0) ? acc[mt][nt].x : acc[mt][nt].z;
                float v1 = (rr == 0) ? acc[mt][nt].y : acc[mt][nt].w;
                if (bias) { v0 += bias[col]; v1 += bias[col + 1]; }
                if (EPI == 2) {
                    float2 ag = *(const float2*)&g_agg[(size_t)r * 128 + col];
                    v0 += ag.x * inv; v1 += ag.y * inv;
                }
                if (EPI != 1) { v0 = gelu_f(v0); v1 = gelu_f(v1); }
                if (OUTMODE == 0) {
                    *(float2*)((float*)C0 + (size_t)r * ldc + col) = make_float2(v0, v1);
                } else {
                    bf16 h0, l0, h1, l1;
                    split_bf(v0, h0, l0);
                    split_bf(v1, h1, l1);
                    bf162 hv; hv.x = h0; hv.y = h1;
                    bf162 lv; lv.x = l0; lv.y = l1;
                    *(bf162*)((bf16*)C0 + (size_t)r * ldc + col) = hv;
                    *(bf162*)((bf16*)C1 + (size_t)r * ldc + col) = lv;
                }
            }
        }
    }
}

// ---------------- graph kernels ----------------
__global__ void deg_kernel(const int* __restrict__ ei, int E) {
    int e = blockIdx.x * blockDim.x + threadIdx.x;
    if (e < E) atomicAdd(&g_deg[ei[E + e]], 1.0f);
}

__global__ void scatter_vec(const float* __restrict__ y, const int* __restrict__ ei, int E) {
    int gidx = blockIdx.x * blockDim.x + threadIdx.x;
    int e = gidx >> 5;
    if (e >= E) return;
    int lane = gidx & 31;
    int src = __ldg(&ei[e]);
    int dst = __ldg(&ei[E + e]);
    float4 v = *(const float4*)&y[(size_t)src * 128 + lane * 4];
    float* p = &g_agg[(size_t)dst * 128 + lane * 4];
    asm volatile("red.global.add.v4.f32 [%0], {%1,%2,%3,%4};"
                 :: "l"(p), "f"(v.x), "f"(v.y), "f"(v.z), "f"(v.w) : "memory");
}

__global__ void conv3_dot(const float* __restrict__ Wl, const float* __restrict__ Wr) {
    int gidx = blockIdx.x * blockDim.x + threadIdx.x;
    int n = gidx >> 5;
    if (n >= NN) return;
    int lane = gidx & 31;
    float4 xv = *(const float4*)&g_h[(size_t)n * 128 + lane * 4];
    float4 wl = *(const float4*)&Wl[lane * 4];
    float4 wr = *(const float4*)&Wr[lane * 4];
    float s1 = xv.x * wl.x + xv.y * wl.y + xv.z * wl.z + xv.w * wl.w;
    float s2 = xv.x * wr.x + xv.y * wr.y + xv.z * wr.z + xv.w * wr.w;
#pragma unroll
    for (int o = 16; o > 0; o >>= 1) {
        s1 += __shfl_down_sync(0xffffffffu, s1, o);
        s2 += __shfl_down_sync(0xffffffffu, s2, o);
    }
    if (lane == 0) { g_s1[n] = s1; g_s2[n] = s2; }
}

__global__ void scatter_scalar(const int* __restrict__ ei, int E) {
    int e = blockIdx.x * blockDim.x + threadIdx.x;
    if (e < E) atomicAdd(&g_aggs[ei[E + e]], g_s1[ei[e]]);
}

__global__ void final_kernel(const float* __restrict__ bl, float* __restrict__ out) {
    int n = blockIdx.x * blockDim.x + threadIdx.x;
    if (n < NN) out[n] = g_aggs[n] / fmaxf(g_deg[n], 1.f) + bl[0] + g_s2[n];
}

// ---------------- host ----------------
extern "C" void kernel_launch(void* const* d_in, const int* in_sizes, int n_in,
                              void* d_out, int out_size) {
    (void)n_in; (void)out_size;
    const int*   x_cat  = (const int*)  d_in[0];
    const float* x_cont = (const float*)d_in[1];
    const int*   ei     = (const int*)  d_in[2];
    const float* emb    = (const float*)d_in[3];
    const float* W1     = (const float*)d_in[4];
    const float* b1     = (const float*)d_in[5];
    const float* W2     = (const float*)d_in[6];
    const float* b2     = (const float*)d_in[7];
    const float* W3     = (const float*)d_in[8];
    const float* b3     = (const float*)d_in[9];
    const float* c1_Wl  = (const float*)d_in[10];
    const float* c1_bl  = (const float*)d_in[11];
    const float* c1_Wr  = (const float*)d_in[12];
    const float* c2_Wl  = (const float*)d_in[13];
    const float* c2_bl  = (const float*)d_in[14];
    const float* c2_Wr  = (const float*)d_in[15];
    const float* c3_Wl  = (const float*)d_in[16];
    const float* c3_bl  = (const float*)d_in[17];
    const float* c3_Wr  = (const float*)d_in[18];
    float* out = (float*)d_out;

    const int E = in_sizes[2] / 2;

    bf16 *p_xhi, *p_xlo, *p1h, *p1l, *p2h, *p2l, *wth, *wtl, *peh, *pel;
    float *p_y, *p_agg, *p_h, *p_deg, *p_aggs;
    cudaGetSymbolAddress((void**)&p_xhi, g_xhi);
    cudaGetSymbolAddress((void**)&p_xlo, g_xlo);
    cudaGetSymbolAddress((void**)&p1h, g_p1hi);
    cudaGetSymbolAddress((void**)&p1l, g_p1lo);
    cudaGetSymbolAddress((void**)&p2h, g_p2hi);
    cudaGetSymbolAddress((void**)&p2l, g_p2lo);
    cudaGetSymbolAddress((void**)&p_y, g_y);
    cudaGetSymbolAddress((void**)&p_agg, g_agg);
    cudaGetSymbolAddress((void**)&p_h, g_h);
    cudaGetSymbolAddress((void**)&p_deg, g_deg);
    cudaGetSymbolAddress((void**)&p_aggs, g_aggs);
    cudaGetSymbolAddress((void**)&wth, g_wthi);
    cudaGetSymbolAddress((void**)&wtl, g_wtlo);
    cudaGetSymbolAddress((void**)&peh, g_ehi);
    cudaGetSymbolAddress((void**)&pel, g_elo);

    // transposed weight offsets (elements)
    const int O_W1  = 0;        // 128 x 640
    const int O_W2  = 81920;    // 128 x 128
    const int O_W3  = 98304;
    const int O_C1L = 114688;   // 128 x 192
    const int O_C1R = 139264;
    const int O_C2L = 163840;
    const int O_C2R = 180224;

    cudaFuncSetAttribute(tgemm3<640, 1, 0, 1>, cudaFuncAttributeMaxDynamicSharedMemorySize, SMEM_DYN);
    cudaFuncSetAttribute(tgemm3<128, 0, 0, 1>, cudaFuncAttributeMaxDynamicSharedMemorySize, SMEM_DYN);
    cudaFuncSetAttribute(tgemm3<128, 0, 1, 1>, cudaFuncAttributeMaxDynamicSharedMemorySize, SMEM_DYN);
    cudaFuncSetAttribute(tgemm3<192, 0, 1, 0>, cudaFuncAttributeMaxDynamicSharedMemorySize, SMEM_DYN);
    cudaFuncSetAttribute(tgemm3<192, 0, 2, 1>, cudaFuncAttributeMaxDynamicSharedMemorySize, SMEM_DYN);
    cudaFuncSetAttribute(tgemm3<128, 0, 1, 0>, cudaFuncAttributeMaxDynamicSharedMemorySize, SMEM_DYN);
    cudaFuncSetAttribute(tgemm3<128, 0, 2, 0>, cudaFuncAttributeMaxDynamicSharedMemorySize, SMEM_DYN);

    const int GB = (NN + 127) / 128;

    // launch index 5 = big MLP gemm (profiled by ncu -s 5 -c 1)
    prep_weight<<<(640 * 128 + 255) / 256, 256>>>(W1, 640, wth + O_W1, wtl + O_W1);       // 0
    prep_emb<<<(NCAT * CARD * EMBD + 255) / 256, 256>>>(emb, NCAT * CARD * EMBD);          // 1
    zero_kernel<<<128, 256>>>(p_deg, NN / 4);                                              // 2
    deg_kernel<<<(E + 255) / 256, 256>>>(ei, E);                                           // 3
    copy_cont_split<<<(NN * 64 + 255) / 256, 256>>>(x_cont);                               // 4
    tgemm3<640, 1, 0, 1><<<GB, 256, SMEM_DYN>>>(nullptr, nullptr, 0, wth + O_W1, wtl + O_W1,
                                                b1, p1h, p1l, 128, x_cat, peh, pel);       // 5

    prep_weight<<<(128 * 128 + 255) / 256, 256>>>(W2, 128, wth + O_W2, wtl + O_W2);
    prep_weight<<<(128 * 128 + 255) / 256, 256>>>(W3, 128, wth + O_W3, wtl + O_W3);
    prep_weight<<<(192 * 128 + 255) / 256, 256>>>(c1_Wl, 192, wth + O_C1L, wtl + O_C1L);
    prep_weight<<<(192 * 128 + 255) / 256, 256>>>(c1_Wr, 192, wth + O_C1R, wtl + O_C1R);
    prep_weight<<<(128 * 128 + 255) / 256, 256>>>(c2_Wl, 128, wth + O_C2L, wtl + O_C2L);
    prep_weight<<<(128 * 128 + 255) / 256, 256>>>(c2_Wr, 128, wth + O_C2R, wtl + O_C2R);

    tgemm3<128, 0, 0, 1><<<GB, 256, SMEM_DYN>>>(p1h, p1l, 128, wth + O_W2, wtl + O_W2,
                                                b2, p2h, p2l, 128, nullptr, nullptr, nullptr);
    tgemm3<128, 0, 1, 1><<<GB, 256, SMEM_DYN>>>(p2h, p2l, 128, wth + O_W3, wtl + O_W3,
                                                b3, p_xhi, p_xlo, 192, nullptr, nullptr, nullptr);

    // conv1
    zero_kernel<<<2048, 256>>>(p_agg, NN * 128 / 4);
    tgemm3<192, 0, 1, 0><<<GB, 256, SMEM_DYN>>>(p_xhi, p_xlo, 192, wth + O_C1L, wtl + O_C1L,
                                                nullptr, p_y, nullptr, 128, nullptr, nullptr, nullptr);
    scatter_vec<<<(E * 32 + 255) / 256, 256>>>(p_y, ei, E);
    tgemm3<192, 0, 2, 1><<<GB, 256, SMEM_DYN>>>(p_xhi, p_xlo, 192, wth + O_C1R, wtl + O_C1R,
                                                c1_bl, p1h, p1l, 128, nullptr, nullptr, nullptr);

    // conv2
    zero_kernel<<<2048, 256>>>(p_agg, NN * 128 / 4);
    tgemm3<128, 0, 1, 0><<<GB, 256, SMEM_DYN>>>(p1h, p1l, 128, wth + O_C2L, wtl + O_C2L,
                                                nullptr, p_y, nullptr, 128, nullptr, nullptr, nullptr);
    scatter_vec<<<(E * 32 + 255) / 256, 256>>>(p_y, ei, E);
    tgemm3<128, 0, 2, 0><<<GB, 256, SMEM_DYN>>>(p1h, p1l, 128, wth + O_C2R, wtl + O_C2R,
                                                c2_bl, p_h, nullptr, 128, nullptr, nullptr, nullptr);

    // conv3 (scalar)
    conv3_dot<<<(NN * 32 + 255) / 256, 256>>>(c3_Wl, c3_Wr);
    zero_kernel<<<128, 256>>>(p_aggs, NN / 4);
    scatter_scalar<<<(E + 255) / 256, 256>>>(ei, E);
    final_kernel<<<(NN + 255) / 256, 256>>>(c3_bl, out);
}

// round 6
// speedup vs baseline: 2.0399x; 1.5034x over previous
#include <cuda_runtime.h>
#include <cuda_bf16.h>
#include <cstdint>
#include <math.h>

#define NN   100000
#define NE   1600000
#define NCAT 20
#define EMBD 32
#define CARD 100
#define NB_SCAN 98   // ceil(NN/1024)

typedef __nv_bfloat16 bf16;
typedef __nv_bfloat162 bf162;

// ---------------- scratch (device globals) ----------------
__device__ bf16 g_xhi[(size_t)NN * 192], g_xlo[(size_t)NN * 192];
__device__ bf16 g_p1hi[(size_t)NN * 128], g_p1lo[(size_t)NN * 128];
__device__ bf16 g_p2hi[(size_t)NN * 128], g_p2lo[(size_t)NN * 128];
__device__ float g_y[(size_t)NN * 128];
__device__ float g_z[(size_t)NN * 128];
__device__ float g_agg[(size_t)NN * 128];
__device__ float g_h[(size_t)NN * 128];
__device__ float g_s1[NN], g_s2[NN];
__device__ bf16 g_wthi[1536 * 128], g_wtlo[1536 * 128];   // [n][k] transposed
__device__ bf16 g_ehi[NCAT * CARD * EMBD], g_elo[NCAT * CARD * EMBD];
// CSR
__device__ int g_cnt[NN];
__device__ int g_start[NN + 1];
__device__ int g_cursor[NN];
__device__ int g_csrc[NE];
__device__ int g_bsum[NB_SCAN];

__device__ __forceinline__ float gelu_f(float v) {
    return 0.5f * v * (1.0f + erff(v * 0.70710678118654752f));
}
__device__ __forceinline__ void split_bf(float v, bf16& h, bf16& l) {
    h = __float2bfloat16(v);
    l = __float2bfloat16(v - __bfloat162float(h));
}
__device__ __forceinline__ void mma_bf16(float4& c, const uint32_t* a, const uint32_t* b) {
    asm volatile("mma.sync.aligned.m16n8k16.row.col.f32.bf16.bf16.f32 "
                 "{%0,%1,%2,%3}, {%4,%5,%6,%7}, {%8,%9}, {%0,%1,%2,%3};"
                 : "+f"(c.x), "+f"(c.y), "+f"(c.z), "+f"(c.w)
                 : "r"(a[0]), "r"(a[1]), "r"(a[2]), "r"(a[3]), "r"(b[0]), "r"(b[1]));
}
__device__ __forceinline__ void cpasync16(uint32_t dst, const void* src) {
    asm volatile("cp.async.cg.shared.global [%0], [%1], 16;" :: "r"(dst), "l"(src));
}
__device__ __forceinline__ void cp_commit() { asm volatile("cp.async.commit_group;"); }
template<int N> __device__ __forceinline__ void cp_wait() {
    asm volatile("cp.async.wait_group %0;" :: "n"(N));
}

// ---------------- prep kernels ----------------
__global__ void prep_weight(const float* __restrict__ W, int K,
                            bf16* __restrict__ oh, bf16* __restrict__ ol) {
    int i = blockIdx.x * blockDim.x + threadIdx.x;
    if (i < 128 * K) {
        int k = i >> 7, n = i & 127;
        float v = W[i];
        bf16 h, l; split_bf(v, h, l);
        oh[(size_t)n * K + k] = h;
        ol[(size_t)n * K + k] = l;
    }
}
__global__ void prep_emb(const float* __restrict__ src, int n) {
    int i = blockIdx.x * blockDim.x + threadIdx.x;
    if (i < n) {
        bf16 h, l; split_bf(src[i], h, l);
        g_ehi[i] = h; g_elo[i] = l;
    }
}
__global__ void copy_cont_split(const float* __restrict__ xc) {
    int i = blockIdx.x * blockDim.x + threadIdx.x;
    if (i < NN * 64) {
        int n = i >> 6, j = i & 63;
        bf16 h, l; split_bf(xc[i], h, l);
        g_xhi[(size_t)n * 192 + 128 + j] = h;
        g_xlo[(size_t)n * 192 + 128 + j] = l;
    }
}

// ---------------- CSR build ----------------
__global__ void zero_cnt() {
    int i = blockIdx.x * blockDim.x + threadIdx.x;
    if (i < NN) g_cnt[i] = 0;
}
__global__ void count_k(const int* __restrict__ ei, int E) {
    int e = blockIdx.x * blockDim.x + threadIdx.x;
    if (e < E) atomicAdd(&g_cnt[ei[E + e]], 1);
}
__global__ void scan_block() {
    __shared__ int sh[1024];
    int tid = threadIdx.x;
    int i = blockIdx.x * 1024 + tid;
    int v = (i < NN) ? g_cnt[i] : 0;
    sh[tid] = v;
    __syncthreads();
#pragma unroll
    for (int off = 1; off < 1024; off <<= 1) {
        int t = (tid >= off) ? sh[tid - off] : 0;
        __syncthreads();
        sh[tid] += t;
        __syncthreads();
    }
    if (i < NN) g_start[i] = sh[tid] - v;     // exclusive within block
    if (tid == 1023) g_bsum[blockIdx.x] = sh[1023];
}
__global__ void scan_top() {
    if (threadIdx.x == 0) {
        int acc = 0;
        for (int j = 0; j < NB_SCAN; j++) { int t = g_bsum[j]; g_bsum[j] = acc; acc += t; }
        g_start[NN] = acc;
    }
}
__global__ void scan_add() {
    int i = blockIdx.x * blockDim.x + threadIdx.x;
    if (i < NN) {
        int s = g_start[i] + g_bsum[i >> 10];
        g_start[i] = s;
        g_cursor[i] = s;
    }
}
__global__ void fill_k(const int* __restrict__ ei, int E) {
    int e = blockIdx.x * blockDim.x + threadIdx.x;
    if (e < E) {
        int dst = ei[E + e];
        int pos = atomicAdd(&g_cursor[dst], 1);
        g_csrc[pos] = ei[e];
    }
}

// ---------------- gather kernels ----------------
// warp per node: agg[n] = mean of y[src] over in-edges (0 if none)
__global__ void gather_vec(const float* __restrict__ y, float* __restrict__ agg) {
    int w = (blockIdx.x * blockDim.x + threadIdx.x) >> 5;
    if (w >= NN) return;
    int lane = threadIdx.x & 31;
    int s = g_start[w], e = g_start[w + 1];
    float inv = 1.f / fmaxf((float)(e - s), 1.f);
    float4 a0 = make_float4(0.f, 0.f, 0.f, 0.f);
    float4 a1 = make_float4(0.f, 0.f, 0.f, 0.f);
    int i = s;
    for (; i + 1 < e; i += 2) {
        int r0 = g_csrc[i], r1 = g_csrc[i + 1];
        float4 v0 = *(const float4*)&y[(size_t)r0 * 128 + lane * 4];
        float4 v1 = *(const float4*)&y[(size_t)r1 * 128 + lane * 4];
        a0.x += v0.x; a0.y += v0.y; a0.z += v0.z; a0.w += v0.w;
        a1.x += v1.x; a1.y += v1.y; a1.z += v1.z; a1.w += v1.w;
    }
    if (i < e) {
        int r0 = g_csrc[i];
        float4 v0 = *(const float4*)&y[(size_t)r0 * 128 + lane * 4];
        a0.x += v0.x; a0.y += v0.y; a0.z += v0.z; a0.w += v0.w;
    }
    float4 o = make_float4((a0.x + a1.x) * inv, (a0.y + a1.y) * inv,
                           (a0.z + a1.z) * inv, (a0.w + a1.w) * inv);
    *(float4*)&agg[(size_t)w * 128 + lane * 4] = o;
}

// warp per node scalar gather + finalize: out = mean(s1[src]) + bl + s2[n]
__global__ void gather3_final(const float* __restrict__ bl, float* __restrict__ out) {
    int w = (blockIdx.x * blockDim.x + threadIdx.x) >> 5;
    if (w >= NN) return;
    int lane = threadIdx.x & 31;
    int s = g_start[w], e = g_start[w + 1];
    float inv = 1.f / fmaxf((float)(e - s), 1.f);
    float sum = 0.f;
    for (int i = s + lane; i < e; i += 32) sum += g_s1[g_csrc[i]];
#pragma unroll
    for (int o = 16; o > 0; o >>= 1) sum += __shfl_down_sync(0xffffffffu, sum, o);
    if (lane == 0) out[w] = sum * inv + bl[0] + g_s2[w];
}

// ---------------- epilogues: v = gelu(z + agg) ----------------
__global__ void ep_split(const float* __restrict__ z, const float* __restrict__ agg,
                         bf16* __restrict__ oh, bf16* __restrict__ ol) {
    int i = blockIdx.x * blockDim.x + threadIdx.x;
    if (i >= NN * 32) return;
    float4 zv = *(const float4*)&z[(size_t)i * 4];
    float4 av = *(const float4*)&agg[(size_t)i * 4];
    float v0 = gelu_f(zv.x + av.x), v1 = gelu_f(zv.y + av.y);
    float v2 = gelu_f(zv.z + av.z), v3 = gelu_f(zv.w + av.w);
    bf16 h0, l0, h1, l1, h2, l2, h3, l3;
    split_bf(v0, h0, l0); split_bf(v1, h1, l1);
    split_bf(v2, h2, l2); split_bf(v3, h3, l3);
    bf162 ha; ha.x = h0; ha.y = h1;
    bf162 hb; hb.x = h2; hb.y = h3;
    bf162 la; la.x = l0; la.y = l1;
    bf162 lb; lb.x = l2; lb.y = l3;
    *(bf162*)&oh[(size_t)i * 4] = ha;
    *(bf162*)&oh[(size_t)i * 4 + 2] = hb;
    *(bf162*)&ol[(size_t)i * 4] = la;
    *(bf162*)&ol[(size_t)i * 4 + 2] = lb;
}
__global__ void ep_f32(const float* __restrict__ z, const float* __restrict__ agg,
                       float* __restrict__ o) {
    int i = blockIdx.x * blockDim.x + threadIdx.x;
    if (i >= NN * 32) return;
    float4 zv = *(const float4*)&z[(size_t)i * 4];
    float4 av = *(const float4*)&agg[(size_t)i * 4];
    float4 ov = make_float4(gelu_f(zv.x + av.x), gelu_f(zv.y + av.y),
                            gelu_f(zv.z + av.z), gelu_f(zv.w + av.w));
    *(float4*)&o[(size_t)i * 4] = ov;
}

// ---------------- conv3 dots ----------------
__global__ void conv3_dot(const float* __restrict__ Wl, const float* __restrict__ Wr) {
    int gidx = blockIdx.x * blockDim.x + threadIdx.x;
    int n = gidx >> 5;
    if (n >= NN) return;
    int lane = gidx & 31;
    float4 xv = *(const float4*)&g_h[(size_t)n * 128 + lane * 4];
    float4 wl = *(const float4*)&Wl[lane * 4];
    float4 wr = *(const float4*)&Wr[lane * 4];
    float s1 = xv.x * wl.x + xv.y * wl.y + xv.z * wl.z + xv.w * wl.w;
    float s2 = xv.x * wr.x + xv.y * wr.y + xv.z * wr.z + xv.w * wr.w;
#pragma unroll
    for (int o = 16; o > 0; o >>= 1) {
        s1 += __shfl_down_sync(0xffffffffu, s1, o);
        s2 += __shfl_down_sync(0xffffffffu, s2, o);
    }
    if (lane == 0) { g_s1[n] = s1; g_s2[n] = s2; }
}

// =====================================================================
// bf16-pair (3-term) tensor GEMM (unchanged from R5)
// =====================================================================
#define SMEM_DYN 65536

template<int K, int INMODE, int EPI, int OUTMODE>
__global__ void __launch_bounds__(256, 2)
tgemm3(const bf16* __restrict__ Ahi, const bf16* __restrict__ Alo, int lda,
       const bf16* __restrict__ Bhi, const bf16* __restrict__ Blo,
       const float* __restrict__ bias,
       void* __restrict__ C0, void* __restrict__ C1, int ldc,
       const int* __restrict__ xcat,
       const bf16* __restrict__ Ehi, const bf16* __restrict__ Elo)
{
    extern __shared__ __align__(16) char sm[];

    const int tid  = threadIdx.x;
    const int m0   = blockIdx.x * 128;
    const int wid  = tid >> 5;
    const int lane = tid & 31;
    const int g    = lane >> 2;
    const int tig  = lane & 3;
    const int warpM = (wid >> 2) * 64;
    const int warpN = (wid & 3) * 32;

    constexpr int NC = K / 32;
    const uint32_t smB = (uint32_t)__cvta_generic_to_shared(sm);

    float4 acc[4][4];
#pragma unroll
    for (int i = 0; i < 4; i++)
#pragma unroll
        for (int j = 0; j < 4; j++) acc[i][j] = make_float4(0.f, 0.f, 0.f, 0.f);

    auto copy_tile = [&](int buf, int k0) {
        uint32_t st = smB + (uint32_t)buf * 32768;
#pragma unroll
        for (int i = 0; i < 4; i++) {
            int flat = tid + i * 256;
            int half = flat >> 9;
            int rem  = flat & 511;
            int r = rem >> 2, seg = rem & 3;
            int row = m0 + r; if (row >= NN) row = NN - 1;
            const bf16* src;
            if (INMODE == 1) {
                int c = k0 >> 5;
                int cat = xcat[(size_t)row * NCAT + c];
                src = (half ? Elo : Ehi) + (size_t)(c * CARD + cat) * EMBD + seg * 8;
            } else {
                src = (half ? Alo : Ahi) + (size_t)row * lda + k0 + seg * 8;
            }
            uint32_t dst = st + (uint32_t)half * 8192 + (uint32_t)r * 64
                         + (uint32_t)((seg ^ ((r >> 1) & 3)) << 4);
            cpasync16(dst, src);
        }
#pragma unroll
        for (int i = 0; i < 4; i++) {
            int flat = tid + i * 256;
            int half = flat >> 9;
            int rem  = flat & 511;
            int n = rem >> 2, seg = rem & 3;
            const bf16* src = (half ? Blo : Bhi) + (size_t)n * K + k0 + seg * 8;
            uint32_t dst = st + 16384u + (uint32_t)half * 8192 + (uint32_t)n * 64
                         + (uint32_t)((seg ^ ((n >> 1) & 3)) << 4);
            cpasync16(dst, src);
        }
        cp_commit();
    };

    copy_tile(0, 0);

    for (int ks = 0; ks < NC; ks++) {
        if (ks + 1 < NC) {
            copy_tile((ks + 1) & 1, (ks + 1) * 32);
            cp_wait<1>();
        } else {
            cp_wait<0>();
        }
        __syncthreads();

        const uint32_t* S = (const uint32_t*)(sm + (ks & 1) * 32768);
        const uint32_t* Ah32 = S;
        const uint32_t* Al32 = S + 2048;
        const uint32_t* Bh32 = S + 4096;
        const uint32_t* Bl32 = S + 6144;

#pragma unroll
        for (int kc = 0; kc < 2; kc++) {
            const int q0 = kc * 2;
            uint32_t bh[4][2], bl[4][2];
#pragma unroll
            for (int nt = 0; nt < 4; nt++) {
                int n = warpN + nt * 8 + g;
                int qa = (q0 ^ ((n >> 1) & 3)) << 2;
                int i0 = n * 16 + tig;
                bh[nt][0] = Bh32[i0 + qa];
                bh[nt][1] = Bh32[i0 + (qa ^ 4)];
                bl[nt][0] = Bl32[i0 + qa];
                bl[nt][1] = Bl32[i0 + (qa ^ 4)];
            }
#pragma unroll
            for (int mt = 0; mt < 4; mt++) {
                int r1 = warpM + mt * 16 + g;
                int r2 = r1 + 8;
                int qa = (q0 ^ ((r1 >> 1) & 3)) << 2;
                int qb = (q0 ^ ((r2 >> 1) & 3)) << 2;
                int i1 = r1 * 16 + tig, i2 = r2 * 16 + tig;
                uint32_t ah[4], al[4];
                ah[0] = Ah32[i1 + qa]; ah[1] = Ah32[i2 + qb];
                ah[2] = Ah32[i1 + (qa ^ 4)]; ah[3] = Ah32[i2 + (qb ^ 4)];
                al[0] = Al32[i1 + qa]; al[1] = Al32[i2 + qb];
                al[2] = Al32[i1 + (qa ^ 4)]; al[3] = Al32[i2 + (qb ^ 4)];
#pragma unroll
                for (int nt = 0; nt < 4; nt++) {
                    mma_bf16(acc[mt][nt], ah, bh[nt]);
                    mma_bf16(acc[mt][nt], ah, bl[nt]);
                    mma_bf16(acc[mt][nt], al, bh[nt]);
                }
            }
        }
        __syncthreads();
    }

#pragma unroll
    for (int mt = 0; mt < 4; mt++) {
        int r0 = m0 + warpM + mt * 16 + g;
#pragma unroll
        for (int rr = 0; rr < 2; rr++) {
            int r = r0 + rr * 8;
            if (r >= NN) continue;
#pragma unroll
            for (int nt = 0; nt < 4; nt++) {
                int col = warpN + nt * 8 + tig * 2;
                float v0 = (rr == 0) ? acc[mt][nt].x : acc[mt][nt].z;
                float v1 = (rr == 0) ? acc[mt][nt].y : acc[mt][nt].w;
                if (bias) { v0 += bias[col]; v1 += bias[col + 1]; }
                if (EPI == 0) { v0 = gelu_f(v0); v1 = gelu_f(v1); }
                if (OUTMODE == 0) {
                    *(float2*)((float*)C0 + (size_t)r * ldc + col) = make_float2(v0, v1);
                } else {
                    bf16 h0, l0, h1, l1;
                    split_bf(v0, h0, l0);
                    split_bf(v1, h1, l1);
                    bf162 hv; hv.x = h0; hv.y = h1;
                    bf162 lv; lv.x = l0; lv.y = l1;
                    *(bf162*)((bf16*)C0 + (size_t)r * ldc + col) = hv;
                    *(bf162*)((bf16*)C1 + (size_t)r * ldc + col) = lv;
                }
            }
        }
    }
}

// ---------------- host ----------------
extern "C" void kernel_launch(void* const* d_in, const int* in_sizes, int n_in,
                              void* d_out, int out_size) {
    (void)n_in; (void)out_size;
    const int*   x_cat  = (const int*)  d_in[0];
    const float* x_cont = (const float*)d_in[1];
    const int*   ei     = (const int*)  d_in[2];
    const float* emb    = (const float*)d_in[3];
    const float* W1     = (const float*)d_in[4];
    const float* b1     = (const float*)d_in[5];
    const float* W2     = (const float*)d_in[6];
    const float* b2     = (const float*)d_in[7];
    const float* W3     = (const float*)d_in[8];
    const float* b3     = (const float*)d_in[9];
    const float* c1_Wl  = (const float*)d_in[10];
    const float* c1_bl  = (const float*)d_in[11];
    const float* c1_Wr  = (const float*)d_in[12];
    const float* c2_Wl  = (const float*)d_in[13];
    const float* c2_bl  = (const float*)d_in[14];
    const float* c2_Wr  = (const float*)d_in[15];
    const float* c3_Wl  = (const float*)d_in[16];
    const float* c3_bl  = (const float*)d_in[17];
    const float* c3_Wr  = (const float*)d_in[18];
    float* out = (float*)d_out;

    const int E = in_sizes[2] / 2;

    bf16 *p_xhi, *p_xlo, *p1h, *p1l, *p2h, *p2l, *wth, *wtl, *peh, *pel;
    float *p_y, *p_z, *p_agg, *p_h;
    cudaGetSymbolAddress((void**)&p_xhi, g_xhi);
    cudaGetSymbolAddress((void**)&p_xlo, g_xlo);
    cudaGetSymbolAddress((void**)&p1h, g_p1hi);
    cudaGetSymbolAddress((void**)&p1l, g_p1lo);
    cudaGetSymbolAddress((void**)&p2h, g_p2hi);
    cudaGetSymbolAddress((void**)&p2l, g_p2lo);
    cudaGetSymbolAddress((void**)&p_y, g_y);
    cudaGetSymbolAddress((void**)&p_z, g_z);
    cudaGetSymbolAddress((void**)&p_agg, g_agg);
    cudaGetSymbolAddress((void**)&p_h, g_h);
    cudaGetSymbolAddress((void**)&wth, g_wthi);
    cudaGetSymbolAddress((void**)&wtl, g_wtlo);
    cudaGetSymbolAddress((void**)&peh, g_ehi);
    cudaGetSymbolAddress((void**)&pel, g_elo);

    const int O_W1  = 0;
    const int O_W2  = 81920;
    const int O_W3  = 98304;
    const int O_C1L = 114688;
    const int O_C1R = 139264;
    const int O_C2L = 163840;
    const int O_C2R = 180224;

    cudaFuncSetAttribute(tgemm3<640, 1, 0, 1>, cudaFuncAttributeMaxDynamicSharedMemorySize, SMEM_DYN);
    cudaFuncSetAttribute(tgemm3<128, 0, 0, 1>, cudaFuncAttributeMaxDynamicSharedMemorySize, SMEM_DYN);
    cudaFuncSetAttribute(tgemm3<128, 0, 1, 1>, cudaFuncAttributeMaxDynamicSharedMemorySize, SMEM_DYN);
    cudaFuncSetAttribute(tgemm3<192, 0, 1, 0>, cudaFuncAttributeMaxDynamicSharedMemorySize, SMEM_DYN);
    cudaFuncSetAttribute(tgemm3<128, 0, 1, 0>, cudaFuncAttributeMaxDynamicSharedMemorySize, SMEM_DYN);

    const int GB = (NN + 127) / 128;
    cudaStream_t ms = 0;

    // second stream + events (created per call; host-side cost only, not replayed)
    cudaStream_t s2;
    cudaStreamCreateWithFlags(&s2, cudaStreamNonBlocking);
    cudaEvent_t ev0, evY1, evG1, evY2, evG2;
    cudaEventCreateWithFlags(&ev0, cudaEventDisableTiming);
    cudaEventCreateWithFlags(&evY1, cudaEventDisableTiming);
    cudaEventCreateWithFlags(&evG1, cudaEventDisableTiming);
    cudaEventCreateWithFlags(&evY2, cudaEventDisableTiming);
    cudaEventCreateWithFlags(&evG2, cudaEventDisableTiming);

    cudaEventRecord(ev0, ms);
    cudaStreamWaitEvent(s2, ev0, 0);

    // main: MLP prep (launch indices 0-2, 5 = big GEMM for ncu -s 5)
    prep_weight<<<(640 * 128 + 255) / 256, 256, 0, ms>>>(W1, 640, wth + O_W1, wtl + O_W1);  // 0
    prep_emb<<<(NCAT * CARD * EMBD + 255) / 256, 256, 0, ms>>>(emb, NCAT * CARD * EMBD);     // 1
    copy_cont_split<<<(NN * 64 + 255) / 256, 256, 0, ms>>>(x_cont);                          // 2
    zero_cnt<<<(NN + 255) / 256, 256, 0, s2>>>();                                            // 3
    count_k<<<(E + 255) / 256, 256, 0, s2>>>(ei, E);                                         // 4
    tgemm3<640, 1, 0, 1><<<GB, 256, SMEM_DYN, ms>>>(nullptr, nullptr, 0, wth + O_W1, wtl + O_W1,
                                                    b1, p1h, p1l, 128, x_cat, peh, pel);     // 5
    // rest of CSR build on s2 (overlaps MLP chain)
    scan_block<<<NB_SCAN, 1024, 0, s2>>>();
    scan_top<<<1, 32, 0, s2>>>();
    scan_add<<<(NN + 255) / 256, 256, 0, s2>>>();
    fill_k<<<(E + 255) / 256, 256, 0, s2>>>(ei, E);

    // main: remaining weight prep + MLP
    prep_weight<<<(128 * 128 + 255) / 256, 256, 0, ms>>>(W2, 128, wth + O_W2, wtl + O_W2);
    prep_weight<<<(128 * 128 + 255) / 256, 256, 0, ms>>>(W3, 128, wth + O_W3, wtl + O_W3);
    prep_weight<<<(192 * 128 + 255) / 256, 256, 0, ms>>>(c1_Wl, 192, wth + O_C1L, wtl + O_C1L);
    prep_weight<<<(192 * 128 + 255) / 256, 256, 0, ms>>>(c1_Wr, 192, wth + O_C1R, wtl + O_C1R);
    prep_weight<<<(128 * 128 + 255) / 256, 256, 0, ms>>>(c2_Wl, 128, wth + O_C2L, wtl + O_C2L);
    prep_weight<<<(128 * 128 + 255) / 256, 256, 0, ms>>>(c2_Wr, 128, wth + O_C2R, wtl + O_C2R);

    tgemm3<128, 0, 0, 1><<<GB, 256, SMEM_DYN, ms>>>(p1h, p1l, 128, wth + O_W2, wtl + O_W2,
                                                    b2, p2h, p2l, 128, nullptr, nullptr, nullptr);
    tgemm3<128, 0, 1, 1><<<GB, 256, SMEM_DYN, ms>>>(p2h, p2l, 128, wth + O_W3, wtl + O_W3,
                                                    b3, p_xhi, p_xlo, 192, nullptr, nullptr, nullptr);

    // ---- conv1: y = x@Wl on main; gather on s2 overlapped with z = x@Wr + bl on main
    tgemm3<192, 0, 1, 0><<<GB, 256, SMEM_DYN, ms>>>(p_xhi, p_xlo, 192, wth + O_C1L, wtl + O_C1L,
                                                    nullptr, p_y, nullptr, 128, nullptr, nullptr, nullptr);
    cudaEventRecord(evY1, ms);
    cudaStreamWaitEvent(s2, evY1, 0);
    gather_vec<<<(NN * 32 + 255) / 256, 256, 0, s2>>>(p_y, p_agg);
    cudaEventRecord(evG1, s2);
    tgemm3<192, 0, 1, 0><<<GB, 256, SMEM_DYN, ms>>>(p_xhi, p_xlo, 192, wth + O_C1R, wtl + O_C1R,
                                                    c1_bl, p_z, nullptr, 128, nullptr, nullptr, nullptr);
    cudaStreamWaitEvent(ms, evG1, 0);
    ep_split<<<(NN * 32 + 255) / 256, 256, 0, ms>>>(p_z, p_agg, p1h, p1l);

    // ---- conv2
    tgemm3<128, 0, 1, 0><<<GB, 256, SMEM_DYN, ms>>>(p1h, p1l, 128, wth + O_C2L, wtl + O_C2L,
                                                    nullptr, p_y, nullptr, 128, nullptr, nullptr, nullptr);
    cudaEventRecord(evY2, ms);
    cudaStreamWaitEvent(s2, evY2, 0);
    gather_vec<<<(NN * 32 + 255) / 256, 256, 0, s2>>>(p_y, p_agg);
    cudaEventRecord(evG2, s2);
    tgemm3<128, 0, 1, 0><<<GB, 256, SMEM_DYN, ms>>>(p1h, p1l, 128, wth + O_C2R, wtl + O_C2R,
                                                    c2_bl, p_z, nullptr, 128, nullptr, nullptr, nullptr);
    cudaStreamWaitEvent(ms, evG2, 0);
    ep_f32<<<(NN * 32 + 255) / 256, 256, 0, ms>>>(p_z, p_agg, p_h);

    // ---- conv3 (scalar)
    conv3_dot<<<(NN * 32 + 255) / 256, 256, 0, ms>>>(c3_Wl, c3_Wr);
    gather3_final<<<(NN * 32 + 255) / 256, 256, 0, ms>>>(c3_bl, out);
}

// round 7
// speedup vs baseline: 2.1067x; 1.0327x over previous
#include <cuda_runtime.h>
#include <cuda_bf16.h>
#include <cstdint>
#include <math.h>

#define NN   100000
#define NE   1600000
#define NCAT 20
#define EMBD 32
#define CARD 100
#define NB_SCAN 98   // ceil(NN/1024)

typedef __nv_bfloat16 bf16;
typedef __nv_bfloat162 bf162;

// ---------------- scratch (device globals) ----------------
__device__ bf16 g_xhi[(size_t)NN * 192], g_xlo[(size_t)NN * 192];
__device__ bf16 g_p1hi[(size_t)NN * 128], g_p1lo[(size_t)NN * 128];
__device__ bf16 g_p2hi[(size_t)NN * 128], g_p2lo[(size_t)NN * 128];
__device__ float g_y[(size_t)NN * 128];
__device__ float g_z[(size_t)NN * 128];
__device__ float g_agg[(size_t)NN * 128];
__device__ float g_h[(size_t)NN * 128];
__device__ float g_s1[NN], g_s2[NN];
__device__ bf16 g_wthi[1536 * 128], g_wtlo[1536 * 128];   // [n][k] transposed
__device__ bf16 g_ehi[NCAT * CARD * EMBD], g_elo[NCAT * CARD * EMBD];
// CSR
__device__ int g_cnt[NN];
__device__ int g_start[NN + 1];
__device__ int g_cursor[NN];
__device__ int g_csrc[NE];
__device__ int g_bsum[NB_SCAN];

__device__ __forceinline__ float gelu_f(float v) {
    return 0.5f * v * (1.0f + erff(v * 0.70710678118654752f));
}
__device__ __forceinline__ void split_bf(float v, bf16& h, bf16& l) {
    h = __float2bfloat16(v);
    l = __float2bfloat16(v - __bfloat162float(h));
}
__device__ __forceinline__ void mma_bf16(float4& c, const uint32_t* a, const uint32_t* b) {
    asm volatile("mma.sync.aligned.m16n8k16.row.col.f32.bf16.bf16.f32 "
                 "{%0,%1,%2,%3}, {%4,%5,%6,%7}, {%8,%9}, {%0,%1,%2,%3};"
                 : "+f"(c.x), "+f"(c.y), "+f"(c.z), "+f"(c.w)
                 : "r"(a[0]), "r"(a[1]), "r"(a[2]), "r"(a[3]), "r"(b[0]), "r"(b[1]));
}
__device__ __forceinline__ void ldmx4(uint32_t& r0, uint32_t& r1, uint32_t& r2, uint32_t& r3,
                                      uint32_t addr) {
    asm volatile("ldmatrix.sync.aligned.m8n8.x4.shared.b16 {%0,%1,%2,%3}, [%4];"
                 : "=r"(r0), "=r"(r1), "=r"(r2), "=r"(r3) : "r"(addr));
}
__device__ __forceinline__ void cpasync16(uint32_t dst, const void* src) {
    asm volatile("cp.async.cg.shared.global [%0], [%1], 16;" :: "r"(dst), "l"(src));
}
__device__ __forceinline__ void cp_commit() { asm volatile("cp.async.commit_group;"); }
template<int N> __device__ __forceinline__ void cp_wait() {
    asm volatile("cp.async.wait_group %0;" :: "n"(N));
}

// ---------------- prep kernels ----------------
__global__ void prep_weight(const float* __restrict__ W, int K,
                            bf16* __restrict__ oh, bf16* __restrict__ ol) {
    int i = blockIdx.x * blockDim.x + threadIdx.x;
    if (i < 128 * K) {
        int k = i >> 7, n = i & 127;
        float v = W[i];
        bf16 h, l; split_bf(v, h, l);
        oh[(size_t)n * K + k] = h;
        ol[(size_t)n * K + k] = l;
    }
}
__global__ void prep_emb(const float* __restrict__ src, int n) {
    int i = blockIdx.x * blockDim.x + threadIdx.x;
    if (i < n) {
        bf16 h, l; split_bf(src[i], h, l);
        g_ehi[i] = h; g_elo[i] = l;
    }
}
__global__ void copy_cont_split(const float* __restrict__ xc) {
    int i = blockIdx.x * blockDim.x + threadIdx.x;
    if (i < NN * 64) {
        int n = i >> 6, j = i & 63;
        bf16 h, l; split_bf(xc[i], h, l);
        g_xhi[(size_t)n * 192 + 128 + j] = h;
        g_xlo[(size_t)n * 192 + 128 + j] = l;
    }
}

// ---------------- CSR build ----------------
__global__ void zero_cnt() {
    int i = blockIdx.x * blockDim.x + threadIdx.x;
    if (i < NN) g_cnt[i] = 0;
}
__global__ void count_k(const int* __restrict__ ei, int E) {
    int e = blockIdx.x * blockDim.x + threadIdx.x;
    if (e < E) atomicAdd(&g_cnt[ei[E + e]], 1);
}
__global__ void scan_block() {
    __shared__ int sh[1024];
    int tid = threadIdx.x;
    int i = blockIdx.x * 1024 + tid;
    int v = (i < NN) ? g_cnt[i] : 0;
    sh[tid] = v;
    __syncthreads();
#pragma unroll
    for (int off = 1; off < 1024; off <<= 1) {
        int t = (tid >= off) ? sh[tid - off] : 0;
        __syncthreads();
        sh[tid] += t;
        __syncthreads();
    }
    if (i < NN) g_start[i] = sh[tid] - v;
    if (tid == 1023) g_bsum[blockIdx.x] = sh[1023];
}
__global__ void scan_top() {
    if (threadIdx.x == 0) {
        int acc = 0;
        for (int j = 0; j < NB_SCAN; j++) { int t = g_bsum[j]; g_bsum[j] = acc; acc += t; }
        g_start[NN] = acc;
    }
}
__global__ void scan_add() {
    int i = blockIdx.x * blockDim.x + threadIdx.x;
    if (i < NN) {
        int s = g_start[i] + g_bsum[i >> 10];
        g_start[i] = s;
        g_cursor[i] = s;
    }
}
__global__ void fill_k(const int* __restrict__ ei, int E) {
    int e = blockIdx.x * blockDim.x + threadIdx.x;
    if (e < E) {
        int dst = ei[E + e];
        int pos = atomicAdd(&g_cursor[dst], 1);
        g_csrc[pos] = ei[e];
    }
}

// ---------------- gather kernels ----------------
__global__ void gather_vec(const float* __restrict__ y, float* __restrict__ agg) {
    int w = (blockIdx.x * blockDim.x + threadIdx.x) >> 5;
    if (w >= NN) return;
    int lane = threadIdx.x & 31;
    int s = g_start[w], e = g_start[w + 1];
    float inv = 1.f / fmaxf((float)(e - s), 1.f);
    float4 a0 = make_float4(0.f, 0.f, 0.f, 0.f);
    float4 a1 = make_float4(0.f, 0.f, 0.f, 0.f);
    int i = s;
    for (; i + 1 < e; i += 2) {
        int r0 = g_csrc[i], r1 = g_csrc[i + 1];
        float4 v0 = *(const float4*)&y[(size_t)r0 * 128 + lane * 4];
        float4 v1 = *(const float4*)&y[(size_t)r1 * 128 + lane * 4];
        a0.x += v0.x; a0.y += v0.y; a0.z += v0.z; a0.w += v0.w;
        a1.x += v1.x; a1.y += v1.y; a1.z += v1.z; a1.w += v1.w;
    }
    if (i < e) {
        int r0 = g_csrc[i];
        float4 v0 = *(const float4*)&y[(size_t)r0 * 128 + lane * 4];
        a0.x += v0.x; a0.y += v0.y; a0.z += v0.z; a0.w += v0.w;
    }
    float4 o = make_float4((a0.x + a1.x) * inv, (a0.y + a1.y) * inv,
                           (a0.z + a1.z) * inv, (a0.w + a1.w) * inv);
    *(float4*)&agg[(size_t)w * 128 + lane * 4] = o;
}

__global__ void gather3_final(const float* __restrict__ bl, float* __restrict__ out) {
    int w = (blockIdx.x * blockDim.x + threadIdx.x) >> 5;
    if (w >= NN) return;
    int lane = threadIdx.x & 31;
    int s = g_start[w], e = g_start[w + 1];
    float inv = 1.f / fmaxf((float)(e - s), 1.f);
    float sum = 0.f;
    for (int i = s + lane; i < e; i += 32) sum += g_s1[g_csrc[i]];
#pragma unroll
    for (int o = 16; o > 0; o >>= 1) sum += __shfl_down_sync(0xffffffffu, sum, o);
    if (lane == 0) out[w] = sum * inv + bl[0] + g_s2[w];
}

// ---------------- epilogues: v = gelu(z + agg) ----------------
__global__ void ep_split(const float* __restrict__ z, const float* __restrict__ agg,
                         bf16* __restrict__ oh, bf16* __restrict__ ol) {
    int i = blockIdx.x * blockDim.x + threadIdx.x;
    if (i >= NN * 32) return;
    float4 zv = *(const float4*)&z[(size_t)i * 4];
    float4 av = *(const float4*)&agg[(size_t)i * 4];
    float v0 = gelu_f(zv.x + av.x), v1 = gelu_f(zv.y + av.y);
    float v2 = gelu_f(zv.z + av.z), v3 = gelu_f(zv.w + av.w);
    bf16 h0, l0, h1, l1, h2, l2, h3, l3;
    split_bf(v0, h0, l0); split_bf(v1, h1, l1);
    split_bf(v2, h2, l2); split_bf(v3, h3, l3);
    bf162 ha; ha.x = h0; ha.y = h1;
    bf162 hb; hb.x = h2; hb.y = h3;
    bf162 la; la.x = l0; la.y = l1;
    bf162 lb; lb.x = l2; lb.y = l3;
    *(bf162*)&oh[(size_t)i * 4] = ha;
    *(bf162*)&oh[(size_t)i * 4 + 2] = hb;
    *(bf162*)&ol[(size_t)i * 4] = la;
    *(bf162*)&ol[(size_t)i * 4 + 2] = lb;
}
__global__ void ep_f32(const float* __restrict__ z, const float* __restrict__ agg,
                       float* __restrict__ o) {
    int i = blockIdx.x * blockDim.x + threadIdx.x;
    if (i >= NN * 32) return;
    float4 zv = *(const float4*)&z[(size_t)i * 4];
    float4 av = *(const float4*)&agg[(size_t)i * 4];
    float4 ov = make_float4(gelu_f(zv.x + av.x), gelu_f(zv.y + av.y),
                            gelu_f(zv.z + av.z), gelu_f(zv.w + av.w));
    *(float4*)&o[(size_t)i * 4] = ov;
}

// ---------------- conv3 dots ----------------
__global__ void conv3_dot(const float* __restrict__ Wl, const float* __restrict__ Wr) {
    int gidx = blockIdx.x * blockDim.x + threadIdx.x;
    int n = gidx >> 5;
    if (n >= NN) return;
    int lane = gidx & 31;
    float4 xv = *(const float4*)&g_h[(size_t)n * 128 + lane * 4];
    float4 wl = *(const float4*)&Wl[lane * 4];
    float4 wr = *(const float4*)&Wr[lane * 4];
    float s1 = xv.x * wl.x + xv.y * wl.y + xv.z * wl.z + xv.w * wl.w;
    float s2 = xv.x * wr.x + xv.y * wr.y + xv.z * wr.z + xv.w * wr.w;
#pragma unroll
    for (int o = 16; o > 0; o >>= 1) {
        s1 += __shfl_down_sync(0xffffffffu, s1, o);
        s2 += __shfl_down_sync(0xffffffffu, s2, o);
    }
    if (lane == 0) { g_s1[n] = s1; g_s2[n] = s2; }
}

// =====================================================================
// bf16-pair (3-term) tensor GEMM with ldmatrix fragment loads
// =====================================================================
#define SMEM_DYN 65536

template<int K, int INMODE, int EPI, int OUTMODE>
__global__ void __launch_bounds__(256, 2)
tgemm3(const bf16* __restrict__ Ahi, const bf16* __restrict__ Alo, int lda,
       const bf16* __restrict__ Bhi, const bf16* __restrict__ Blo,
       const float* __restrict__ bias,
       void* __restrict__ C0, void* __restrict__ C1, int ldc,
       const int* __restrict__ xcat,
       const bf16* __restrict__ Ehi, const bf16* __restrict__ Elo)
{
    extern __shared__ __align__(16) char sm[];

    const int tid  = threadIdx.x;
    const int m0   = blockIdx.x * 128;
    const int wid  = tid >> 5;
    const int lane = tid & 31;
    const int g    = lane >> 2;
    const int tig  = lane & 3;
    const int warpM = (wid >> 2) * 64;
    const int warpN = (wid & 3) * 32;

    constexpr int NC = K / 32;
    const uint32_t smB = (uint32_t)__cvta_generic_to_shared(sm);

    // ldmatrix lane constants
    const int laneT8 = lane & 7;
    const int aRow   = laneT8 + ((lane >> 3) & 1) * 8;   // m offset within 16
    const int aKh    = lane >> 4;                        // k-half for A tiles
    const int bNsel  = lane >> 4;                        // nt-within-pair for B
    const int bKh    = (lane >> 3) & 1;                  // k-half for B tiles

    float4 acc[4][4];
#pragma unroll
    for (int i = 0; i < 4; i++)
#pragma unroll
        for (int j = 0; j < 4; j++) acc[i][j] = make_float4(0.f, 0.f, 0.f, 0.f);

    auto copy_tile = [&](int buf, int k0) {
        uint32_t st = smB + (uint32_t)buf * 32768;
#pragma unroll
        for (int i = 0; i < 4; i++) {
            int flat = tid + i * 256;
            int half = flat >> 9;
            int rem  = flat & 511;
            int r = rem >> 2, seg = rem & 3;
            int row = m0 + r; if (row >= NN) row = NN - 1;
            const bf16* src;
            if (INMODE == 1) {
                int c = k0 >> 5;
                int cat = xcat[(size_t)row * NCAT + c];
                src = (half ? Elo : Ehi) + (size_t)(c * CARD + cat) * EMBD + seg * 8;
            } else {
                src = (half ? Alo : Ahi) + (size_t)row * lda + k0 + seg * 8;
            }
            uint32_t dst = st + (uint32_t)half * 8192 + (uint32_t)r * 64
                         + (uint32_t)((seg ^ ((r >> 1) & 3)) << 4);
            cpasync16(dst, src);
        }
#pragma unroll
        for (int i = 0; i < 4; i++) {
            int flat = tid + i * 256;
            int half = flat >> 9;
            int rem  = flat & 511;
            int n = rem >> 2, seg = rem & 3;
            const bf16* src = (half ? Blo : Bhi) + (size_t)n * K + k0 + seg * 8;
            uint32_t dst = st + 16384u + (uint32_t)half * 8192 + (uint32_t)n * 64
                         + (uint32_t)((seg ^ ((n >> 1) & 3)) << 4);
            cpasync16(dst, src);
        }
        cp_commit();
    };

    copy_tile(0, 0);

    for (int ks = 0; ks < NC; ks++) {
        if (ks + 1 < NC) {
            copy_tile((ks + 1) & 1, (ks + 1) * 32);
            cp_wait<1>();
        } else {
            cp_wait<0>();
        }
        __syncthreads();

        const uint32_t stage = smB + (uint32_t)(ks & 1) * 32768;
        const uint32_t Abase = stage;            // +8192 = Alo
        const uint32_t Bbase = stage + 16384u;   // +8192 = Blo

#pragma unroll
        for (int kc = 0; kc < 2; kc++) {
            // B fragments: two ldmatrix.x4 per half cover 4 n-tiles
            uint32_t bh[4][2], bl[4][2];
#pragma unroll
            for (int p = 0; p < 2; p++) {
                int n = warpN + (p * 2 + bNsel) * 8 + laneT8;
                int seg = kc * 2 + bKh;
                uint32_t addr = Bbase + (uint32_t)n * 64
                              + (uint32_t)((seg ^ ((n >> 1) & 3)) << 4);
                ldmx4(bh[p * 2][0], bh[p * 2][1], bh[p * 2 + 1][0], bh[p * 2 + 1][1], addr);
                ldmx4(bl[p * 2][0], bl[p * 2][1], bl[p * 2 + 1][0], bl[p * 2 + 1][1], addr + 8192u);
            }
#pragma unroll
            for (int mt = 0; mt < 4; mt++) {
                int r = warpM + mt * 16 + aRow;
                int seg = kc * 2 + aKh;
                uint32_t addr = Abase + (uint32_t)r * 64
                              + (uint32_t)((seg ^ ((r >> 1) & 3)) << 4);
                uint32_t ah[4], al[4];
                ldmx4(ah[0], ah[1], ah[2], ah[3], addr);
                ldmx4(al[0], al[1], al[2], al[3], addr + 8192u);
#pragma unroll
                for (int nt = 0; nt < 4; nt++) {
                    mma_bf16(acc[mt][nt], ah, bh[nt]);
                    mma_bf16(acc[mt][nt], ah, bl[nt]);
                    mma_bf16(acc[mt][nt], al, bh[nt]);
                }
            }
        }
        __syncthreads();
    }

#pragma unroll
    for (int mt = 0; mt < 4; mt++) {
        int r0 = m0 + warpM + mt * 16 + g;
#pragma unroll
        for (int rr = 0; rr < 2; rr++) {
            int r = r0 + rr * 8;
            if (r >= NN) continue;
#pragma unroll
            for (int nt = 0; nt < 4; nt++) {
                int col = warpN + nt * 8 + tig * 2;
                float v0 = (rr == 0) ? acc[mt][nt].x : acc[mt][nt].z;
                float v1 = (rr == 0) ? acc[mt][nt].y : acc[mt][nt].w;
                if (bias) { v0 += bias[col]; v1 += bias[col + 1]; }
                if (EPI == 0) { v0 = gelu_f(v0); v1 = gelu_f(v1); }
                if (OUTMODE == 0) {
                    *(float2*)((float*)C0 + (size_t)r * ldc + col) = make_float2(v0, v1);
                } else {
                    bf16 h0, l0, h1, l1;
                    split_bf(v0, h0, l0);
                    split_bf(v1, h1, l1);
                    bf162 hv; hv.x = h0; hv.y = h1;
                    bf162 lv; lv.x = l0; lv.y = l1;
                    *(bf162*)((bf16*)C0 + (size_t)r * ldc + col) = hv;
                    *(bf162*)((bf16*)C1 + (size_t)r * ldc + col) = lv;
                }
            }
        }
    }
}

// ---------------- host ----------------
extern "C" void kernel_launch(void* const* d_in, const int* in_sizes, int n_in,
                              void* d_out, int out_size) {
    (void)n_in; (void)out_size;
    const int*   x_cat  = (const int*)  d_in[0];
    const float* x_cont = (const float*)d_in[1];
    const int*   ei     = (const int*)  d_in[2];
    const float* emb    = (const float*)d_in[3];
    const float* W1     = (const float*)d_in[4];
    const float* b1     = (const float*)d_in[5];
    const float* W2     = (const float*)d_in[6];
    const float* b2     = (const float*)d_in[7];
    const float* W3     = (const float*)d_in[8];
    const float* b3     = (const float*)d_in[9];
    const float* c1_Wl  = (const float*)d_in[10];
    const float* c1_bl  = (const float*)d_in[11];
    const float* c1_Wr  = (const float*)d_in[12];
    const float* c2_Wl  = (const float*)d_in[13];
    const float* c2_bl  = (const float*)d_in[14];
    const float* c2_Wr  = (const float*)d_in[15];
    const float* c3_Wl  = (const float*)d_in[16];
    const float* c3_bl  = (const float*)d_in[17];
    const float* c3_Wr  = (const float*)d_in[18];
    float* out = (float*)d_out;

    const int E = in_sizes[2] / 2;

    bf16 *p_xhi, *p_xlo, *p1h, *p1l, *p2h, *p2l, *wth, *wtl, *peh, *pel;
    float *p_y, *p_z, *p_agg, *p_h;
    cudaGetSymbolAddress((void**)&p_xhi, g_xhi);
    cudaGetSymbolAddress((void**)&p_xlo, g_xlo);
    cudaGetSymbolAddress((void**)&p1h, g_p1hi);
    cudaGetSymbolAddress((void**)&p1l, g_p1lo);
    cudaGetSymbolAddress((void**)&p2h, g_p2hi);
    cudaGetSymbolAddress((void**)&p2l, g_p2lo);
    cudaGetSymbolAddress((void**)&p_y, g_y);
    cudaGetSymbolAddress((void**)&p_z, g_z);
    cudaGetSymbolAddress((void**)&p_agg, g_agg);
    cudaGetSymbolAddress((void**)&p_h, g_h);
    cudaGetSymbolAddress((void**)&wth, g_wthi);
    cudaGetSymbolAddress((void**)&wtl, g_wtlo);
    cudaGetSymbolAddress((void**)&peh, g_ehi);
    cudaGetSymbolAddress((void**)&pel, g_elo);

    const int O_W1  = 0;
    const int O_W2  = 81920;
    const int O_W3  = 98304;
    const int O_C1L = 114688;
    const int O_C1R = 139264;
    const int O_C2L = 163840;
    const int O_C2R = 180224;

    cudaFuncSetAttribute(tgemm3<640, 1, 0, 1>, cudaFuncAttributeMaxDynamicSharedMemorySize, SMEM_DYN);
    cudaFuncSetAttribute(tgemm3<128, 0, 0, 1>, cudaFuncAttributeMaxDynamicSharedMemorySize, SMEM_DYN);
    cudaFuncSetAttribute(tgemm3<128, 0, 1, 1>, cudaFuncAttributeMaxDynamicSharedMemorySize, SMEM_DYN);
    cudaFuncSetAttribute(tgemm3<192, 0, 1, 0>, cudaFuncAttributeMaxDynamicSharedMemorySize, SMEM_DYN);
    cudaFuncSetAttribute(tgemm3<128, 0, 1, 0>, cudaFuncAttributeMaxDynamicSharedMemorySize, SMEM_DYN);

    const int GB = (NN + 127) / 128;
    cudaStream_t ms = 0;

    cudaStream_t s2;
    cudaStreamCreateWithFlags(&s2, cudaStreamNonBlocking);
    cudaEvent_t ev0, evY1, evG1, evY2, evG2;
    cudaEventCreateWithFlags(&ev0, cudaEventDisableTiming);
    cudaEventCreateWithFlags(&evY1, cudaEventDisableTiming);
    cudaEventCreateWithFlags(&evG1, cudaEventDisableTiming);
    cudaEventCreateWithFlags(&evY2, cudaEventDisableTiming);
    cudaEventCreateWithFlags(&evG2, cudaEventDisableTiming);

    cudaEventRecord(ev0, ms);
    cudaStreamWaitEvent(s2, ev0, 0);

    prep_weight<<<(640 * 128 + 255) / 256, 256, 0, ms>>>(W1, 640, wth + O_W1, wtl + O_W1);
    prep_emb<<<(NCAT * CARD * EMBD + 255) / 256, 256, 0, ms>>>(emb, NCAT * CARD * EMBD);
    copy_cont_split<<<(NN * 64 + 255) / 256, 256, 0, ms>>>(x_cont);
    zero_cnt<<<(NN + 255) / 256, 256, 0, s2>>>();
    count_k<<<(E + 255) / 256, 256, 0, s2>>>(ei, E);
    tgemm3<640, 1, 0, 1><<<GB, 256, SMEM_DYN, ms>>>(nullptr, nullptr, 0, wth + O_W1, wtl + O_W1,
                                                    b1, p1h, p1l, 128, x_cat, peh, pel);
    scan_block<<<NB_SCAN, 1024, 0, s2>>>();
    scan_top<<<1, 32, 0, s2>>>();
    scan_add<<<(NN + 255) / 256, 256, 0, s2>>>();
    fill_k<<<(E + 255) / 256, 256, 0, s2>>>(ei, E);

    prep_weight<<<(128 * 128 + 255) / 256, 256, 0, ms>>>(W2, 128, wth + O_W2, wtl + O_W2);
    prep_weight<<<(128 * 128 + 255) / 256, 256, 0, ms>>>(W3, 128, wth + O_W3, wtl + O_W3);
    prep_weight<<<(192 * 128 + 255) / 256, 256, 0, ms>>>(c1_Wl, 192, wth + O_C1L, wtl + O_C1L);
    prep_weight<<<(192 * 128 + 255) / 256, 256, 0, ms>>>(c1_Wr, 192, wth + O_C1R, wtl + O_C1R);
    prep_weight<<<(128 * 128 + 255) / 256, 256, 0, ms>>>(c2_Wl, 128, wth + O_C2L, wtl + O_C2L);
    prep_weight<<<(128 * 128 + 255) / 256, 256, 0, ms>>>(c2_Wr, 128, wth + O_C2R, wtl + O_C2R);

    tgemm3<128, 0, 0, 1><<<GB, 256, SMEM_DYN, ms>>>(p1h, p1l, 128, wth + O_W2, wtl + O_W2,
                                                    b2, p2h, p2l, 128, nullptr, nullptr, nullptr);
    tgemm3<128, 0, 1, 1><<<GB, 256, SMEM_DYN, ms>>>(p2h, p2l, 128, wth + O_W3, wtl + O_W3,
                                                    b3, p_xhi, p_xlo, 192, nullptr, nullptr, nullptr);

    // ---- conv1
    tgemm3<192, 0, 1, 0><<<GB, 256, SMEM_DYN, ms>>>(p_xhi, p_xlo, 192, wth + O_C1L, wtl + O_C1L,
                                                    nullptr, p_y, nullptr, 128, nullptr, nullptr, nullptr);
    cudaEventRecord(evY1, ms);
    cudaStreamWaitEvent(s2, evY1, 0);
    gather_vec<<<(NN * 32 + 255) / 256, 256, 0, s2>>>(p_y, p_agg);
    cudaEventRecord(evG1, s2);
    tgemm3<192, 0, 1, 0><<<GB, 256, SMEM_DYN, ms>>>(p_xhi, p_xlo, 192, wth + O_C1R, wtl + O_C1R,
                                                    c1_bl, p_z, nullptr, 128, nullptr, nullptr, nullptr);
    cudaStreamWaitEvent(ms, evG1, 0);
    ep_split<<<(NN * 32 + 255) / 256, 256, 0, ms>>>(p_z, p_agg, p1h, p1l);

    // ---- conv2
    tgemm3<128, 0, 1, 0><<<GB, 256, SMEM_DYN, ms>>>(p1h, p1l, 128, wth + O_C2L, wtl + O_C2L,
                                                    nullptr, p_y, nullptr, 128, nullptr, nullptr, nullptr);
    cudaEventRecord(evY2, ms);
    cudaStreamWaitEvent(s2, evY2, 0);
    gather_vec<<<(NN * 32 + 255) / 256, 256, 0, s2>>>(p_y, p_agg);
    cudaEventRecord(evG2, s2);
    tgemm3<128, 0, 1, 0><<<GB, 256, SMEM_DYN, ms>>>(p1h, p1l, 128, wth + O_C2R, wtl + O_C2R,
                                                    c2_bl, p_z, nullptr, 128, nullptr, nullptr, nullptr);
    cudaStreamWaitEvent(ms, evG2, 0);
    ep_f32<<<(NN * 32 + 255) / 256, 256, 0, ms>>>(p_z, p_agg, p_h);

    // ---- conv3 (scalar)
    conv3_dot<<<(NN * 32 + 255) / 256, 256, 0, ms>>>(c3_Wl, c3_Wr);
    gather3_final<<<(NN * 32 + 255) / 256, 256, 0, ms>>>(c3_bl, out);
}

// round 8
// speedup vs baseline: 2.4289x; 1.1530x over previous
#include <cuda_runtime.h>
#include <cuda_bf16.h>
#include <cstdint>
#include <math.h>

#define NN   100000
#define NE   1600000
#define NCAT 20
#define EMBD 32
#define CARD 100
#define NB_SCAN 98   // ceil(NN/1024)

typedef __nv_bfloat16 bf16;
typedef __nv_bfloat162 bf162;

// ---------------- scratch (device globals) ----------------
__device__ bf16 g_xhi[(size_t)NN * 192], g_xlo[(size_t)NN * 192];
__device__ bf16 g_p1hi[(size_t)NN * 128], g_p1lo[(size_t)NN * 128];
__device__ bf16 g_p2hi[(size_t)NN * 128], g_p2lo[(size_t)NN * 128];
__device__ float g_y[(size_t)NN * 128];
__device__ float g_z[(size_t)NN * 128];
__device__ float g_agg[(size_t)NN * 128];
__device__ float g_s1[NN], g_s2[NN];
__device__ bf16 g_wthi[1024 * 128], g_wtlo[1024 * 128];   // [n][k] transposed (W2,W3,c1L,c1R,c2L,c2R)
__device__ float g_T[NCAT * CARD * 128];                   // fused emb@W1 tables (1MB)
// CSR
__device__ int g_cnt[NN];
__device__ int g_start[NN + 1];
__device__ int g_cursor[NN];
__device__ int g_csrc[NE];
__device__ int g_bsum[NB_SCAN];

__device__ __forceinline__ float gelu_f(float v) {
    return 0.5f * v * (1.0f + erff(v * 0.70710678118654752f));
}
__device__ __forceinline__ void split_bf(float v, bf16& h, bf16& l) {
    h = __float2bfloat16(v);
    l = __float2bfloat16(v - __bfloat162float(h));
}
__device__ __forceinline__ void mma_bf16(float4& c, const uint32_t* a, const uint32_t* b) {
    asm volatile("mma.sync.aligned.m16n8k16.row.col.f32.bf16.bf16.f32 "
                 "{%0,%1,%2,%3}, {%4,%5,%6,%7}, {%8,%9}, {%0,%1,%2,%3};"
                 : "+f"(c.x), "+f"(c.y), "+f"(c.z), "+f"(c.w)
                 : "r"(a[0]), "r"(a[1]), "r"(a[2]), "r"(a[3]), "r"(b[0]), "r"(b[1]));
}
__device__ __forceinline__ void ldmx4(uint32_t& r0, uint32_t& r1, uint32_t& r2, uint32_t& r3,
                                      uint32_t addr) {
    asm volatile("ldmatrix.sync.aligned.m8n8.x4.shared.b16 {%0,%1,%2,%3}, [%4];"
                 : "=r"(r0), "=r"(r1), "=r"(r2), "=r"(r3) : "r"(addr));
}
__device__ __forceinline__ void cpasync16(uint32_t dst, const void* src) {
    asm volatile("cp.async.cg.shared.global [%0], [%1], 16;" :: "r"(dst), "l"(src));
}
__device__ __forceinline__ void cp_commit() { asm volatile("cp.async.commit_group;"); }
template<int N> __device__ __forceinline__ void cp_wait() {
    asm volatile("cp.async.wait_group %0;" :: "n"(N));
}

// ---------------- prep kernels ----------------
__global__ void prep_weight(const float* __restrict__ W, int K,
                            bf16* __restrict__ oh, bf16* __restrict__ ol) {
    int i = blockIdx.x * blockDim.x + threadIdx.x;
    if (i < 128 * K) {
        int k = i >> 7, n = i & 127;
        float v = W[i];
        bf16 h, l; split_bf(v, h, l);
        oh[(size_t)n * K + k] = h;
        ol[(size_t)n * K + k] = l;
    }
}
__global__ void copy_cont_split(const float* __restrict__ xc) {
    int i = blockIdx.x * blockDim.x + threadIdx.x;
    if (i < NN * 64) {
        int n = i >> 6, j = i & 63;
        bf16 h, l; split_bf(xc[i], h, l);
        g_xhi[(size_t)n * 192 + 128 + j] = h;
        g_xlo[(size_t)n * 192 + 128 + j] = l;
    }
}

// ---------------- emb@W1 table precompute ----------------
// block b handles (c = b>>1, row-half = b&1): T[c][r][n] = sum_d emb[c][r][d]*W1[c*32+d][n]
__global__ void __launch_bounds__(256)
prep_T(const float* __restrict__ emb, const float* __restrict__ W1) {
    __shared__ float se[50 * 32];    // 50 emb rows x 32
    __shared__ float sw[32 * 128];   // 32 k x 128 n
    int c = blockIdx.x >> 1;
    int rh = blockIdx.x & 1;
    int tid = threadIdx.x;
    for (int i = tid; i < 50 * 32; i += 256)
        se[i] = emb[(size_t)c * CARD * EMBD + rh * 50 * 32 + i];
    for (int i = tid; i < 32 * 128; i += 256)
        sw[i] = W1[(size_t)(c * 32) * 128 + i];
    __syncthreads();
    // 50*128 = 6400 outputs / 256 threads = 25 each
    for (int i = 0; i < 25; i++) {
        int idx = tid + i * 256;
        int r = idx >> 7, n = idx & 127;
        float acc = 0.f;
#pragma unroll
        for (int d = 0; d < 32; d++)
            acc += se[r * 32 + d] * sw[d * 128 + n];
        g_T[((size_t)c * CARD + rh * 50 + r) * 128 + n] = acc;
    }
}

// ---------------- MLP layer 1 via table lookup-sum ----------------
// warp per node: h = gelu(b1 + sum_c T[c][cat_c]); split -> p1h/p1l
__global__ void __launch_bounds__(256)
emb_mlp1(const int* __restrict__ xcat, const float* __restrict__ b1,
         bf16* __restrict__ oh, bf16* __restrict__ ol) {
    int w = (blockIdx.x * blockDim.x + threadIdx.x) >> 5;
    if (w >= NN) return;
    int lane = threadIdx.x & 31;
    const int* xc = xcat + (size_t)w * NCAT;
    float4 acc = *(const float4*)&b1[lane * 4];
#pragma unroll
    for (int c = 0; c < NCAT; c++) {
        int cat = __ldg(&xc[c]);
        float4 t = *(const float4*)&g_T[((size_t)c * CARD + cat) * 128 + lane * 4];
        acc.x += t.x; acc.y += t.y; acc.z += t.z; acc.w += t.w;
    }
    float v0 = gelu_f(acc.x), v1 = gelu_f(acc.y), v2 = gelu_f(acc.z), v3 = gelu_f(acc.w);
    bf16 h0, l0, h1, l1, h2, l2, h3, l3;
    split_bf(v0, h0, l0); split_bf(v1, h1, l1);
    split_bf(v2, h2, l2); split_bf(v3, h3, l3);
    bf162 ha; ha.x = h0; ha.y = h1;
    bf162 hb; hb.x = h2; hb.y = h3;
    bf162 la; la.x = l0; la.y = l1;
    bf162 lb; lb.x = l2; lb.y = l3;
    size_t o = (size_t)w * 128 + lane * 4;
    *(bf162*)&oh[o] = ha; *(bf162*)&oh[o + 2] = hb;
    *(bf162*)&ol[o] = la; *(bf162*)&ol[o + 2] = lb;
}

// ---------------- CSR build ----------------
__global__ void zero_cnt() {
    int i = blockIdx.x * blockDim.x + threadIdx.x;
    if (i < NN) g_cnt[i] = 0;
}
__global__ void count_k(const int* __restrict__ ei, int E) {
    int e = blockIdx.x * blockDim.x + threadIdx.x;
    if (e < E) atomicAdd(&g_cnt[ei[E + e]], 1);
}
__global__ void scan_block() {
    __shared__ int sh[1024];
    int tid = threadIdx.x;
    int i = blockIdx.x * 1024 + tid;
    int v = (i < NN) ? g_cnt[i] : 0;
    sh[tid] = v;
    __syncthreads();
#pragma unroll
    for (int off = 1; off < 1024; off <<= 1) {
        int t = (tid >= off) ? sh[tid - off] : 0;
        __syncthreads();
        sh[tid] += t;
        __syncthreads();
    }
    if (i < NN) g_start[i] = sh[tid] - v;
    if (tid == 1023) g_bsum[blockIdx.x] = sh[1023];
}
__global__ void scan_top() {
    if (threadIdx.x == 0) {
        int acc = 0;
        for (int j = 0; j < NB_SCAN; j++) { int t = g_bsum[j]; g_bsum[j] = acc; acc += t; }
        g_start[NN] = acc;
    }
}
__global__ void scan_add() {
    int i = blockIdx.x * blockDim.x + threadIdx.x;
    if (i < NN) {
        int s = g_start[i] + g_bsum[i >> 10];
        g_start[i] = s;
        g_cursor[i] = s;
    }
}
__global__ void fill_k(const int* __restrict__ ei, int E) {
    int e = blockIdx.x * blockDim.x + threadIdx.x;
    if (e < E) {
        int dst = ei[E + e];
        int pos = atomicAdd(&g_cursor[dst], 1);
        g_csrc[pos] = ei[e];
    }
}

// ---------------- gather kernels ----------------
__global__ void gather_vec(const float* __restrict__ y, float* __restrict__ agg) {
    int w = (blockIdx.x * blockDim.x + threadIdx.x) >> 5;
    if (w >= NN) return;
    int lane = threadIdx.x & 31;
    int s = g_start[w], e = g_start[w + 1];
    float inv = 1.f / fmaxf((float)(e - s), 1.f);
    float4 a0 = make_float4(0.f, 0.f, 0.f, 0.f);
    float4 a1 = make_float4(0.f, 0.f, 0.f, 0.f);
    int i = s;
    for (; i + 1 < e; i += 2) {
        int r0 = g_csrc[i], r1 = g_csrc[i + 1];
        float4 v0 = *(const float4*)&y[(size_t)r0 * 128 + lane * 4];
        float4 v1 = *(const float4*)&y[(size_t)r1 * 128 + lane * 4];
        a0.x += v0.x; a0.y += v0.y; a0.z += v0.z; a0.w += v0.w;
        a1.x += v1.x; a1.y += v1.y; a1.z += v1.z; a1.w += v1.w;
    }
    if (i < e) {
        int r0 = g_csrc[i];
        float4 v0 = *(const float4*)&y[(size_t)r0 * 128 + lane * 4];
        a0.x += v0.x; a0.y += v0.y; a0.z += v0.z; a0.w += v0.w;
    }
    float4 o = make_float4((a0.x + a1.x) * inv, (a0.y + a1.y) * inv,
                           (a0.z + a1.z) * inv, (a0.w + a1.w) * inv);
    *(float4*)&agg[(size_t)w * 128 + lane * 4] = o;
}

__global__ void gather3_final(const float* __restrict__ bl, float* __restrict__ out) {
    int w = (blockIdx.x * blockDim.x + threadIdx.x) >> 5;
    if (w >= NN) return;
    int lane = threadIdx.x & 31;
    int s = g_start[w], e = g_start[w + 1];
    float inv = 1.f / fmaxf((float)(e - s), 1.f);
    float sum = 0.f;
    for (int i = s + lane; i < e; i += 32) sum += g_s1[g_csrc[i]];
#pragma unroll
    for (int o = 16; o > 0; o >>= 1) sum += __shfl_down_sync(0xffffffffu, sum, o);
    if (lane == 0) out[w] = sum * inv + bl[0] + g_s2[w];
}

// ---------------- epilogue conv1: v = gelu(z + agg) -> split ----------------
__global__ void ep_split(const float* __restrict__ z, const float* __restrict__ agg,
                         bf16* __restrict__ oh, bf16* __restrict__ ol) {
    int i = blockIdx.x * blockDim.x + threadIdx.x;
    if (i >= NN * 32) return;
    float4 zv = *(const float4*)&z[(size_t)i * 4];
    float4 av = *(const float4*)&agg[(size_t)i * 4];
    float v0 = gelu_f(zv.x + av.x), v1 = gelu_f(zv.y + av.y);
    float v2 = gelu_f(zv.z + av.z), v3 = gelu_f(zv.w + av.w);
    bf16 h0, l0, h1, l1, h2, l2, h3, l3;
    split_bf(v0, h0, l0); split_bf(v1, h1, l1);
    split_bf(v2, h2, l2); split_bf(v3, h3, l3);
    bf162 ha; ha.x = h0; ha.y = h1;
    bf162 hb; hb.x = h2; hb.y = h3;
    bf162 la; la.x = l0; la.y = l1;
    bf162 lb; lb.x = l2; lb.y = l3;
    *(bf162*)&oh[(size_t)i * 4] = ha;
    *(bf162*)&oh[(size_t)i * 4 + 2] = hb;
    *(bf162*)&ol[(size_t)i * 4] = la;
    *(bf162*)&ol[(size_t)i * 4 + 2] = lb;
}

// ---------------- epilogue conv2 fused with conv3 dots ----------------
// warp per node: h = gelu(z + agg); s1 = h . Wl; s2 = h . Wr
__global__ void ep2_conv3(const float* __restrict__ z, const float* __restrict__ agg,
                          const float* __restrict__ Wl, const float* __restrict__ Wr) {
    int w = (blockIdx.x * blockDim.x + threadIdx.x) >> 5;
    if (w >= NN) return;
    int lane = threadIdx.x & 31;
    size_t o = (size_t)w * 128 + lane * 4;
    float4 zv = *(const float4*)&z[o];
    float4 av = *(const float4*)&agg[o];
    float h0 = gelu_f(zv.x + av.x), h1 = gelu_f(zv.y + av.y);
    float h2 = gelu_f(zv.z + av.z), h3 = gelu_f(zv.w + av.w);
    float4 wl = *(const float4*)&Wl[lane * 4];
    float4 wr = *(const float4*)&Wr[lane * 4];
    float s1 = h0 * wl.x + h1 * wl.y + h2 * wl.z + h3 * wl.w;
    float s2 = h0 * wr.x + h1 * wr.y + h2 * wr.z + h3 * wr.w;
#pragma unroll
    for (int off = 16; off > 0; off >>= 1) {
        s1 += __shfl_down_sync(0xffffffffu, s1, off);
        s2 += __shfl_down_sync(0xffffffffu, s2, off);
    }
    if (lane == 0) { g_s1[w] = s1; g_s2[w] = s2; }
}

// =====================================================================
// bf16-pair (3-term) tensor GEMM with ldmatrix fragment loads
// EPI: 0 = gelu(v+bias); 1 = v+bias (bias may be null)
// OUTMODE: 0 = fp32 -> C0; 1 = bf16 hi->C0, lo->C1
// =====================================================================
#define SMEM_DYN 65536

template<int K, int EPI, int OUTMODE>
__global__ void __launch_bounds__(256, 2)
tgemm3(const bf16* __restrict__ Ahi, const bf16* __restrict__ Alo, int lda,
       const bf16* __restrict__ Bhi, const bf16* __restrict__ Blo,
       const float* __restrict__ bias,
       void* __restrict__ C0, void* __restrict__ C1, int ldc)
{
    extern __shared__ __align__(16) char sm[];

    const int tid  = threadIdx.x;
    const int m0   = blockIdx.x * 128;
    const int wid  = tid >> 5;
    const int lane = tid & 31;
    const int g    = lane >> 2;
    const int tig  = lane & 3;
    const int warpM = (wid >> 2) * 64;
    const int warpN = (wid & 3) * 32;

    constexpr int NC = K / 32;
    const uint32_t smB = (uint32_t)__cvta_generic_to_shared(sm);

    const int laneT8 = lane & 7;
    const int aRow   = laneT8 + ((lane >> 3) & 1) * 8;
    const int aKh    = lane >> 4;
    const int bNsel  = lane >> 4;
    const int bKh    = (lane >> 3) & 1;

    float4 acc[4][4];
#pragma unroll
    for (int i = 0; i < 4; i++)
#pragma unroll
        for (int j = 0; j < 4; j++) acc[i][j] = make_float4(0.f, 0.f, 0.f, 0.f);

    auto copy_tile = [&](int buf, int k0) {
        uint32_t st = smB + (uint32_t)buf * 32768;
#pragma unroll
        for (int i = 0; i < 4; i++) {
            int flat = tid + i * 256;
            int half = flat >> 9;
            int rem  = flat & 511;
            int r = rem >> 2, seg = rem & 3;
            int row = m0 + r; if (row >= NN) row = NN - 1;
            const bf16* src = (half ? Alo : Ahi) + (size_t)row * lda + k0 + seg * 8;
            uint32_t dst = st + (uint32_t)half * 8192 + (uint32_t)r * 64
                         + (uint32_t)((seg ^ ((r >> 1) & 3)) << 4);
            cpasync16(dst, src);
        }
#pragma unroll
        for (int i = 0; i < 4; i++) {
            int flat = tid + i * 256;
            int half = flat >> 9;
            int rem  = flat & 511;
            int n = rem >> 2, seg = rem & 3;
            const bf16* src = (half ? Blo : Bhi) + (size_t)n * K + k0 + seg * 8;
            uint32_t dst = st + 16384u + (uint32_t)half * 8192 + (uint32_t)n * 64
                         + (uint32_t)((seg ^ ((n >> 1) & 3)) << 4);
            cpasync16(dst, src);
        }
        cp_commit();
    };

    copy_tile(0, 0);

    for (int ks = 0; ks < NC; ks++) {
        if (ks + 1 < NC) {
            copy_tile((ks + 1) & 1, (ks + 1) * 32);
            cp_wait<1>();
        } else {
            cp_wait<0>();
        }
        __syncthreads();

        const uint32_t stage = smB + (uint32_t)(ks & 1) * 32768;
        const uint32_t Abase = stage;
        const uint32_t Bbase = stage + 16384u;

#pragma unroll
        for (int kc = 0; kc < 2; kc++) {
            uint32_t bh[4][2], bl[4][2];
#pragma unroll
            for (int p = 0; p < 2; p++) {
                int n = warpN + (p * 2 + bNsel) * 8 + laneT8;
                int seg = kc * 2 + bKh;
                uint32_t addr = Bbase + (uint32_t)n * 64
                              + (uint32_t)((seg ^ ((n >> 1) & 3)) << 4);
                ldmx4(bh[p * 2][0], bh[p * 2][1], bh[p * 2 + 1][0], bh[p * 2 + 1][1], addr);
                ldmx4(bl[p * 2][0], bl[p * 2][1], bl[p * 2 + 1][0], bl[p * 2 + 1][1], addr + 8192u);
            }
#pragma unroll
            for (int mt = 0; mt < 4; mt++) {
                int r = warpM + mt * 16 + aRow;
                int seg = kc * 2 + aKh;
                uint32_t addr = Abase + (uint32_t)r * 64
                              + (uint32_t)((seg ^ ((r >> 1) & 3)) << 4);
                uint32_t ah[4], al[4];
                ldmx4(ah[0], ah[1], ah[2], ah[3], addr);
                ldmx4(al[0], al[1], al[2], al[3], addr + 8192u);
#pragma unroll
                for (int nt = 0; nt < 4; nt++) {
                    mma_bf16(acc[mt][nt], ah, bh[nt]);
                    mma_bf16(acc[mt][nt], ah, bl[nt]);
                    mma_bf16(acc[mt][nt], al, bh[nt]);
                }
            }
        }
        __syncthreads();
    }

#pragma unroll
    for (int mt = 0; mt < 4; mt++) {
        int r0 = m0 + warpM + mt * 16 + g;
#pragma unroll
        for (int rr = 0; rr < 2; rr++) {
            int r = r0 + rr * 8;
            if (r >= NN) continue;
#pragma unroll
            for (int nt = 0; nt < 4; nt++) {
                int col = warpN + nt * 8 + tig * 2;
                float v0 = (rr == 0) ? acc[mt][nt].x : acc[mt][nt].z;
                float v1 = (rr == 0) ? acc[mt][nt].y : acc[mt][nt].w;
                if (bias) { v0 += bias[col]; v1 += bias[col + 1]; }
                if (EPI == 0) { v0 = gelu_f(v0); v1 = gelu_f(v1); }
                if (OUTMODE == 0) {
                    *(float2*)((float*)C0 + (size_t)r * ldc + col) = make_float2(v0, v1);
                } else {
                    bf16 h0, l0, h1, l1;
                    split_bf(v0, h0, l0);
                    split_bf(v1, h1, l1);
                    bf162 hv; hv.x = h0; hv.y = h1;
                    bf162 lv; lv.x = l0; lv.y = l1;
                    *(bf162*)((bf16*)C0 + (size_t)r * ldc + col) = hv;
                    *(bf162*)((bf16*)C1 + (size_t)r * ldc + col) = lv;
                }
            }
        }
    }
}

// ---------------- host ----------------
extern "C" void kernel_launch(void* const* d_in, const int* in_sizes, int n_in,
                              void* d_out, int out_size) {
    (void)n_in; (void)out_size;
    const int*   x_cat  = (const int*)  d_in[0];
    const float* x_cont = (const float*)d_in[1];
    const int*   ei     = (const int*)  d_in[2];
    const float* emb    = (const float*)d_in[3];
    const float* W1     = (const float*)d_in[4];
    const float* b1     = (const float*)d_in[5];
    const float* W2     = (const float*)d_in[6];
    const float* b2     = (const float*)d_in[7];
    const float* W3     = (const float*)d_in[8];
    const float* b3     = (const float*)d_in[9];
    const float* c1_Wl  = (const float*)d_in[10];
    const float* c1_bl  = (const float*)d_in[11];
    const float* c1_Wr  = (const float*)d_in[12];
    const float* c2_Wl  = (const float*)d_in[13];
    const float* c2_bl  = (const float*)d_in[14];
    const float* c2_Wr  = (const float*)d_in[15];
    const float* c3_Wl  = (const float*)d_in[16];
    const float* c3_bl  = (const float*)d_in[17];
    const float* c3_Wr  = (const float*)d_in[18];
    float* out = (float*)d_out;

    const int E = in_sizes[2] / 2;

    bf16 *p_xhi, *p_xlo, *p1h, *p1l, *p2h, *p2l, *wth, *wtl;
    float *p_y, *p_z, *p_agg;
    cudaGetSymbolAddress((void**)&p_xhi, g_xhi);
    cudaGetSymbolAddress((void**)&p_xlo, g_xlo);
    cudaGetSymbolAddress((void**)&p1h, g_p1hi);
    cudaGetSymbolAddress((void**)&p1l, g_p1lo);
    cudaGetSymbolAddress((void**)&p2h, g_p2hi);
    cudaGetSymbolAddress((void**)&p2l, g_p2lo);
    cudaGetSymbolAddress((void**)&p_y, g_y);
    cudaGetSymbolAddress((void**)&p_z, g_z);
    cudaGetSymbolAddress((void**)&p_agg, g_agg);
    cudaGetSymbolAddress((void**)&wth, g_wthi);
    cudaGetSymbolAddress((void**)&wtl, g_wtlo);

    // transposed weight offsets (elements)
    const int O_W2  = 0;        // 128x128
    const int O_W3  = 16384;
    const int O_C1L = 32768;    // 128x192
    const int O_C1R = 57344;
    const int O_C2L = 81920;
    const int O_C2R = 98304;

    cudaFuncSetAttribute(tgemm3<128, 0, 1>, cudaFuncAttributeMaxDynamicSharedMemorySize, SMEM_DYN);
    cudaFuncSetAttribute(tgemm3<128, 1, 1>, cudaFuncAttributeMaxDynamicSharedMemorySize, SMEM_DYN);
    cudaFuncSetAttribute(tgemm3<192, 1, 0>, cudaFuncAttributeMaxDynamicSharedMemorySize, SMEM_DYN);
    cudaFuncSetAttribute(tgemm3<128, 1, 0>, cudaFuncAttributeMaxDynamicSharedMemorySize, SMEM_DYN);

    const int GB = (NN + 127) / 128;
    cudaStream_t ms = 0;

    cudaStream_t s2;
    cudaStreamCreateWithFlags(&s2, cudaStreamNonBlocking);
    cudaEvent_t ev0, evY1, evG1, evY2, evG2;
    cudaEventCreateWithFlags(&ev0, cudaEventDisableTiming);
    cudaEventCreateWithFlags(&evY1, cudaEventDisableTiming);
    cudaEventCreateWithFlags(&evG1, cudaEventDisableTiming);
    cudaEventCreateWithFlags(&evY2, cudaEventDisableTiming);
    cudaEventCreateWithFlags(&evG2, cudaEventDisableTiming);

    cudaEventRecord(ev0, ms);
    cudaStreamWaitEvent(s2, ev0, 0);

    // CSR build rides s2 under the MLP chain
    zero_cnt<<<(NN + 255) / 256, 256, 0, s2>>>();
    count_k<<<(E + 255) / 256, 256, 0, s2>>>(ei, E);
    scan_block<<<NB_SCAN, 1024, 0, s2>>>();
    scan_top<<<1, 32, 0, s2>>>();
    scan_add<<<(NN + 255) / 256, 256, 0, s2>>>();
    fill_k<<<(E + 255) / 256, 256, 0, s2>>>(ei, E);

    // MLP layer 1 via fused tables
    prep_T<<<NCAT * 2, 256, 0, ms>>>(emb, W1);
    copy_cont_split<<<(NN * 64 + 255) / 256, 256, 0, ms>>>(x_cont);
    emb_mlp1<<<(NN * 32 + 255) / 256, 256, 0, ms>>>(x_cat, b1, p1h, p1l);

    // weight prep
    prep_weight<<<(128 * 128 + 255) / 256, 256, 0, ms>>>(W2, 128, wth + O_W2, wtl + O_W2);
    prep_weight<<<(128 * 128 + 255) / 256, 256, 0, ms>>>(W3, 128, wth + O_W3, wtl + O_W3);
    prep_weight<<<(192 * 128 + 255) / 256, 256, 0, ms>>>(c1_Wl, 192, wth + O_C1L, wtl + O_C1L);
    prep_weight<<<(192 * 128 + 255) / 256, 256, 0, ms>>>(c1_Wr, 192, wth + O_C1R, wtl + O_C1R);
    prep_weight<<<(128 * 128 + 255) / 256, 256, 0, ms>>>(c2_Wl, 128, wth + O_C2L, wtl + O_C2L);
    prep_weight<<<(128 * 128 + 255) / 256, 256, 0, ms>>>(c2_Wr, 128, wth + O_C2R, wtl + O_C2R);

    // MLP layers 2-3
    tgemm3<128, 0, 1><<<GB, 256, SMEM_DYN, ms>>>(p1h, p1l, 128, wth + O_W2, wtl + O_W2,
                                                 b2, p2h, p2l, 128);
    tgemm3<128, 1, 1><<<GB, 256, SMEM_DYN, ms>>>(p2h, p2l, 128, wth + O_W3, wtl + O_W3,
                                                 b3, p_xhi, p_xlo, 192);

    // ---- conv1
    tgemm3<192, 1, 0><<<GB, 256, SMEM_DYN, ms>>>(p_xhi, p_xlo, 192, wth + O_C1L, wtl + O_C1L,
                                                 nullptr, p_y, nullptr, 128);
    cudaEventRecord(evY1, ms);
    cudaStreamWaitEvent(s2, evY1, 0);
    gather_vec<<<(NN * 32 + 255) / 256, 256, 0, s2>>>(p_y, p_agg);
    cudaEventRecord(evG1, s2);
    tgemm3<192, 1, 0><<<GB, 256, SMEM_DYN, ms>>>(p_xhi, p_xlo, 192, wth + O_C1R, wtl + O_C1R,
                                                 c1_bl, p_z, nullptr, 128);
    cudaStreamWaitEvent(ms, evG1, 0);
    ep_split<<<(NN * 32 + 255) / 256, 256, 0, ms>>>(p_z, p_agg, p1h, p1l);

    // ---- conv2
    tgemm3<128, 1, 0><<<GB, 256, SMEM_DYN, ms>>>(p1h, p1l, 128, wth + O_C2L, wtl + O_C2L,
                                                 nullptr, p_y, nullptr, 128);
    cudaEventRecord(evY2, ms);
    cudaStreamWaitEvent(s2, evY2, 0);
    gather_vec<<<(NN * 32 + 255) / 256, 256, 0, s2>>>(p_y, p_agg);
    cudaEventRecord(evG2, s2);
    tgemm3<128, 1, 0><<<GB, 256, SMEM_DYN, ms>>>(p1h, p1l, 128, wth + O_C2R, wtl + O_C2R,
                                                 c2_bl, p_z, nullptr, 128);
    cudaStreamWaitEvent(ms, evG2, 0);

    // ---- conv2 epilogue fused with conv3 dots, then final gather
    ep2_conv3<<<(NN * 32 + 255) / 256, 256, 0, ms>>>(p_z, p_agg, c3_Wl, c3_Wr);
    gather3_final<<<(NN * 32 + 255) / 256, 256, 0, ms>>>(c3_bl, out);
}

// round 9
// speedup vs baseline: 2.5139x; 1.0350x over previous
#include <cuda_runtime.h>
#include <cuda_bf16.h>
#include <cuda_fp16.h>
#include <cstdint>
#include <math.h>

#define NN   100000
#define NE   1600000
#define NCAT 20
#define EMBD 32
#define CARD 100
#define NB_SCAN 98   // ceil(NN/1024)

typedef __nv_bfloat16 bf16;
typedef __nv_bfloat162 bf162;

// ---------------- scratch (device globals) ----------------
__device__ bf16 g_xhi[(size_t)NN * 192], g_xlo[(size_t)NN * 192];
__device__ bf16 g_p1hi[(size_t)NN * 128], g_p1lo[(size_t)NN * 128];
__device__ bf16 g_p2hi[(size_t)NN * 128], g_p2lo[(size_t)NN * 128];
__device__ __half g_y[(size_t)NN * 128];          // fp16 pre-aggregation features
__device__ float g_z[(size_t)NN * 128];
__device__ float g_agg[(size_t)NN * 128];
__device__ float g_s1[NN], g_s2[NN];
__device__ bf16 g_wthi[1024 * 128], g_wtlo[1024 * 128];   // [n][k] transposed
__device__ __half g_Th[NCAT * CARD * 128];                 // fused emb@W1 tables (fp16, 512KB)
// CSR
__device__ int g_cnt[NN];
__device__ int g_start[NN + 1];
__device__ int g_cursor[NN];
__device__ int g_csrc[NE];
__device__ int g_bsum[NB_SCAN];

__device__ __forceinline__ float gelu_f(float v) {
    return 0.5f * v * (1.0f + erff(v * 0.70710678118654752f));
}
__device__ __forceinline__ void split_bf(float v, bf16& h, bf16& l) {
    h = __float2bfloat16(v);
    l = __float2bfloat16(v - __bfloat162float(h));
}
__device__ __forceinline__ void mma_bf16(float4& c, const uint32_t* a, const uint32_t* b) {
    asm volatile("mma.sync.aligned.m16n8k16.row.col.f32.bf16.bf16.f32 "
                 "{%0,%1,%2,%3}, {%4,%5,%6,%7}, {%8,%9}, {%0,%1,%2,%3};"
                 : "+f"(c.x), "+f"(c.y), "+f"(c.z), "+f"(c.w)
                 : "r"(a[0]), "r"(a[1]), "r"(a[2]), "r"(a[3]), "r"(b[0]), "r"(b[1]));
}
__device__ __forceinline__ void ldmx4(uint32_t& r0, uint32_t& r1, uint32_t& r2, uint32_t& r3,
                                      uint32_t addr) {
    asm volatile("ldmatrix.sync.aligned.m8n8.x4.shared.b16 {%0,%1,%2,%3}, [%4];"
                 : "=r"(r0), "=r"(r1), "=r"(r2), "=r"(r3) : "r"(addr));
}
__device__ __forceinline__ void cpasync16(uint32_t dst, const void* src) {
    asm volatile("cp.async.cg.shared.global [%0], [%1], 16;" :: "r"(dst), "l"(src));
}
__device__ __forceinline__ void cp_commit() { asm volatile("cp.async.commit_group;"); }
template<int N> __device__ __forceinline__ void cp_wait() {
    asm volatile("cp.async.wait_group %0;" :: "n"(N));
}

// ---------------- prep kernels ----------------
__global__ void prep_weight(const float* __restrict__ W, int K,
                            bf16* __restrict__ oh, bf16* __restrict__ ol) {
    int i = blockIdx.x * blockDim.x + threadIdx.x;
    if (i < 128 * K) {
        int k = i >> 7, n = i & 127;
        float v = W[i];
        bf16 h, l; split_bf(v, h, l);
        oh[(size_t)n * K + k] = h;
        ol[(size_t)n * K + k] = l;
    }
}
__global__ void copy_cont_split(const float* __restrict__ xc) {
    int i = blockIdx.x * blockDim.x + threadIdx.x;
    if (i < NN * 64) {
        int n = i >> 6, j = i & 63;
        bf16 h, l; split_bf(xc[i], h, l);
        g_xhi[(size_t)n * 192 + 128 + j] = h;
        g_xlo[(size_t)n * 192 + 128 + j] = l;
    }
}

// ---------------- emb@W1 table precompute (fp16 output) ----------------
__global__ void __launch_bounds__(256)
prep_T(const float* __restrict__ emb, const float* __restrict__ W1) {
    __shared__ float se[50 * 32];
    __shared__ float sw[32 * 128];
    int c = blockIdx.x >> 1;
    int rh = blockIdx.x & 1;
    int tid = threadIdx.x;
    for (int i = tid; i < 50 * 32; i += 256)
        se[i] = emb[(size_t)c * CARD * EMBD + rh * 50 * 32 + i];
    for (int i = tid; i < 32 * 128; i += 256)
        sw[i] = W1[(size_t)(c * 32) * 128 + i];
    __syncthreads();
    for (int i = 0; i < 25; i++) {
        int idx = tid + i * 256;
        int r = idx >> 7, n = idx & 127;
        float acc = 0.f;
#pragma unroll
        for (int d = 0; d < 32; d++)
            acc += se[r * 32 + d] * sw[d * 128 + n];
        g_Th[((size_t)c * CARD + rh * 50 + r) * 128 + n] = __float2half(acc);
    }
}

// ---------------- MLP layer 1 via fp16 table lookup-sum ----------------
__global__ void __launch_bounds__(256)
emb_mlp1(const int* __restrict__ xcat, const float* __restrict__ b1,
         bf16* __restrict__ oh, bf16* __restrict__ ol) {
    int w = (blockIdx.x * blockDim.x + threadIdx.x) >> 5;
    if (w >= NN) return;
    int lane = threadIdx.x & 31;
    const int* xc = xcat + (size_t)w * NCAT;
    float4 acc = *(const float4*)&b1[lane * 4];
#pragma unroll
    for (int c = 0; c < NCAT; c++) {
        int cat = __ldg(&xc[c]);
        uint2 u = *(const uint2*)&g_Th[((size_t)c * CARD + cat) * 128 + lane * 4];
        float2 f0 = __half22float2(*(__half2*)&u.x);
        float2 f1 = __half22float2(*(__half2*)&u.y);
        acc.x += f0.x; acc.y += f0.y; acc.z += f1.x; acc.w += f1.y;
    }
    float v0 = gelu_f(acc.x), v1 = gelu_f(acc.y), v2 = gelu_f(acc.z), v3 = gelu_f(acc.w);
    bf16 h0, l0, h1, l1, h2, l2, h3, l3;
    split_bf(v0, h0, l0); split_bf(v1, h1, l1);
    split_bf(v2, h2, l2); split_bf(v3, h3, l3);
    bf162 ha; ha.x = h0; ha.y = h1;
    bf162 hb; hb.x = h2; hb.y = h3;
    bf162 la; la.x = l0; la.y = l1;
    bf162 lb; lb.x = l2; lb.y = l3;
    size_t o = (size_t)w * 128 + lane * 4;
    *(bf162*)&oh[o] = ha; *(bf162*)&oh[o + 2] = hb;
    *(bf162*)&ol[o] = la; *(bf162*)&ol[o + 2] = lb;
}

// ---------------- CSR build ----------------
__global__ void zero_cnt() {
    int i = blockIdx.x * blockDim.x + threadIdx.x;
    if (i < NN) g_cnt[i] = 0;
}
__global__ void count_k(const int* __restrict__ ei, int E) {
    int e = blockIdx.x * blockDim.x + threadIdx.x;
    if (e < E) atomicAdd(&g_cnt[ei[E + e]], 1);
}
__global__ void scan_block() {
    __shared__ int sh[1024];
    int tid = threadIdx.x;
    int i = blockIdx.x * 1024 + tid;
    int v = (i < NN) ? g_cnt[i] : 0;
    sh[tid] = v;
    __syncthreads();
#pragma unroll
    for (int off = 1; off < 1024; off <<= 1) {
        int t = (tid >= off) ? sh[tid - off] : 0;
        __syncthreads();
        sh[tid] += t;
        __syncthreads();
    }
    if (i < NN) g_start[i] = sh[tid] - v;
    if (tid == 1023) g_bsum[blockIdx.x] = sh[1023];
}
__global__ void scan_top() {
    if (threadIdx.x == 0) {
        int acc = 0;
        for (int j = 0; j < NB_SCAN; j++) { int t = g_bsum[j]; g_bsum[j] = acc; acc += t; }
        g_start[NN] = acc;
    }
}
__global__ void scan_add() {
    int i = blockIdx.x * blockDim.x + threadIdx.x;
    if (i < NN) {
        int s = g_start[i] + g_bsum[i >> 10];
        g_start[i] = s;
        g_cursor[i] = s;
    }
}
__global__ void fill_k(const int* __restrict__ ei, int E) {
    int e = blockIdx.x * blockDim.x + threadIdx.x;
    if (e < E) {
        int dst = ei[E + e];
        int pos = atomicAdd(&g_cursor[dst], 1);
        g_csrc[pos] = ei[e];
    }
}

// ---------------- gather kernels ----------------
// warp per node: agg[n] = mean of y[src] (fp16 rows, 256B) over in-edges
__global__ void gather_vec(const __half* __restrict__ y, float* __restrict__ agg) {
    int w = (blockIdx.x * blockDim.x + threadIdx.x) >> 5;
    if (w >= NN) return;
    int lane = threadIdx.x & 31;
    int s = g_start[w], e = g_start[w + 1];
    float inv = 1.f / fmaxf((float)(e - s), 1.f);
    float a0 = 0.f, a1 = 0.f, a2 = 0.f, a3 = 0.f;
    float b0 = 0.f, b1 = 0.f, b2 = 0.f, b3 = 0.f;
    int i = s;
    for (; i + 1 < e; i += 2) {
        int r0 = g_csrc[i], r1 = g_csrc[i + 1];
        uint2 u0 = *(const uint2*)&y[(size_t)r0 * 128 + lane * 4];
        uint2 u1 = *(const uint2*)&y[(size_t)r1 * 128 + lane * 4];
        float2 p0 = __half22float2(*(__half2*)&u0.x);
        float2 p1 = __half22float2(*(__half2*)&u0.y);
        float2 q0 = __half22float2(*(__half2*)&u1.x);
        float2 q1 = __half22float2(*(__half2*)&u1.y);
        a0 += p0.x; a1 += p0.y; a2 += p1.x; a3 += p1.y;
        b0 += q0.x; b1 += q0.y; b2 += q1.x; b3 += q1.y;
    }
    if (i < e) {
        int r0 = g_csrc[i];
        uint2 u0 = *(const uint2*)&y[(size_t)r0 * 128 + lane * 4];
        float2 p0 = __half22float2(*(__half2*)&u0.x);
        float2 p1 = __half22float2(*(__half2*)&u0.y);
        a0 += p0.x; a1 += p0.y; a2 += p1.x; a3 += p1.y;
    }
    float4 o = make_float4((a0 + b0) * inv, (a1 + b1) * inv,
                           (a2 + b2) * inv, (a3 + b3) * inv);
    *(float4*)&agg[(size_t)w * 128 + lane * 4] = o;
}

__global__ void gather3_final(const float* __restrict__ bl, float* __restrict__ out) {
    int w = (blockIdx.x * blockDim.x + threadIdx.x) >> 5;
    if (w >= NN) return;
    int lane = threadIdx.x & 31;
    int s = g_start[w], e = g_start[w + 1];
    float inv = 1.f / fmaxf((float)(e - s), 1.f);
    float sum = 0.f;
    for (int i = s + lane; i < e; i += 32) sum += g_s1[g_csrc[i]];
#pragma unroll
    for (int o = 16; o > 0; o >>= 1) sum += __shfl_down_sync(0xffffffffu, sum, o);
    if (lane == 0) out[w] = sum * inv + bl[0] + g_s2[w];
}

// ---------------- epilogue conv1: v = gelu(z + agg) -> split ----------------
__global__ void ep_split(const float* __restrict__ z, const float* __restrict__ agg,
                         bf16* __restrict__ oh, bf16* __restrict__ ol) {
    int i = blockIdx.x * blockDim.x + threadIdx.x;
    if (i >= NN * 32) return;
    float4 zv = *(const float4*)&z[(size_t)i * 4];
    float4 av = *(const float4*)&agg[(size_t)i * 4];
    float v0 = gelu_f(zv.x + av.x), v1 = gelu_f(zv.y + av.y);
    float v2 = gelu_f(zv.z + av.z), v3 = gelu_f(zv.w + av.w);
    bf16 h0, l0, h1, l1, h2, l2, h3, l3;
    split_bf(v0, h0, l0); split_bf(v1, h1, l1);
    split_bf(v2, h2, l2); split_bf(v3, h3, l3);
    bf162 ha; ha.x = h0; ha.y = h1;
    bf162 hb; hb.x = h2; hb.y = h3;
    bf162 la; la.x = l0; la.y = l1;
    bf162 lb; lb.x = l2; lb.y = l3;
    *(bf162*)&oh[(size_t)i * 4] = ha;
    *(bf162*)&oh[(size_t)i * 4 + 2] = hb;
    *(bf162*)&ol[(size_t)i * 4] = la;
    *(bf162*)&ol[(size_t)i * 4 + 2] = lb;
}

// ---------------- epilogue conv2 fused with conv3 dots ----------------
__global__ void ep2_conv3(const float* __restrict__ z, const float* __restrict__ agg,
                          const float* __restrict__ Wl, const float* __restrict__ Wr) {
    int w = (blockIdx.x * blockDim.x + threadIdx.x) >> 5;
    if (w >= NN) return;
    int lane = threadIdx.x & 31;
    size_t o = (size_t)w * 128 + lane * 4;
    float4 zv = *(const float4*)&z[o];
    float4 av = *(const float4*)&agg[o];
    float h0 = gelu_f(zv.x + av.x), h1 = gelu_f(zv.y + av.y);
    float h2 = gelu_f(zv.z + av.z), h3 = gelu_f(zv.w + av.w);
    float4 wl = *(const float4*)&Wl[lane * 4];
    float4 wr = *(const float4*)&Wr[lane * 4];
    float s1 = h0 * wl.x + h1 * wl.y + h2 * wl.z + h3 * wl.w;
    float s2 = h0 * wr.x + h1 * wr.y + h2 * wr.z + h3 * wr.w;
#pragma unroll
    for (int off = 16; off > 0; off >>= 1) {
        s1 += __shfl_down_sync(0xffffffffu, s1, off);
        s2 += __shfl_down_sync(0xffffffffu, s2, off);
    }
    if (lane == 0) { g_s1[w] = s1; g_s2[w] = s2; }
}

// =====================================================================
// bf16-pair (3-term) tensor GEMM with ldmatrix fragment loads
// EPI: 0 = gelu(v+bias); 1 = v+bias (bias may be null)
// OUTMODE: 0 = fp32 -> C0; 1 = bf16 hi->C0, lo->C1; 2 = fp16 -> C0
// =====================================================================
#define SMEM_DYN 65536

template<int K, int EPI, int OUTMODE>
__global__ void __launch_bounds__(256, 2)
tgemm3(const bf16* __restrict__ Ahi, const bf16* __restrict__ Alo, int lda,
       const bf16* __restrict__ Bhi, const bf16* __restrict__ Blo,
       const float* __restrict__ bias,
       void* __restrict__ C0, void* __restrict__ C1, int ldc)
{
    extern __shared__ __align__(16) char sm[];

    const int tid  = threadIdx.x;
    const int m0   = blockIdx.x * 128;
    const int wid  = tid >> 5;
    const int lane = tid & 31;
    const int g    = lane >> 2;
    const int tig  = lane & 3;
    const int warpM = (wid >> 2) * 64;
    const int warpN = (wid & 3) * 32;

    constexpr int NC = K / 32;
    const uint32_t smB = (uint32_t)__cvta_generic_to_shared(sm);

    const int laneT8 = lane & 7;
    const int aRow   = laneT8 + ((lane >> 3) & 1) * 8;
    const int aKh    = lane >> 4;
    const int bNsel  = lane >> 4;
    const int bKh    = (lane >> 3) & 1;

    float4 acc[4][4];
#pragma unroll
    for (int i = 0; i < 4; i++)
#pragma unroll
        for (int j = 0; j < 4; j++) acc[i][j] = make_float4(0.f, 0.f, 0.f, 0.f);

    auto copy_tile = [&](int buf, int k0) {
        uint32_t st = smB + (uint32_t)buf * 32768;
#pragma unroll
        for (int i = 0; i < 4; i++) {
            int flat = tid + i * 256;
            int half = flat >> 9;
            int rem  = flat & 511;
            int r = rem >> 2, seg = rem & 3;
            int row = m0 + r; if (row >= NN) row = NN - 1;
            const bf16* src = (half ? Alo : Ahi) + (size_t)row * lda + k0 + seg * 8;
            uint32_t dst = st + (uint32_t)half * 8192 + (uint32_t)r * 64
                         + (uint32_t)((seg ^ ((r >> 1) & 3)) << 4);
            cpasync16(dst, src);
        }
#pragma unroll
        for (int i = 0; i < 4; i++) {
            int flat = tid + i * 256;
            int half = flat >> 9;
            int rem  = flat & 511;
            int n = rem >> 2, seg = rem & 3;
            const bf16* src = (half ? Blo : Bhi) + (size_t)n * K + k0 + seg * 8;
            uint32_t dst = st + 16384u + (uint32_t)half * 8192 + (uint32_t)n * 64
                         + (uint32_t)((seg ^ ((n >> 1) & 3)) << 4);
            cpasync16(dst, src);
        }
        cp_commit();
    };

    copy_tile(0, 0);

    for (int ks = 0; ks < NC; ks++) {
        if (ks + 1 < NC) {
            copy_tile((ks + 1) & 1, (ks + 1) * 32);
            cp_wait<1>();
        } else {
            cp_wait<0>();
        }
        __syncthreads();

        const uint32_t stage = smB + (uint32_t)(ks & 1) * 32768;
        const uint32_t Abase = stage;
        const uint32_t Bbase = stage + 16384u;

#pragma unroll
        for (int kc = 0; kc < 2; kc++) {
            uint32_t bh[4][2], bl[4][2];
#pragma unroll
            for (int p = 0; p < 2; p++) {
                int n = warpN + (p * 2 + bNsel) * 8 + laneT8;
                int seg = kc * 2 + bKh;
                uint32_t addr = Bbase + (uint32_t)n * 64
                              + (uint32_t)((seg ^ ((n >> 1) & 3)) << 4);
                ldmx4(bh[p * 2][0], bh[p * 2][1], bh[p * 2 + 1][0], bh[p * 2 + 1][1], addr);
                ldmx4(bl[p * 2][0], bl[p * 2][1], bl[p * 2 + 1][0], bl[p * 2 + 1][1], addr + 8192u);
            }
#pragma unroll
            for (int mt = 0; mt < 4; mt++) {
                int r = warpM + mt * 16 + aRow;
                int seg = kc * 2 + aKh;
                uint32_t addr = Abase + (uint32_t)r * 64
                              + (uint32_t)((seg ^ ((r >> 1) & 3)) << 4);
                uint32_t ah[4], al[4];
                ldmx4(ah[0], ah[1], ah[2], ah[3], addr);
                ldmx4(al[0], al[1], al[2], al[3], addr + 8192u);
#pragma unroll
                for (int nt = 0; nt < 4; nt++) {
                    mma_bf16(acc[mt][nt], ah, bh[nt]);
                    mma_bf16(acc[mt][nt], ah, bl[nt]);
                    mma_bf16(acc[mt][nt], al, bh[nt]);
                }
            }
        }
        __syncthreads();
    }

#pragma unroll
    for (int mt = 0; mt < 4; mt++) {
        int r0 = m0 + warpM + mt * 16 + g;
#pragma unroll
        for (int rr = 0; rr < 2; rr++) {
            int r = r0 + rr * 8;
            if (r >= NN) continue;
#pragma unroll
            for (int nt = 0; nt < 4; nt++) {
                int col = warpN + nt * 8 + tig * 2;
                float v0 = (rr == 0) ? acc[mt][nt].x : acc[mt][nt].z;
                float v1 = (rr == 0) ? acc[mt][nt].y : acc[mt][nt].w;
                if (bias) { v0 += bias[col]; v1 += bias[col + 1]; }
                if (EPI == 0) { v0 = gelu_f(v0); v1 = gelu_f(v1); }
                if (OUTMODE == 0) {
                    *(float2*)((float*)C0 + (size_t)r * ldc + col) = make_float2(v0, v1);
                } else if (OUTMODE == 1) {
                    bf16 h0, l0, h1, l1;
                    split_bf(v0, h0, l0);
                    split_bf(v1, h1, l1);
                    bf162 hv; hv.x = h0; hv.y = h1;
                    bf162 lv; lv.x = l0; lv.y = l1;
                    *(bf162*)((bf16*)C0 + (size_t)r * ldc + col) = hv;
                    *(bf162*)((bf16*)C1 + (size_t)r * ldc + col) = lv;
                } else {
                    __half2 hv = __floats2half2_rn(v0, v1);
                    *(__half2*)((__half*)C0 + (size_t)r * ldc + col) = hv;
                }
            }
        }
    }
}

// ---------------- host ----------------
extern "C" void kernel_launch(void* const* d_in, const int* in_sizes, int n_in,
                              void* d_out, int out_size) {
    (void)n_in; (void)out_size;
    const int*   x_cat  = (const int*)  d_in[0];
    const float* x_cont = (const float*)d_in[1];
    const int*   ei     = (const int*)  d_in[2];
    const float* emb    = (const float*)d_in[3];
    const float* W1     = (const float*)d_in[4];
    const float* b1     = (const float*)d_in[5];
    const float* W2     = (const float*)d_in[6];
    const float* b2     = (const float*)d_in[7];
    const float* W3     = (const float*)d_in[8];
    const float* b3     = (const float*)d_in[9];
    const float* c1_Wl  = (const float*)d_in[10];
    const float* c1_bl  = (const float*)d_in[11];
    const float* c1_Wr  = (const float*)d_in[12];
    const float* c2_Wl  = (const float*)d_in[13];
    const float* c2_bl  = (const float*)d_in[14];
    const float* c2_Wr  = (const float*)d_in[15];
    const float* c3_Wl  = (const float*)d_in[16];
    const float* c3_bl  = (const float*)d_in[17];
    const float* c3_Wr  = (const float*)d_in[18];
    float* out = (float*)d_out;

    const int E = in_sizes[2] / 2;

    bf16 *p_xhi, *p_xlo, *p1h, *p1l, *p2h, *p2l, *wth, *wtl;
    __half* p_y;
    float *p_z, *p_agg;
    cudaGetSymbolAddress((void**)&p_xhi, g_xhi);
    cudaGetSymbolAddress((void**)&p_xlo, g_xlo);
    cudaGetSymbolAddress((void**)&p1h, g_p1hi);
    cudaGetSymbolAddress((void**)&p1l, g_p1lo);
    cudaGetSymbolAddress((void**)&p2h, g_p2hi);
    cudaGetSymbolAddress((void**)&p2l, g_p2lo);
    cudaGetSymbolAddress((void**)&p_y, g_y);
    cudaGetSymbolAddress((void**)&p_z, g_z);
    cudaGetSymbolAddress((void**)&p_agg, g_agg);
    cudaGetSymbolAddress((void**)&wth, g_wthi);
    cudaGetSymbolAddress((void**)&wtl, g_wtlo);

    const int O_W2  = 0;
    const int O_W3  = 16384;
    const int O_C1L = 32768;
    const int O_C1R = 57344;
    const int O_C2L = 81920;
    const int O_C2R = 98304;

    cudaFuncSetAttribute(tgemm3<128, 0, 1>, cudaFuncAttributeMaxDynamicSharedMemorySize, SMEM_DYN);
    cudaFuncSetAttribute(tgemm3<128, 1, 1>, cudaFuncAttributeMaxDynamicSharedMemorySize, SMEM_DYN);
    cudaFuncSetAttribute(tgemm3<192, 1, 2>, cudaFuncAttributeMaxDynamicSharedMemorySize, SMEM_DYN);
    cudaFuncSetAttribute(tgemm3<192, 1, 0>, cudaFuncAttributeMaxDynamicSharedMemorySize, SMEM_DYN);
    cudaFuncSetAttribute(tgemm3<128, 1, 2>, cudaFuncAttributeMaxDynamicSharedMemorySize, SMEM_DYN);
    cudaFuncSetAttribute(tgemm3<128, 1, 0>, cudaFuncAttributeMaxDynamicSharedMemorySize, SMEM_DYN);

    const int GB = (NN + 127) / 128;
    cudaStream_t ms = 0;

    cudaStream_t s2;
    cudaStreamCreateWithFlags(&s2, cudaStreamNonBlocking);
    cudaEvent_t ev0, evY1, evG1, evY2, evG2;
    cudaEventCreateWithFlags(&ev0, cudaEventDisableTiming);
    cudaEventCreateWithFlags(&evY1, cudaEventDisableTiming);
    cudaEventCreateWithFlags(&evG1, cudaEventDisableTiming);
    cudaEventCreateWithFlags(&evY2, cudaEventDisableTiming);
    cudaEventCreateWithFlags(&evG2, cudaEventDisableTiming);

    cudaEventRecord(ev0, ms);
    cudaStreamWaitEvent(s2, ev0, 0);

    // CSR build rides s2 under the MLP chain
    zero_cnt<<<(NN + 255) / 256, 256, 0, s2>>>();
    count_k<<<(E + 255) / 256, 256, 0, s2>>>(ei, E);
    scan_block<<<NB_SCAN, 1024, 0, s2>>>();
    scan_top<<<1, 32, 0, s2>>>();
    scan_add<<<(NN + 255) / 256, 256, 0, s2>>>();
    fill_k<<<(E + 255) / 256, 256, 0, s2>>>(ei, E);

    // MLP layer 1 via fused fp16 tables
    prep_T<<<NCAT * 2, 256, 0, ms>>>(emb, W1);
    copy_cont_split<<<(NN * 64 + 255) / 256, 256, 0, ms>>>(x_cont);
    emb_mlp1<<<(NN * 32 + 255) / 256, 256, 0, ms>>>(x_cat, b1, p1h, p1l);

    // weight prep
    prep_weight<<<(128 * 128 + 255) / 256, 256, 0, ms>>>(W2, 128, wth + O_W2, wtl + O_W2);
    prep_weight<<<(128 * 128 + 255) / 256, 256, 0, ms>>>(W3, 128, wth + O_W3, wtl + O_W3);
    prep_weight<<<(192 * 128 + 255) / 256, 256, 0, ms>>>(c1_Wl, 192, wth + O_C1L, wtl + O_C1L);
    prep_weight<<<(192 * 128 + 255) / 256, 256, 0, ms>>>(c1_Wr, 192, wth + O_C1R, wtl + O_C1R);
    prep_weight<<<(128 * 128 + 255) / 256, 256, 0, ms>>>(c2_Wl, 128, wth + O_C2L, wtl + O_C2L);
    prep_weight<<<(128 * 128 + 255) / 256, 256, 0, ms>>>(c2_Wr, 128, wth + O_C2R, wtl + O_C2R);

    // MLP layers 2-3
    tgemm3<128, 0, 1><<<GB, 256, SMEM_DYN, ms>>>(p1h, p1l, 128, wth + O_W2, wtl + O_W2,
                                                 b2, p2h, p2l, 128);
    tgemm3<128, 1, 1><<<GB, 256, SMEM_DYN, ms>>>(p2h, p2l, 128, wth + O_W3, wtl + O_W3,
                                                 b3, p_xhi, p_xlo, 192);

    // ---- conv1: y (fp16) on main; gather on s2 overlapped with z = x@Wr
    tgemm3<192, 1, 2><<<GB, 256, SMEM_DYN, ms>>>(p_xhi, p_xlo, 192, wth + O_C1L, wtl + O_C1L,
                                                 nullptr, p_y, nullptr, 128);
    cudaEventRecord(evY1, ms);
    cudaStreamWaitEvent(s2, evY1, 0);
    gather_vec<<<(NN * 32 + 255) / 256, 256, 0, s2>>>(p_y, p_agg);
    cudaEventRecord(evG1, s2);
    tgemm3<192, 1, 0><<<GB, 256, SMEM_DYN, ms>>>(p_xhi, p_xlo, 192, wth + O_C1R, wtl + O_C1R,
                                                 c1_bl, p_z, nullptr, 128);
    cudaStreamWaitEvent(ms, evG1, 0);
    ep_split<<<(NN * 32 + 255) / 256, 256, 0, ms>>>(p_z, p_agg, p1h, p1l);

    // ---- conv2
    tgemm3<128, 1, 2><<<GB, 256, SMEM_DYN, ms>>>(p1h, p1l, 128, wth + O_C2L, wtl + O_C2L,
                                                 nullptr, p_y, nullptr, 128);
    cudaEventRecord(evY2, ms);
    cudaStreamWaitEvent(s2, evY2, 0);
    gather_vec<<<(NN * 32 + 255) / 256, 256, 0, s2>>>(p_y, p_agg);
    cudaEventRecord(evG2, s2);
    tgemm3<128, 1, 0><<<GB, 256, SMEM_DYN, ms>>>(p1h, p1l, 128, wth + O_C2R, wtl + O_C2R,
                                                 c2_bl, p_z, nullptr, 128);
    cudaStreamWaitEvent(ms, evG2, 0);

    // ---- conv2 epilogue fused with conv3 dots, then final gather
    ep2_conv3<<<(NN * 32 + 255) / 256, 256, 0, ms>>>(p_z, p_agg, c3_Wl, c3_Wr);
    gather3_final<<<(NN * 32 + 255) / 256, 256, 0, ms>>>(c3_bl, out);
}

// round 11
// speedup vs baseline: 2.7304x; 1.0861x over previous
#include <cuda_runtime.h>
#include <cuda_bf16.h>
#include <cuda_fp16.h>
#include <cstdint>
#include <math.h>

#define NN   100000
#define NE   1600000
#define NCAT 20
#define EMBD 32
#define CARD 100
#define NB_SCAN 98   // ceil(NN/1024)

typedef __nv_bfloat16 bf16;
typedef __nv_bfloat162 bf162;

// ---------------- scratch (device globals) ----------------
__device__ bf16 g_ch[(size_t)NN * 64], g_cl[(size_t)NN * 64];     // x_cont split
__device__ bf16 g_p1hi[(size_t)NN * 128], g_p1lo[(size_t)NN * 128];
__device__ bf16 g_p2hi[(size_t)NN * 128], g_p2lo[(size_t)NN * 128];
__device__ __half g_y[(size_t)NN * 128];          // fp16 pre-aggregation features
__device__ float g_z[(size_t)NN * 128];
__device__ float g_agg[(size_t)NN * 128];
__device__ float g_s1[NN], g_s2[NN];
__device__ bf16 g_wthi[768 * 128], g_wtlo[768 * 128];   // [n][k] transposed weights
__device__ float g_bfl[128], g_bfr[128];                 // folded conv1 biases
__device__ __half g_Th[NCAT * CARD * 128];               // fused emb@W1 tables (fp16)
// CSR
__device__ int g_cnt[NN];
__device__ int g_start[NN + 1];
__device__ int g_cursor[NN];
__device__ int g_csrc[NE];
__device__ int g_bsum[NB_SCAN];

__device__ __forceinline__ float gelu_f(float v) {
    return 0.5f * v * (1.0f + erff(v * 0.70710678118654752f));
}
__device__ __forceinline__ void split_bf(float v, bf16& h, bf16& l) {
    h = __float2bfloat16(v);
    l = __float2bfloat16(v - __bfloat162float(h));
}
__device__ __forceinline__ void mma_bf16(float4& c, const uint32_t* a, const uint32_t* b) {
    asm volatile("mma.sync.aligned.m16n8k16.row.col.f32.bf16.bf16.f32 "
                 "{%0,%1,%2,%3}, {%4,%5,%6,%7}, {%8,%9}, {%0,%1,%2,%3};"
                 : "+f"(c.x), "+f"(c.y), "+f"(c.z), "+f"(c.w)
                 : "r"(a[0]), "r"(a[1]), "r"(a[2]), "r"(a[3]), "r"(b[0]), "r"(b[1]));
}
__device__ __forceinline__ void ldmx4(uint32_t& r0, uint32_t& r1, uint32_t& r2, uint32_t& r3,
                                      uint32_t addr) {
    asm volatile("ldmatrix.sync.aligned.m8n8.x4.shared.b16 {%0,%1,%2,%3}, [%4];"
                 : "=r"(r0), "=r"(r1), "=r"(r2), "=r"(r3) : "r"(addr));
}
__device__ __forceinline__ void cpasync16(uint32_t dst, const void* src) {
    asm volatile("cp.async.cg.shared.global [%0], [%1], 16;" :: "r"(dst), "l"(src));
}
__device__ __forceinline__ void cp_commit() { asm volatile("cp.async.commit_group;"); }
template<int N> __device__ __forceinline__ void cp_wait() {
    asm volatile("cp.async.wait_group %0;" :: "n"(N));
}

// ---------------- prep kernels ----------------
// W [K][128] fp32 -> out [128][K] bf16 hi/lo
__global__ void prep_weight(const float* __restrict__ W, int K,
                            bf16* __restrict__ oh, bf16* __restrict__ ol) {
    int i = blockIdx.x * blockDim.x + threadIdx.x;
    if (i < 128 * K) {
        int k = i >> 7, n = i & 127;
        float v = W[i];
        bf16 h, l; split_bf(v, h, l);
        oh[(size_t)n * K + k] = h;
        ol[(size_t)n * K + k] = l;
    }
}
// fold: Wf = W3 @ cW[:128]  (fp32), transposed-split out; bias[n] = b3@cW[:,n] + extra
__global__ void __launch_bounds__(256)
fold_w3(const float* __restrict__ W3, const float* __restrict__ cW,
        const float* __restrict__ b3, const float* __restrict__ extra_bias,
        bf16* __restrict__ oh, bf16* __restrict__ ol, float* __restrict__ obias) {
    int idx = blockIdx.x * 256 + threadIdx.x;   // 0..16383
    int k = idx >> 7, n = idx & 127;
    float acc = 0.f;
    for (int d = 0; d < 128; d++)
        acc += W3[k * 128 + d] * cW[d * 128 + n];
    bf16 h, l; split_bf(acc, h, l);
    oh[(size_t)n * 128 + k] = h;
    ol[(size_t)n * 128 + k] = l;
    if (k == 0) {
        float bacc = extra_bias ? extra_bias[n] : 0.f;
        for (int d = 0; d < 128; d++) bacc += b3[d] * cW[d * 128 + n];
        obias[n] = bacc;
    }
}
__global__ void copy_cont_split(const float* __restrict__ xc) {
    int i = blockIdx.x * blockDim.x + threadIdx.x;
    if (i < NN * 64) {
        bf16 h, l; split_bf(xc[i], h, l);
        g_ch[i] = h; g_cl[i] = l;
    }
}

// ---------------- emb@W1 table precompute (fp16 output) ----------------
__global__ void __launch_bounds__(256)
prep_T(const float* __restrict__ emb, const float* __restrict__ W1) {
    __shared__ float se[50 * 32];
    __shared__ float sw[32 * 128];
    int c = blockIdx.x >> 1;
    int rh = blockIdx.x & 1;
    int tid = threadIdx.x;
    for (int i = tid; i < 50 * 32; i += 256)
        se[i] = emb[(size_t)c * CARD * EMBD + rh * 50 * 32 + i];
    for (int i = tid; i < 32 * 128; i += 256)
        sw[i] = W1[(size_t)(c * 32) * 128 + i];
    __syncthreads();
    for (int i = 0; i < 25; i++) {
        int idx = tid + i * 256;
        int r = idx >> 7, n = idx & 127;
        float acc = 0.f;
#pragma unroll
        for (int d = 0; d < 32; d++)
            acc += se[r * 32 + d] * sw[d * 128 + n];
        g_Th[((size_t)c * CARD + rh * 50 + r) * 128 + n] = __float2half(acc);
    }
}

// ---------------- MLP layer 1 via fp16 table lookup-sum ----------------
__global__ void __launch_bounds__(256)
emb_mlp1(const int* __restrict__ xcat, const float* __restrict__ b1,
         bf16* __restrict__ oh, bf16* __restrict__ ol) {
    int w = (blockIdx.x * blockDim.x + threadIdx.x) >> 5;
    if (w >= NN) return;
    int lane = threadIdx.x & 31;
    const int* xc = xcat + (size_t)w * NCAT;
    float4 acc = *(const float4*)&b1[lane * 4];
#pragma unroll
    for (int c = 0; c < NCAT; c++) {
        int cat = __ldg(&xc[c]);
        uint2 u = *(const uint2*)&g_Th[((size_t)c * CARD + cat) * 128 + lane * 4];
        float2 f0 = __half22float2(*(__half2*)&u.x);
        float2 f1 = __half22float2(*(__half2*)&u.y);
        acc.x += f0.x; acc.y += f0.y; acc.z += f1.x; acc.w += f1.y;
    }
    float v0 = gelu_f(acc.x), v1 = gelu_f(acc.y), v2 = gelu_f(acc.z), v3 = gelu_f(acc.w);
    bf16 h0, l0, h1, l1, h2, l2, h3, l3;
    split_bf(v0, h0, l0); split_bf(v1, h1, l1);
    split_bf(v2, h2, l2); split_bf(v3, h3, l3);
    bf162 ha; ha.x = h0; ha.y = h1;
    bf162 hb; hb.x = h2; hb.y = h3;
    bf162 la; la.x = l0; la.y = l1;
    bf162 lb; lb.x = l2; lb.y = l3;
    size_t o = (size_t)w * 128 + lane * 4;
    *(bf162*)&oh[o] = ha; *(bf162*)&oh[o + 2] = hb;
    *(bf162*)&ol[o] = la; *(bf162*)&ol[o + 2] = lb;
}

// ---------------- CSR build ----------------
__global__ void zero_cnt() {
    int i = blockIdx.x * blockDim.x + threadIdx.x;
    if (i < NN) g_cnt[i] = 0;
}
__global__ void count_k(const int* __restrict__ ei, int E) {
    int e = blockIdx.x * blockDim.x + threadIdx.x;
    if (e < E) atomicAdd(&g_cnt[ei[E + e]], 1);
}
__global__ void scan_block() {
    __shared__ int sh[1024];
    int tid = threadIdx.x;
    int i = blockIdx.x * 1024 + tid;
    int v = (i < NN) ? g_cnt[i] : 0;
    sh[tid] = v;
    __syncthreads();
#pragma unroll
    for (int off = 1; off < 1024; off <<= 1) {
        int t = (tid >= off) ? sh[tid - off] : 0;
        __syncthreads();
        sh[tid] += t;
        __syncthreads();
    }
    if (i < NN) g_start[i] = sh[tid] - v;
    if (tid == 1023) g_bsum[blockIdx.x] = sh[1023];
}
__global__ void scan_top() {
    if (threadIdx.x == 0) {
        int acc = 0;
        for (int j = 0; j < NB_SCAN; j++) { int t = g_bsum[j]; g_bsum[j] = acc; acc += t; }
        g_start[NN] = acc;
    }
}
__global__ void scan_add() {
    int i = blockIdx.x * blockDim.x + threadIdx.x;
    if (i < NN) {
        int s = g_start[i] + g_bsum[i >> 10];
        g_start[i] = s;
        g_cursor[i] = s;
    }
}
__global__ void fill_k(const int* __restrict__ ei, int E) {
    int e = blockIdx.x * blockDim.x + threadIdx.x;
    if (e < E) {
        int dst = ei[E + e];
        int pos = atomicAdd(&g_cursor[dst], 1);
        g_csrc[pos] = ei[e];
    }
}

// ---------------- gather kernels ----------------
__global__ void gather_vec(const __half* __restrict__ y, float* __restrict__ agg) {
    int w = (blockIdx.x * blockDim.x + threadIdx.x) >> 5;
    if (w >= NN) return;
    int lane = threadIdx.x & 31;
    int s = g_start[w], e = g_start[w + 1];
    float inv = 1.f / fmaxf((float)(e - s), 1.f);
    float a0 = 0.f, a1 = 0.f, a2 = 0.f, a3 = 0.f;
    float b0 = 0.f, b1 = 0.f, b2 = 0.f, b3 = 0.f;
    int i = s;
    for (; i + 1 < e; i += 2) {
        int r0 = g_csrc[i], r1 = g_csrc[i + 1];
        uint2 u0 = *(const uint2*)&y[(size_t)r0 * 128 + lane * 4];
        uint2 u1 = *(const uint2*)&y[(size_t)r1 * 128 + lane * 4];
        float2 p0 = __half22float2(*(__half2*)&u0.x);
        float2 p1 = __half22float2(*(__half2*)&u0.y);
        float2 q0 = __half22float2(*(__half2*)&u1.x);
        float2 q1 = __half22float2(*(__half2*)&u1.y);
        a0 += p0.x; a1 += p0.y; a2 += p1.x; a3 += p1.y;
        b0 += q0.x; b1 += q0.y; b2 += q1.x; b3 += q1.y;
    }
    if (i < e) {
        int r0 = g_csrc[i];
        uint2 u0 = *(const uint2*)&y[(size_t)r0 * 128 + lane * 4];
        float2 p0 = __half22float2(*(__half2*)&u0.x);
        float2 p1 = __half22float2(*(__half2*)&u0.y);
        a0 += p0.x; a1 += p0.y; a2 += p1.x; a3 += p1.y;
    }
    float4 o = make_float4((a0 + b0) * inv, (a1 + b1) * inv,
                           (a2 + b2) * inv, (a3 + b3) * inv);
    *(float4*)&agg[(size_t)w * 128 + lane * 4] = o;
}

__global__ void gather3_final(const float* __restrict__ bl, float* __restrict__ out) {
    int w = (blockIdx.x * blockDim.x + threadIdx.x) >> 5;
    if (w >= NN) return;
    int lane = threadIdx.x & 31;
    int s = g_start[w], e = g_start[w + 1];
    float inv = 1.f / fmaxf((float)(e - s), 1.f);
    float sum = 0.f;
    for (int i = s + lane; i < e; i += 32) sum += g_s1[g_csrc[i]];
#pragma unroll
    for (int o = 16; o > 0; o >>= 1) sum += __shfl_down_sync(0xffffffffu, sum, o);
    if (lane == 0) out[w] = sum * inv + bl[0] + g_s2[w];
}

// ---------------- epilogue conv1: v = gelu(z + agg) -> split ----------------
__global__ void ep_split(const float* __restrict__ z, const float* __restrict__ agg,
                         bf16* __restrict__ oh, bf16* __restrict__ ol) {
    int i = blockIdx.x * blockDim.x + threadIdx.x;
    if (i >= NN * 32) return;
    float4 zv = *(const float4*)&z[(size_t)i * 4];
    float4 av = *(const float4*)&agg[(size_t)i * 4];
    float v0 = gelu_f(zv.x + av.x), v1 = gelu_f(zv.y + av.y);
    float v2 = gelu_f(zv.z + av.z), v3 = gelu_f(zv.w + av.w);
    bf16 h0, l0, h1, l1, h2, l2, h3, l3;
    split_bf(v0, h0, l0); split_bf(v1, h1, l1);
    split_bf(v2, h2, l2); split_bf(v3, h3, l3);
    bf162 ha; ha.x = h0; ha.y = h1;
    bf162 hb; hb.x = h2; hb.y = h3;
    bf162 la; la.x = l0; la.y = l1;
    bf162 lb; lb.x = l2; lb.y = l3;
    *(bf162*)&oh[(size_t)i * 4] = ha;
    *(bf162*)&oh[(size_t)i * 4 + 2] = hb;
    *(bf162*)&ol[(size_t)i * 4] = la;
    *(bf162*)&ol[(size_t)i * 4 + 2] = lb;
}

// ---------------- epilogue conv2 fused with conv3 dots ----------------
__global__ void ep2_conv3(const float* __restrict__ z, const float* __restrict__ agg,
                          const float* __restrict__ Wl, const float* __restrict__ Wr) {
    int w = (blockIdx.x * blockDim.x + threadIdx.x) >> 5;
    if (w >= NN) return;
    int lane = threadIdx.x & 31;
    size_t o = (size_t)w * 128 + lane * 4;
    float4 zv = *(const float4*)&z[o];
    float4 av = *(const float4*)&agg[o];
    float h0 = gelu_f(zv.x + av.x), h1 = gelu_f(zv.y + av.y);
    float h2 = gelu_f(zv.z + av.z), h3 = gelu_f(zv.w + av.w);
    float4 wl = *(const float4*)&Wl[lane * 4];
    float4 wr = *(const float4*)&Wr[lane * 4];
    float s1 = h0 * wl.x + h1 * wl.y + h2 * wl.z + h3 * wl.w;
    float s2 = h0 * wr.x + h1 * wr.y + h2 * wr.z + h3 * wr.w;
#pragma unroll
    for (int off = 16; off > 0; off >>= 1) {
        s1 += __shfl_down_sync(0xffffffffu, s1, off);
        s2 += __shfl_down_sync(0xffffffffu, s2, off);
    }
    if (lane == 0) { g_s1[w] = s1; g_s2[w] = s2; }
}

// =====================================================================
// bf16-pair (3-term) tensor GEMM with ldmatrix fragment loads
// SPLIT: A/B come from two sources — k<128 from (Ahi/Alo, Bhi/Blo; strides lda/128),
//        k>=128 from (A2,B2; stride 64). K must be 192 when SPLIT.
// EPI: 0 = gelu(v+bias); 1 = v+bias (bias may be null)
// OUTMODE: 0 = fp32 -> C0; 1 = bf16 hi->C0, lo->C1; 2 = fp16 -> C0
// =====================================================================
#define SMEM_DYN 65536

template<int K, int EPI, int OUTMODE, bool SPLIT>
__global__ void __launch_bounds__(256, 2)
tgemm3(const bf16* __restrict__ Ahi, const bf16* __restrict__ Alo, int lda,
       const bf16* __restrict__ Bhi, const bf16* __restrict__ Blo,
       const float* __restrict__ bias,
       void* __restrict__ C0, void* __restrict__ C1, int ldc,
       const bf16* __restrict__ A2hi, const bf16* __restrict__ A2lo,
       const bf16* __restrict__ B2hi, const bf16* __restrict__ B2lo)
{
    extern __shared__ __align__(16) char sm[];

    const int tid  = threadIdx.x;
    const int m0   = blockIdx.x * 128;
    const int wid  = tid >> 5;
    const int lane = tid & 31;
    const int g    = lane >> 2;
    const int tig  = lane & 3;
    const int warpM = (wid >> 2) * 64;
    const int warpN = (wid & 3) * 32;

    constexpr int NC = K / 32;
    constexpr int BK = SPLIT ? 128 : K;    // stride of first B source
    const uint32_t smB = (uint32_t)__cvta_generic_to_shared(sm);

    const int laneT8 = lane & 7;
    const int aRow   = laneT8 + ((lane >> 3) & 1) * 8;
    const int aKh    = lane >> 4;
    const int bNsel  = lane >> 4;
    const int bKh    = (lane >> 3) & 1;

    float4 acc[4][4];
#pragma unroll
    for (int i = 0; i < 4; i++)
#pragma unroll
        for (int j = 0; j < 4; j++) acc[i][j] = make_float4(0.f, 0.f, 0.f, 0.f);

    auto copy_tile = [&](int buf, int k0) {
        uint32_t st = smB + (uint32_t)buf * 32768;
#pragma unroll
        for (int i = 0; i < 4; i++) {
            int flat = tid + i * 256;
            int half = flat >> 9;
            int rem  = flat & 511;
            int r = rem >> 2, seg = rem & 3;
            int row = m0 + r; if (row >= NN) row = NN - 1;
            const bf16* src;
            if (SPLIT && k0 >= 128) {
                src = (half ? A2lo : A2hi) + (size_t)row * 64 + (k0 - 128) + seg * 8;
            } else {
                src = (half ? Alo : Ahi) + (size_t)row * lda + k0 + seg * 8;
            }
            uint32_t dst = st + (uint32_t)half * 8192 + (uint32_t)r * 64
                         + (uint32_t)((seg ^ ((r >> 1) & 3)) << 4);
            cpasync16(dst, src);
        }
#pragma unroll
        for (int i = 0; i < 4; i++) {
            int flat = tid + i * 256;
            int half = flat >> 9;
            int rem  = flat & 511;
            int n = rem >> 2, seg = rem & 3;
            const bf16* src;
            if (SPLIT && k0 >= 128) {
                src = (half ? B2lo : B2hi) + (size_t)n * 64 + (k0 - 128) + seg * 8;
            } else {
                src = (half ? Blo : Bhi) + (size_t)n * BK + k0 + seg * 8;
            }
            uint32_t dst = st + 16384u + (uint32_t)half * 8192 + (uint32_t)n * 64
                         + (uint32_t)((seg ^ ((n >> 1) & 3)) << 4);
            cpasync16(dst, src);
        }
        cp_commit();
    };

    copy_tile(0, 0);

    for (int ks = 0; ks < NC; ks++) {
        if (ks + 1 < NC) {
            copy_tile((ks + 1) & 1, (ks + 1) * 32);
            cp_wait<1>();
        } else {
            cp_wait<0>();
        }
        __syncthreads();

        const uint32_t stage = smB + (uint32_t)(ks & 1) * 32768;
        const uint32_t Abase = stage;
        const uint32_t Bbase = stage + 16384u;

#pragma unroll
        for (int kc = 0; kc < 2; kc++) {
            uint32_t bh[4][2], bl[4][2];
#pragma unroll
            for (int p = 0; p < 2; p++) {
                int n = warpN + (p * 2 + bNsel) * 8 + laneT8;
                int seg = kc * 2 + bKh;
                uint32_t addr = Bbase + (uint32_t)n * 64
                              + (uint32_t)((seg ^ ((n >> 1) & 3)) << 4);
                ldmx4(bh[p * 2][0], bh[p * 2][1], bh[p * 2 + 1][0], bh[p * 2 + 1][1], addr);
                ldmx4(bl[p * 2][0], bl[p * 2][1], bl[p * 2 + 1][0], bl[p * 2 + 1][1], addr + 8192u);
            }
#pragma unroll
            for (int mt = 0; mt < 4; mt++) {
                int r = warpM + mt * 16 + aRow;
                int seg = kc * 2 + aKh;
                uint32_t addr = Abase + (uint32_t)r * 64
                              + (uint32_t)((seg ^ ((r >> 1) & 3)) << 4);
                uint32_t ah[4], al[4];
                ldmx4(ah[0], ah[1], ah[2], ah[3], addr);
                ldmx4(al[0], al[1], al[2], al[3], addr + 8192u);
#pragma unroll
                for (int nt = 0; nt < 4; nt++) {
                    mma_bf16(acc[mt][nt], ah, bh[nt]);
                    mma_bf16(acc[mt][nt], ah, bl[nt]);
                    mma_bf16(acc[mt][nt], al, bh[nt]);
                }
            }
        }
        __syncthreads();
    }

#pragma unroll
    for (int mt = 0; mt < 4; mt++) {
        int r0 = m0 + warpM + mt * 16 + g;
#pragma unroll
        for (int rr = 0; rr < 2; rr++) {
            int r = r0 + rr * 8;
            if (r >= NN) continue;
#pragma unroll
            for (int nt = 0; nt < 4; nt++) {
                int col = warpN + nt * 8 + tig * 2;
                float v0 = (rr == 0) ? acc[mt][nt].x : acc[mt][nt].z;
                float v1 = (rr == 0) ? acc[mt][nt].y : acc[mt][nt].w;
                if (bias) { v0 += bias[col]; v1 += bias[col + 1]; }
                if (EPI == 0) { v0 = gelu_f(v0); v1 = gelu_f(v1); }
                if (OUTMODE == 0) {
                    *(float2*)((float*)C0 + (size_t)r * ldc + col) = make_float2(v0, v1);
                } else if (OUTMODE == 1) {
                    bf16 h0, l0, h1, l1;
                    split_bf(v0, h0, l0);
                    split_bf(v1, h1, l1);
                    bf162 hv; hv.x = h0; hv.y = h1;
                    bf162 lv; lv.x = l0; lv.y = l1;
                    *(bf162*)((bf16*)C0 + (size_t)r * ldc + col) = hv;
                    *(bf162*)((bf16*)C1 + (size_t)r * ldc + col) = lv;
                } else {
                    __half2 hv = __floats2half2_rn(v0, v1);
                    *(__half2*)((__half*)C0 + (size_t)r * ldc + col) = hv;
                }
            }
        }
    }
}

// ---------------- host ----------------
extern "C" void kernel_launch(void* const* d_in, const int* in_sizes, int n_in,
                              void* d_out, int out_size) {
    (void)n_in; (void)out_size;
    const int*   x_cat  = (const int*)  d_in[0];
    const float* x_cont = (const float*)d_in[1];
    const int*   ei     = (const int*)  d_in[2];
    const float* emb    = (const float*)d_in[3];
    const float* W1     = (const float*)d_in[4];
    const float* b1     = (const float*)d_in[5];
    const float* W2     = (const float*)d_in[6];
    const float* b2     = (const float*)d_in[7];
    const float* W3     = (const float*)d_in[8];
    const float* b3     = (const float*)d_in[9];
    const float* c1_Wl  = (const float*)d_in[10];
    const float* c1_bl  = (const float*)d_in[11];
    const float* c1_Wr  = (const float*)d_in[12];
    const float* c2_Wl  = (const float*)d_in[13];
    const float* c2_bl  = (const float*)d_in[14];
    const float* c2_Wr  = (const float*)d_in[15];
    const float* c3_Wl  = (const float*)d_in[16];
    const float* c3_bl  = (const float*)d_in[17];
    const float* c3_Wr  = (const float*)d_in[18];
    float* out = (float*)d_out;

    const int E = in_sizes[2] / 2;

    bf16 *p_ch, *p_cl, *p1h, *p1l, *p2h, *p2l, *wth, *wtl;
    __half* p_y;
    float *p_z, *p_agg, *p_bfl, *p_bfr;
    cudaGetSymbolAddress((void**)&p_ch, g_ch);
    cudaGetSymbolAddress((void**)&p_cl, g_cl);
    cudaGetSymbolAddress((void**)&p1h, g_p1hi);
    cudaGetSymbolAddress((void**)&p1l, g_p1lo);
    cudaGetSymbolAddress((void**)&p2h, g_p2hi);
    cudaGetSymbolAddress((void**)&p2l, g_p2lo);
    cudaGetSymbolAddress((void**)&p_y, g_y);
    cudaGetSymbolAddress((void**)&p_z, g_z);
    cudaGetSymbolAddress((void**)&p_agg, g_agg);
    cudaGetSymbolAddress((void**)&wth, g_wthi);
    cudaGetSymbolAddress((void**)&wtl, g_wtlo);
    cudaGetSymbolAddress((void**)&p_bfl, g_bfl);
    cudaGetSymbolAddress((void**)&p_bfr, g_bfr);

    // transposed weight offsets (elements)
    const int O_W2  = 0;        // 128x128
    const int O_FL  = 16384;    // folded conv1 Wl (128x128)
    const int O_FR  = 32768;    // folded conv1 Wr (128x128)
    const int O_CL  = 49152;    // conv1 Wl cont part (128x64)
    const int O_CR  = 57344;    // conv1 Wr cont part (128x64)
    const int O_C2L = 65536;    // 128x128
    const int O_C2R = 81920;    // 128x128

    // ---- persistent streams/events: created ONCE (first call, before the
    // harness takes its pre-capture memory baseline). No allocation happens
    // during graph capture or replay; work per call is identical.
    static cudaStream_t s2 = nullptr, s3 = nullptr;
    static cudaEvent_t ev0, evW, evY1, evG1, evY2, evG2;
    static bool init_done = false;
    if (!init_done) {
        cudaStreamCreateWithFlags(&s2, cudaStreamNonBlocking);
        cudaStreamCreateWithFlags(&s3, cudaStreamNonBlocking);
        cudaEventCreateWithFlags(&ev0, cudaEventDisableTiming);
        cudaEventCreateWithFlags(&evW, cudaEventDisableTiming);
        cudaEventCreateWithFlags(&evY1, cudaEventDisableTiming);
        cudaEventCreateWithFlags(&evG1, cudaEventDisableTiming);
        cudaEventCreateWithFlags(&evY2, cudaEventDisableTiming);
        cudaEventCreateWithFlags(&evG2, cudaEventDisableTiming);
        cudaFuncSetAttribute(tgemm3<128, 0, 1, false>, cudaFuncAttributeMaxDynamicSharedMemorySize, SMEM_DYN);
        cudaFuncSetAttribute(tgemm3<192, 1, 2, true>,  cudaFuncAttributeMaxDynamicSharedMemorySize, SMEM_DYN);
        cudaFuncSetAttribute(tgemm3<192, 1, 0, true>,  cudaFuncAttributeMaxDynamicSharedMemorySize, SMEM_DYN);
        cudaFuncSetAttribute(tgemm3<128, 1, 2, false>, cudaFuncAttributeMaxDynamicSharedMemorySize, SMEM_DYN);
        cudaFuncSetAttribute(tgemm3<128, 1, 0, false>, cudaFuncAttributeMaxDynamicSharedMemorySize, SMEM_DYN);
        init_done = true;
    }

    const int GB = (NN + 127) / 128;
    cudaStream_t ms = 0;

    cudaEventRecord(ev0, ms);
    cudaStreamWaitEvent(s2, ev0, 0);
    cudaStreamWaitEvent(s3, ev0, 0);

    // s2: CSR build
    zero_cnt<<<(NN + 255) / 256, 256, 0, s2>>>();
    count_k<<<(E + 255) / 256, 256, 0, s2>>>(ei, E);
    scan_block<<<NB_SCAN, 1024, 0, s2>>>();
    scan_top<<<1, 32, 0, s2>>>();
    scan_add<<<(NN + 255) / 256, 256, 0, s2>>>();
    fill_k<<<(E + 255) / 256, 256, 0, s2>>>(ei, E);

    // s3: weight prep + folding
    prep_weight<<<(128 * 128 + 255) / 256, 256, 0, s3>>>(W2, 128, wth + O_W2, wtl + O_W2);
    fold_w3<<<64, 256, 0, s3>>>(W3, c1_Wl, b3, nullptr, wth + O_FL, wtl + O_FL, p_bfl);
    fold_w3<<<64, 256, 0, s3>>>(W3, c1_Wr, b3, c1_bl,   wth + O_FR, wtl + O_FR, p_bfr);
    prep_weight<<<(128 * 64 + 255) / 256, 256, 0, s3>>>(c1_Wl + 128 * 128, 64, wth + O_CL, wtl + O_CL);
    prep_weight<<<(128 * 64 + 255) / 256, 256, 0, s3>>>(c1_Wr + 128 * 128, 64, wth + O_CR, wtl + O_CR);
    prep_weight<<<(128 * 128 + 255) / 256, 256, 0, s3>>>(c2_Wl, 128, wth + O_C2L, wtl + O_C2L);
    prep_weight<<<(128 * 128 + 255) / 256, 256, 0, s3>>>(c2_Wr, 128, wth + O_C2R, wtl + O_C2R);
    cudaEventRecord(evW, s3);

    // ms: MLP layer 1 via fused fp16 tables
    prep_T<<<NCAT * 2, 256, 0, ms>>>(emb, W1);
    copy_cont_split<<<(NN * 64 + 255) / 256, 256, 0, ms>>>(x_cont);
    emb_mlp1<<<(NN * 32 + 255) / 256, 256, 0, ms>>>(x_cat, b1, p1h, p1l);

    cudaStreamWaitEvent(ms, evW, 0);

    // MLP layer 2 (W3 folded into conv1)
    tgemm3<128, 0, 1, false><<<GB, 256, SMEM_DYN, ms>>>(p1h, p1l, 128, wth + O_W2, wtl + O_W2,
                                                        b2, p2h, p2l, 128,
                                                        nullptr, nullptr, nullptr, nullptr);

    // ---- conv1: y = h2@Wfl + xc@Wlc + bfl (fp16 out); gather on s2; z = h2@Wfr + xc@Wrc + bfr
    tgemm3<192, 1, 2, true><<<GB, 256, SMEM_DYN, ms>>>(p2h, p2l, 128, wth + O_FL, wtl + O_FL,
                                                       p_bfl, p_y, nullptr, 128,
                                                       p_ch, p_cl, wth + O_CL, wtl + O_CL);
    cudaEventRecord(evY1, ms);
    cudaStreamWaitEvent(s2, evY1, 0);
    gather_vec<<<(NN * 32 + 255) / 256, 256, 0, s2>>>(p_y, p_agg);
    cudaEventRecord(evG1, s2);
    tgemm3<192, 1, 0, true><<<GB, 256, SMEM_DYN, ms>>>(p2h, p2l, 128, wth + O_FR, wtl + O_FR,
                                                       p_bfr, p_z, nullptr, 128,
                                                       p_ch, p_cl, wth + O_CR, wtl + O_CR);
    cudaStreamWaitEvent(ms, evG1, 0);
    ep_split<<<(NN * 32 + 255) / 256, 256, 0, ms>>>(p_z, p_agg, p1h, p1l);

    // ---- conv2
    tgemm3<128, 1, 2, false><<<GB, 256, SMEM_DYN, ms>>>(p1h, p1l, 128, wth + O_C2L, wtl + O_C2L,
                                                        nullptr, p_y, nullptr, 128,
                                                        nullptr, nullptr, nullptr, nullptr);
    cudaEventRecord(evY2, ms);
    cudaStreamWaitEvent(s2, evY2, 0);
    gather_vec<<<(NN * 32 + 255) / 256, 256, 0, s2>>>(p_y, p_agg);
    cudaEventRecord(evG2, s2);
    tgemm3<128, 1, 0, false><<<GB, 256, SMEM_DYN, ms>>>(p1h, p1l, 128, wth + O_C2R, wtl + O_C2R,
                                                        c2_bl, p_z, nullptr, 128,
                                                        nullptr, nullptr, nullptr, nullptr);
    cudaStreamWaitEvent(ms, evG2, 0);

    // ---- conv2 epilogue fused with conv3 dots, then final gather
    ep2_conv3<<<(NN * 32 + 255) / 256, 256, 0, ms>>>(p_z, p_agg, c3_Wl, c3_Wr);
    gather3_final<<<(NN * 32 + 255) / 256, 256, 0, ms>>>(c3_bl, out);
}

// round 12
// speedup vs baseline: 3.6263x; 1.3281x over previous
#include <cuda_runtime.h>
#include <cuda_bf16.h>
#include <cuda_fp16.h>
#include <cstdint>
#include <math.h>

#define NN   100000
#define NE   1600000
#define NCAT 20
#define EMBD 32
#define CARD 100
#define NB_SCAN 98   // ceil(NN/1024)

// ---------------- scratch (device globals) ----------------
__device__ __half g_c[(size_t)NN * 64];           // x_cont fp16
__device__ __half g_p1[(size_t)NN * 128];         // layer buffers (fp16)
__device__ __half g_p2[(size_t)NN * 128];
__device__ __half g_y[(size_t)NN * 128];          // fp16 pre-aggregation features
__device__ float g_z[(size_t)NN * 128];
__device__ float g_agg[(size_t)NN * 128];
__device__ float g_s1[NN], g_s2[NN];
__device__ __half g_wt[768 * 128];                // [n][k] transposed fp16 weights
__device__ float g_bfl[128], g_bfr[128];          // folded conv1 biases
__device__ __half g_Th[NCAT * CARD * 128];        // fused emb@W1 tables (fp16)
// CSR
__device__ int g_cnt[NN];
__device__ int g_start[NN + 1];
__device__ int g_cursor[NN];
__device__ int g_csrc[NE];
__device__ int g_bsum[NB_SCAN];

__device__ __forceinline__ float gelu_f(float v) {
    return 0.5f * v * (1.0f + erff(v * 0.70710678118654752f));
}
__device__ __forceinline__ void mma_f16(float4& c, const uint32_t* a, const uint32_t* b) {
    asm volatile("mma.sync.aligned.m16n8k16.row.col.f32.f16.f16.f32 "
                 "{%0,%1,%2,%3}, {%4,%5,%6,%7}, {%8,%9}, {%0,%1,%2,%3};"
                 : "+f"(c.x), "+f"(c.y), "+f"(c.z), "+f"(c.w)
                 : "r"(a[0]), "r"(a[1]), "r"(a[2]), "r"(a[3]), "r"(b[0]), "r"(b[1]));
}
__device__ __forceinline__ void ldmx4(uint32_t& r0, uint32_t& r1, uint32_t& r2, uint32_t& r3,
                                      uint32_t addr) {
    asm volatile("ldmatrix.sync.aligned.m8n8.x4.shared.b16 {%0,%1,%2,%3}, [%4];"
                 : "=r"(r0), "=r"(r1), "=r"(r2), "=r"(r3) : "r"(addr));
}
__device__ __forceinline__ void cpasync16(uint32_t dst, const void* src) {
    asm volatile("cp.async.cg.shared.global [%0], [%1], 16;" :: "r"(dst), "l"(src));
}
__device__ __forceinline__ void cp_commit() { asm volatile("cp.async.commit_group;"); }
template<int N> __device__ __forceinline__ void cp_wait() {
    asm volatile("cp.async.wait_group %0;" :: "n"(N));
}

// ---------------- prep kernels ----------------
// W [K][128] fp32 -> out [128][K] fp16
__global__ void prep_weight(const float* __restrict__ W, int K, __half* __restrict__ o) {
    int i = blockIdx.x * blockDim.x + threadIdx.x;
    if (i < 128 * K) {
        int k = i >> 7, n = i & 127;
        o[(size_t)n * K + k] = __float2half(W[i]);
    }
}
// fold: Wf = W3 @ cW[:128] (fp32) -> [128][128] fp16 transposed; bias[n] = b3@cW[:,n] + extra
__global__ void __launch_bounds__(256)
fold_w3(const float* __restrict__ W3, const float* __restrict__ cW,
        const float* __restrict__ b3, const float* __restrict__ extra_bias,
        __half* __restrict__ o, float* __restrict__ obias) {
    int idx = blockIdx.x * 256 + threadIdx.x;   // 0..16383
    int k = idx >> 7, n = idx & 127;
    float acc = 0.f;
    for (int d = 0; d < 128; d++)
        acc += W3[k * 128 + d] * cW[d * 128 + n];
    o[(size_t)n * 128 + k] = __float2half(acc);
    if (k == 0) {
        float bacc = extra_bias ? extra_bias[n] : 0.f;
        for (int d = 0; d < 128; d++) bacc += b3[d] * cW[d * 128 + n];
        obias[n] = bacc;
    }
}
__global__ void copy_cont_h(const float* __restrict__ xc) {
    int i = blockIdx.x * blockDim.x + threadIdx.x;
    if (i < NN * 32) {
        float2 v = *(const float2*)&xc[(size_t)i * 2];
        *(__half2*)&g_c[(size_t)i * 2] = __floats2half2_rn(v.x, v.y);
    }
}

// ---------------- emb@W1 table precompute (fp16 output) ----------------
__global__ void __launch_bounds__(256)
prep_T(const float* __restrict__ emb, const float* __restrict__ W1) {
    __shared__ float se[50 * 32];
    __shared__ float sw[32 * 128];
    int c = blockIdx.x >> 1;
    int rh = blockIdx.x & 1;
    int tid = threadIdx.x;
    for (int i = tid; i < 50 * 32; i += 256)
        se[i] = emb[(size_t)c * CARD * EMBD + rh * 50 * 32 + i];
    for (int i = tid; i < 32 * 128; i += 256)
        sw[i] = W1[(size_t)(c * 32) * 128 + i];
    __syncthreads();
    for (int i = 0; i < 25; i++) {
        int idx = tid + i * 256;
        int r = idx >> 7, n = idx & 127;
        float acc = 0.f;
#pragma unroll
        for (int d = 0; d < 32; d++)
            acc += se[r * 32 + d] * sw[d * 128 + n];
        g_Th[((size_t)c * CARD + rh * 50 + r) * 128 + n] = __float2half(acc);
    }
}

// ---------------- MLP layer 1 via fp16 table lookup-sum ----------------
__global__ void __launch_bounds__(256)
emb_mlp1(const int* __restrict__ xcat, const float* __restrict__ b1,
         __half* __restrict__ o) {
    int w = (blockIdx.x * blockDim.x + threadIdx.x) >> 5;
    if (w >= NN) return;
    int lane = threadIdx.x & 31;
    const int* xc = xcat + (size_t)w * NCAT;
    float4 acc = *(const float4*)&b1[lane * 4];
#pragma unroll
    for (int c = 0; c < NCAT; c++) {
        int cat = __ldg(&xc[c]);
        uint2 u = *(const uint2*)&g_Th[((size_t)c * CARD + cat) * 128 + lane * 4];
        float2 f0 = __half22float2(*(__half2*)&u.x);
        float2 f1 = __half22float2(*(__half2*)&u.y);
        acc.x += f0.x; acc.y += f0.y; acc.z += f1.x; acc.w += f1.y;
    }
    __half2 o0 = __floats2half2_rn(gelu_f(acc.x), gelu_f(acc.y));
    __half2 o1 = __floats2half2_rn(gelu_f(acc.z), gelu_f(acc.w));
    size_t off = (size_t)w * 128 + lane * 4;
    *(__half2*)&o[off] = o0;
    *(__half2*)&o[off + 2] = o1;
}

// ---------------- CSR build ----------------
__global__ void zero_cnt() {
    int i = blockIdx.x * blockDim.x + threadIdx.x;
    if (i < NN) g_cnt[i] = 0;
}
__global__ void count_k(const int* __restrict__ ei, int E) {
    int e = blockIdx.x * blockDim.x + threadIdx.x;
    if (e < E) atomicAdd(&g_cnt[ei[E + e]], 1);
}
__global__ void scan_block() {
    __shared__ int sh[1024];
    int tid = threadIdx.x;
    int i = blockIdx.x * 1024 + tid;
    int v = (i < NN) ? g_cnt[i] : 0;
    sh[tid] = v;
    __syncthreads();
#pragma unroll
    for (int off = 1; off < 1024; off <<= 1) {
        int t = (tid >= off) ? sh[tid - off] : 0;
        __syncthreads();
        sh[tid] += t;
        __syncthreads();
    }
    if (i < NN) g_start[i] = sh[tid] - v;
    if (tid == 1023) g_bsum[blockIdx.x] = sh[1023];
}
__global__ void scan_top() {
    if (threadIdx.x == 0) {
        int acc = 0;
        for (int j = 0; j < NB_SCAN; j++) { int t = g_bsum[j]; g_bsum[j] = acc; acc += t; }
        g_start[NN] = acc;
    }
}
__global__ void scan_add() {
    int i = blockIdx.x * blockDim.x + threadIdx.x;
    if (i < NN) {
        int s = g_start[i] + g_bsum[i >> 10];
        g_start[i] = s;
        g_cursor[i] = s;
    }
}
__global__ void fill_k(const int* __restrict__ ei, int E) {
    int e = blockIdx.x * blockDim.x + threadIdx.x;
    if (e < E) {
        int dst = ei[E + e];
        int pos = atomicAdd(&g_cursor[dst], 1);
        g_csrc[pos] = ei[e];
    }
}

// ---------------- gather kernels ----------------
__global__ void gather_vec(const __half* __restrict__ y, float* __restrict__ agg) {
    int w = (blockIdx.x * blockDim.x + threadIdx.x) >> 5;
    if (w >= NN) return;
    int lane = threadIdx.x & 31;
    int s = g_start[w], e = g_start[w + 1];
    float inv = 1.f / fmaxf((float)(e - s), 1.f);
    float a0 = 0.f, a1 = 0.f, a2 = 0.f, a3 = 0.f;
    float b0 = 0.f, b1 = 0.f, b2 = 0.f, b3 = 0.f;
    int i = s;
    for (; i + 1 < e; i += 2) {
        int r0 = g_csrc[i], r1 = g_csrc[i + 1];
        uint2 u0 = *(const uint2*)&y[(size_t)r0 * 128 + lane * 4];
        uint2 u1 = *(const uint2*)&y[(size_t)r1 * 128 + lane * 4];
        float2 p0 = __half22float2(*(__half2*)&u0.x);
        float2 p1 = __half22float2(*(__half2*)&u0.y);
        float2 q0 = __half22float2(*(__half2*)&u1.x);
        float2 q1 = __half22float2(*(__half2*)&u1.y);
        a0 += p0.x; a1 += p0.y; a2 += p1.x; a3 += p1.y;
        b0 += q0.x; b1 += q0.y; b2 += q1.x; b3 += q1.y;
    }
    if (i < e) {
        int r0 = g_csrc[i];
        uint2 u0 = *(const uint2*)&y[(size_t)r0 * 128 + lane * 4];
        float2 p0 = __half22float2(*(__half2*)&u0.x);
        float2 p1 = __half22float2(*(__half2*)&u0.y);
        a0 += p0.x; a1 += p0.y; a2 += p1.x; a3 += p1.y;
    }
    float4 o = make_float4((a0 + b0) * inv, (a1 + b1) * inv,
                           (a2 + b2) * inv, (a3 + b3) * inv);
    *(float4*)&agg[(size_t)w * 128 + lane * 4] = o;
}

__global__ void gather3_final(const float* __restrict__ bl, float* __restrict__ out) {
    int w = (blockIdx.x * blockDim.x + threadIdx.x) >> 5;
    if (w >= NN) return;
    int lane = threadIdx.x & 31;
    int s = g_start[w], e = g_start[w + 1];
    float inv = 1.f / fmaxf((float)(e - s), 1.f);
    float sum = 0.f;
    for (int i = s + lane; i < e; i += 32) sum += g_s1[g_csrc[i]];
#pragma unroll
    for (int o = 16; o > 0; o >>= 1) sum += __shfl_down_sync(0xffffffffu, sum, o);
    if (lane == 0) out[w] = sum * inv + bl[0] + g_s2[w];
}

// ---------------- epilogue conv1: v = gelu(z + agg) -> fp16 ----------------
__global__ void ep_h(const float* __restrict__ z, const float* __restrict__ agg,
                     __half* __restrict__ o) {
    int i = blockIdx.x * blockDim.x + threadIdx.x;
    if (i >= NN * 32) return;
    float4 zv = *(const float4*)&z[(size_t)i * 4];
    float4 av = *(const float4*)&agg[(size_t)i * 4];
    __half2 o0 = __floats2half2_rn(gelu_f(zv.x + av.x), gelu_f(zv.y + av.y));
    __half2 o1 = __floats2half2_rn(gelu_f(zv.z + av.z), gelu_f(zv.w + av.w));
    *(__half2*)&o[(size_t)i * 4] = o0;
    *(__half2*)&o[(size_t)i * 4 + 2] = o1;
}

// ---------------- epilogue conv2 fused with conv3 dots ----------------
__global__ void ep2_conv3(const float* __restrict__ z, const float* __restrict__ agg,
                          const float* __restrict__ Wl, const float* __restrict__ Wr) {
    int w = (blockIdx.x * blockDim.x + threadIdx.x) >> 5;
    if (w >= NN) return;
    int lane = threadIdx.x & 31;
    size_t o = (size_t)w * 128 + lane * 4;
    float4 zv = *(const float4*)&z[o];
    float4 av = *(const float4*)&agg[o];
    float h0 = gelu_f(zv.x + av.x), h1 = gelu_f(zv.y + av.y);
    float h2 = gelu_f(zv.z + av.z), h3 = gelu_f(zv.w + av.w);
    float4 wl = *(const float4*)&Wl[lane * 4];
    float4 wr = *(const float4*)&Wr[lane * 4];
    float s1 = h0 * wl.x + h1 * wl.y + h2 * wl.z + h3 * wl.w;
    float s2 = h0 * wr.x + h1 * wr.y + h2 * wr.z + h3 * wr.w;
#pragma unroll
    for (int off = 16; off > 0; off >>= 1) {
        s1 += __shfl_down_sync(0xffffffffu, s1, off);
        s2 += __shfl_down_sync(0xffffffffu, s2, off);
    }
    if (lane == 0) { g_s1[w] = s1; g_s2[w] = s2; }
}

// =====================================================================
// single-fp16 tensor GEMM with ldmatrix fragment loads
// SPLIT: k<128 from (A stride lda, B stride 128); k>=128 from (A2,B2; stride 64)
// EPI: 0 = gelu(v+bias); 1 = v+bias (bias may be null)
// OUTMODE: 0 = fp32 -> C0; 2 = fp16 -> C0
// smem: per stage A 8KB + B 8KB = 16KB; 2 stages = 32KB
// =====================================================================
#define SMEM_DYN 32768

template<int K, int EPI, int OUTMODE, bool SPLIT>
__global__ void __launch_bounds__(256, 2)
tgemm_h(const __half* __restrict__ A, int lda,
        const __half* __restrict__ B,
        const float* __restrict__ bias,
        void* __restrict__ C0, int ldc,
        const __half* __restrict__ A2, const __half* __restrict__ B2)
{
    extern __shared__ __align__(16) char sm[];

    const int tid  = threadIdx.x;
    const int m0   = blockIdx.x * 128;
    const int wid  = tid >> 5;
    const int lane = tid & 31;
    const int g    = lane >> 2;
    const int tig  = lane & 3;
    const int warpM = (wid >> 2) * 64;
    const int warpN = (wid & 3) * 32;

    constexpr int NC = K / 32;
    constexpr int BK = SPLIT ? 128 : K;
    const uint32_t smB = (uint32_t)__cvta_generic_to_shared(sm);

    const int laneT8 = lane & 7;
    const int aRow   = laneT8 + ((lane >> 3) & 1) * 8;
    const int aKh    = lane >> 4;
    const int bNsel  = lane >> 4;
    const int bKh    = (lane >> 3) & 1;

    float4 acc[4][4];
#pragma unroll
    for (int i = 0; i < 4; i++)
#pragma unroll
        for (int j = 0; j < 4; j++) acc[i][j] = make_float4(0.f, 0.f, 0.f, 0.f);

    auto copy_tile = [&](int buf, int k0) {
        uint32_t st = smB + (uint32_t)buf * 16384;
        // A: 128 rows x 32 halfs = 512 16B-segs -> 2 per thread
#pragma unroll
        for (int i = 0; i < 2; i++) {
            int flat = tid + i * 256;          // 0..511
            int r = flat >> 2, seg = flat & 3;
            int row = m0 + r; if (row >= NN) row = NN - 1;
            const __half* src;
            if (SPLIT && k0 >= 128) {
                src = A2 + (size_t)row * 64 + (k0 - 128) + seg * 8;
            } else {
                src = A + (size_t)row * lda + k0 + seg * 8;
            }
            uint32_t dst = st + (uint32_t)r * 64
                         + (uint32_t)((seg ^ ((r >> 1) & 3)) << 4);
            cpasync16(dst, src);
        }
        // B: 128 n-rows x 32 halfs -> 2 per thread
#pragma unroll
        for (int i = 0; i < 2; i++) {
            int flat = tid + i * 256;
            int n = flat >> 2, seg = flat & 3;
            const __half* src;
            if (SPLIT && k0 >= 128) {
                src = B2 + (size_t)n * 64 + (k0 - 128) + seg * 8;
            } else {
                src = B + (size_t)n * BK + k0 + seg * 8;
            }
            uint32_t dst = st + 8192u + (uint32_t)n * 64
                         + (uint32_t)((seg ^ ((n >> 1) & 3)) << 4);
            cpasync16(dst, src);
        }
        cp_commit();
    };

    copy_tile(0, 0);

    for (int ks = 0; ks < NC; ks++) {
        if (ks + 1 < NC) {
            copy_tile((ks + 1) & 1, (ks + 1) * 32);
            cp_wait<1>();
        } else {
            cp_wait<0>();
        }
        __syncthreads();

        const uint32_t stage = smB + (uint32_t)(ks & 1) * 16384;
        const uint32_t Abase = stage;
        const uint32_t Bbase = stage + 8192u;

#pragma unroll
        for (int kc = 0; kc < 2; kc++) {
            uint32_t bf[4][2];
#pragma unroll
            for (int p = 0; p < 2; p++) {
                int n = warpN + (p * 2 + bNsel) * 8 + laneT8;
                int seg = kc * 2 + bKh;
                uint32_t addr = Bbase + (uint32_t)n * 64
                              + (uint32_t)((seg ^ ((n >> 1) & 3)) << 4);
                ldmx4(bf[p * 2][0], bf[p * 2][1], bf[p * 2 + 1][0], bf[p * 2 + 1][1], addr);
            }
#pragma unroll
            for (int mt = 0; mt < 4; mt++) {
                int r = warpM + mt * 16 + aRow;
                int seg = kc * 2 + aKh;
                uint32_t addr = Abase + (uint32_t)r * 64
                              + (uint32_t)((seg ^ ((r >> 1) & 3)) << 4);
                uint32_t af[4];
                ldmx4(af[0], af[1], af[2], af[3], addr);
#pragma unroll
                for (int nt = 0; nt < 4; nt++)
                    mma_f16(acc[mt][nt], af, bf[nt]);
            }
        }
        __syncthreads();
    }

#pragma unroll
    for (int mt = 0; mt < 4; mt++) {
        int r0 = m0 + warpM + mt * 16 + g;
#pragma unroll
        for (int rr = 0; rr < 2; rr++) {
            int r = r0 + rr * 8;
            if (r >= NN) continue;
#pragma unroll
            for (int nt = 0; nt < 4; nt++) {
                int col = warpN + nt * 8 + tig * 2;
                float v0 = (rr == 0) ? acc[mt][nt].x : acc[mt][nt].z;
                float v1 = (rr == 0) ? acc[mt][nt].y : acc[mt][nt].w;
                if (bias) { v0 += bias[col]; v1 += bias[col + 1]; }
                if (EPI == 0) { v0 = gelu_f(v0); v1 = gelu_f(v1); }
                if (OUTMODE == 0) {
                    *(float2*)((float*)C0 + (size_t)r * ldc + col) = make_float2(v0, v1);
                } else {
                    *(__half2*)((__half*)C0 + (size_t)r * ldc + col) = __floats2half2_rn(v0, v1);
                }
            }
        }
    }
}

// ---------------- host ----------------
extern "C" void kernel_launch(void* const* d_in, const int* in_sizes, int n_in,
                              void* d_out, int out_size) {
    (void)n_in; (void)out_size;
    const int*   x_cat  = (const int*)  d_in[0];
    const float* x_cont = (const float*)d_in[1];
    const int*   ei     = (const int*)  d_in[2];
    const float* emb    = (const float*)d_in[3];
    const float* W1     = (const float*)d_in[4];
    const float* b1     = (const float*)d_in[5];
    const float* W2     = (const float*)d_in[6];
    const float* b2     = (const float*)d_in[7];
    const float* W3     = (const float*)d_in[8];
    const float* b3     = (const float*)d_in[9];
    const float* c1_Wl  = (const float*)d_in[10];
    const float* c1_bl  = (const float*)d_in[11];
    const float* c1_Wr  = (const float*)d_in[12];
    const float* c2_Wl  = (const float*)d_in[13];
    const float* c2_bl  = (const float*)d_in[14];
    const float* c2_Wr  = (const float*)d_in[15];
    const float* c3_Wl  = (const float*)d_in[16];
    const float* c3_bl  = (const float*)d_in[17];
    const float* c3_Wr  = (const float*)d_in[18];
    float* out = (float*)d_out;

    const int E = in_sizes[2] / 2;

    __half *p_c, *p1, *p2, *p_y, *wt;
    float *p_z, *p_agg, *p_bfl, *p_bfr;
    cudaGetSymbolAddress((void**)&p_c, g_c);
    cudaGetSymbolAddress((void**)&p1, g_p1);
    cudaGetSymbolAddress((void**)&p2, g_p2);
    cudaGetSymbolAddress((void**)&p_y, g_y);
    cudaGetSymbolAddress((void**)&p_z, g_z);
    cudaGetSymbolAddress((void**)&p_agg, g_agg);
    cudaGetSymbolAddress((void**)&wt, g_wt);
    cudaGetSymbolAddress((void**)&p_bfl, g_bfl);
    cudaGetSymbolAddress((void**)&p_bfr, g_bfr);

    // transposed weight offsets (elements)
    const int O_W2  = 0;        // 128x128
    const int O_FL  = 16384;    // folded conv1 Wl (128x128)
    const int O_FR  = 32768;    // folded conv1 Wr (128x128)
    const int O_CL  = 49152;    // conv1 Wl cont part (128x64)
    const int O_CR  = 57344;    // conv1 Wr cont part (128x64)
    const int O_C2L = 65536;    // 128x128
    const int O_C2R = 81920;    // 128x128

    // persistent streams/events (created once, before pre-capture baseline)
    static cudaStream_t s2 = nullptr, s3 = nullptr;
    static cudaEvent_t ev0, evW, evY1, evG1, evY2, evG2;
    static bool init_done = false;
    if (!init_done) {
        cudaStreamCreateWithFlags(&s2, cudaStreamNonBlocking);
        cudaStreamCreateWithFlags(&s3, cudaStreamNonBlocking);
        cudaEventCreateWithFlags(&ev0, cudaEventDisableTiming);
        cudaEventCreateWithFlags(&evW, cudaEventDisableTiming);
        cudaEventCreateWithFlags(&evY1, cudaEventDisableTiming);
        cudaEventCreateWithFlags(&evG1, cudaEventDisableTiming);
        cudaEventCreateWithFlags(&evY2, cudaEventDisableTiming);
        cudaEventCreateWithFlags(&evG2, cudaEventDisableTiming);
        cudaFuncSetAttribute(tgemm_h<128, 0, 2, false>, cudaFuncAttributeMaxDynamicSharedMemorySize, SMEM_DYN);
        cudaFuncSetAttribute(tgemm_h<192, 1, 2, true>,  cudaFuncAttributeMaxDynamicSharedMemorySize, SMEM_DYN);
        cudaFuncSetAttribute(tgemm_h<192, 1, 0, true>,  cudaFuncAttributeMaxDynamicSharedMemorySize, SMEM_DYN);
        cudaFuncSetAttribute(tgemm_h<128, 1, 2, false>, cudaFuncAttributeMaxDynamicSharedMemorySize, SMEM_DYN);
        cudaFuncSetAttribute(tgemm_h<128, 1, 0, false>, cudaFuncAttributeMaxDynamicSharedMemorySize, SMEM_DYN);
        init_done = true;
    }

    const int GB = (NN + 127) / 128;
    cudaStream_t ms = 0;

    cudaEventRecord(ev0, ms);
    cudaStreamWaitEvent(s2, ev0, 0);
    cudaStreamWaitEvent(s3, ev0, 0);

    // s2: CSR build
    zero_cnt<<<(NN + 255) / 256, 256, 0, s2>>>();
    count_k<<<(E + 255) / 256, 256, 0, s2>>>(ei, E);
    scan_block<<<NB_SCAN, 1024, 0, s2>>>();
    scan_top<<<1, 32, 0, s2>>>();
    scan_add<<<(NN + 255) / 256, 256, 0, s2>>>();
    fill_k<<<(E + 255) / 256, 256, 0, s2>>>(ei, E);

    // s3: weight prep + folding
    prep_weight<<<(128 * 128 + 255) / 256, 256, 0, s3>>>(W2, 128, wt + O_W2);
    fold_w3<<<64, 256, 0, s3>>>(W3, c1_Wl, b3, nullptr, wt + O_FL, p_bfl);
    fold_w3<<<64, 256, 0, s3>>>(W3, c1_Wr, b3, c1_bl,   wt + O_FR, p_bfr);
    prep_weight<<<(128 * 64 + 255) / 256, 256, 0, s3>>>(c1_Wl + 128 * 128, 64, wt + O_CL);
    prep_weight<<<(128 * 64 + 255) / 256, 256, 0, s3>>>(c1_Wr + 128 * 128, 64, wt + O_CR);
    prep_weight<<<(128 * 128 + 255) / 256, 256, 0, s3>>>(c2_Wl, 128, wt + O_C2L);
    prep_weight<<<(128 * 128 + 255) / 256, 256, 0, s3>>>(c2_Wr, 128, wt + O_C2R);
    cudaEventRecord(evW, s3);

    // ms: MLP layer 1 via fused fp16 tables
    prep_T<<<NCAT * 2, 256, 0, ms>>>(emb, W1);
    copy_cont_h<<<(NN * 32 + 255) / 256, 256, 0, ms>>>(x_cont);
    emb_mlp1<<<(NN * 32 + 255) / 256, 256, 0, ms>>>(x_cat, b1, p1);

    cudaStreamWaitEvent(ms, evW, 0);

    // MLP layer 2 (W3 folded into conv1)
    tgemm_h<128, 0, 2, false><<<GB, 256, SMEM_DYN, ms>>>(p1, 128, wt + O_W2, b2, p2, 128,
                                                         nullptr, nullptr);

    // ---- conv1: y = h2@Wfl + xc@Wlc + bfl (fp16); gather on s2; z = h2@Wfr + xc@Wrc + bfr
    tgemm_h<192, 1, 2, true><<<GB, 256, SMEM_DYN, ms>>>(p2, 128, wt + O_FL, p_bfl, p_y, 128,
                                                        p_c, wt + O_CL);
    cudaEventRecord(evY1, ms);
    cudaStreamWaitEvent(s2, evY1, 0);
    gather_vec<<<(NN * 32 + 255) / 256, 256, 0, s2>>>(p_y, p_agg);
    cudaEventRecord(evG1, s2);
    tgemm_h<192, 1, 0, true><<<GB, 256, SMEM_DYN, ms>>>(p2, 128, wt + O_FR, p_bfr, p_z, 128,
                                                        p_c, wt + O_CR);
    cudaStreamWaitEvent(ms, evG1, 0);
    ep_h<<<(NN * 32 + 255) / 256, 256, 0, ms>>>(p_z, p_agg, p1);

    // ---- conv2
    tgemm_h<128, 1, 2, false><<<GB, 256, SMEM_DYN, ms>>>(p1, 128, wt + O_C2L, nullptr, p_y, 128,
                                                         nullptr, nullptr);
    cudaEventRecord(evY2, ms);
    cudaStreamWaitEvent(s2, evY2, 0);
    gather_vec<<<(NN * 32 + 255) / 256, 256, 0, s2>>>(p_y, p_agg);
    cudaEventRecord(evG2, s2);
    tgemm_h<128, 1, 0, false><<<GB, 256, SMEM_DYN, ms>>>(p1, 128, wt + O_C2R, c2_bl, p_z, 128,
                                                         nullptr, nullptr);
    cudaStreamWaitEvent(ms, evG2, 0);

    // ---- conv2 epilogue fused with conv3 dots, then final gather
    ep2_conv3<<<(NN * 32 + 255) / 256, 256, 0, ms>>>(p_z, p_agg, c3_Wl, c3_Wr);
    gather3_final<<<(NN * 32 + 255) / 256, 256, 0, ms>>>(c3_bl, out);
}